// round 1
// baseline (speedup 1.0000x reference)
#include <cuda_runtime.h>
#include <math.h>
#include <stdint.h>

// Problem dims
#define B_ 32
#define T_ 64
#define S_ 64
#define V_ 32000
#define E_ 512
#define H_ 512
#define U_ 1024
#define NH_ 8
#define D_ 64
#define DV_ 128
#define FEATW 2048   // E + H + U

// ---------------- scratch (one big device global, no allocations) ----------------
// offsets in floats
#define OFF_FEAT   0ull                         // [B,T,2048] = 4,194,304
#define OFF_KEYUP  4194304ull                   // [B,NH,S,D] = 1,048,576
#define OFF_LOGITS 5242880ull                   // [B,T,512]  = 1,048,576
#define OFF_H      6291456ull                   // [B,512]
#define OFF_TMP    6307840ull                   // [B,512]
#define OFF_CTXV   6324224ull                   // [B,1024]
#define OFF_PART   6356992ull                   // [4][32][2048] = 262,144
#define OFF_W1     6619136ull                   // [1024,2048] = 2,097,152
#define OFF_W2     8716288ull                   // [1536,2048] = 3,145,728
#define OFF_WQT   11862016ull                   // [512,512]
#define OFF_WFT   12124160ull                   // [1024,1024] = 1,048,576
#define SCRATCH_FLOATS 13172736ull

__device__ float g_scratch[SCRATCH_FLOATS];

// ---------------- embedding gather into feat[:, :, 0:512] ----------------
__global__ void k_embed(const int* __restrict__ tokens, const float* __restrict__ embed_w,
                        float* __restrict__ feat) {
    int bt = blockIdx.x;                 // 0..2047 (b*T+t)
    int tok = tokens[bt];
    const float4* src = reinterpret_cast<const float4*>(embed_w + (size_t)tok * E_);
    float4* dst = reinterpret_cast<float4*>(feat + (size_t)bt * FEATW);
    dst[threadIdx.x] = src[threadIdx.x]; // 128 threads * float4 = 512 floats
}

// ---------------- bridge: h0 = tanh(fwd_n @ bridge_W.T + b) ----------------
__global__ __launch_bounds__(512) void k_bridge(const unsigned char* __restrict__ mask,
                                                const float* __restrict__ enc_out,
                                                const float* __restrict__ Wb,
                                                const float* __restrict__ bb,
                                                float* __restrict__ h0) {
    int b = blockIdx.x;
    int j = threadIdx.x;  // 0..511
    __shared__ float fn[512];
    __shared__ int sL;
    if (j == 0) {
        int L = S_;
        for (int s = 0; s < S_; s++) if (mask[b * S_ + s]) L--;
        sL = L;
    }
    __syncthreads();
    int L = sL;
    fn[j] = enc_out[((size_t)(L - 1) * B_ + b) * U_ + j];   // forward half (first 512)
    __syncthreads();
    float acc = bb[j];
    const float* wr = Wb + (size_t)j * 512;
    for (int k = 0; k < 512; k++) acc += fn[k] * wr[k];
    h0[b * H_ + j] = tanhf(acc);
}

// ---------------- weight packing ----------------
// W1cat [K'=1024][2048] : cols [Sr | Sz | Xn | Hn]
__global__ void k_pack1(const float* __restrict__ Wx, const float* __restrict__ Wh,
                        float* __restrict__ Wc) {
    int idx = blockIdx.x * 256 + threadIdx.x;
    if (idx >= 1024 * 2048) return;
    int k = idx >> 11, col = idx & 2047;
    int g = col >> 9, j = col & 511;
    float v = 0.f;
    if (k < 512) {
        if (g == 0)      v = Wx[(size_t)j * 512 + k];
        else if (g == 1) v = Wx[(size_t)(512 + j) * 512 + k];
        else if (g == 2) v = Wx[(size_t)(1024 + j) * 512 + k];
    } else {
        int kh = k - 512;
        if (g == 0)      v = Wh[(size_t)j * 512 + kh];
        else if (g == 1) v = Wh[(size_t)(512 + j) * 512 + kh];
        else if (g == 3) v = Wh[(size_t)(1024 + j) * 512 + kh];
    }
    Wc[idx] = v;
}

// W2cat [K'=1536][2048]
__global__ void k_pack2(const float* __restrict__ Wx, const float* __restrict__ Wh,
                        float* __restrict__ Wc) {
    int idx = blockIdx.x * 256 + threadIdx.x;
    if (idx >= 1536 * 2048) return;
    int k = idx >> 11, col = idx & 2047;
    int g = col >> 9, j = col & 511;
    float v = 0.f;
    if (k < 1024) {
        if (g == 0)      v = Wx[(size_t)j * 1024 + k];
        else if (g == 1) v = Wx[(size_t)(512 + j) * 1024 + k];
        else if (g == 2) v = Wx[(size_t)(1024 + j) * 1024 + k];
    } else {
        int kh = k - 1024;
        if (g == 0)      v = Wh[(size_t)j * 512 + kh];
        else if (g == 1) v = Wh[(size_t)(512 + j) * 512 + kh];
        else if (g == 3) v = Wh[(size_t)(1024 + j) * 512 + kh];
    }
    Wc[idx] = v;
}

// WT[k*R + n] = W[n*C + k]
__global__ void k_transpose(const float* __restrict__ W, float* __restrict__ WT, int R, int C) {
    int idx = blockIdx.x * 256 + threadIdx.x;
    if (idx >= R * C) return;
    int n = idx / C, k = idx % C;
    WT[(size_t)k * R + n] = W[idx];
}

// ---------------- split-K skinny gates GEMM: part[kc][32][N] ----------------
#define GFMA(wv, kk) { \
    const float4* ap_ = reinterpret_cast<const float4*>(&As[(kk) * 32 + m0]); \
    float4 a0_ = ap_[0], a1_ = ap_[1], a2_ = ap_[2], a3_ = ap_[3]; \
    acc[0]  += a0_.x * (wv); acc[1]  += a0_.y * (wv); acc[2]  += a0_.z * (wv); acc[3]  += a0_.w * (wv); \
    acc[4]  += a1_.x * (wv); acc[5]  += a1_.y * (wv); acc[6]  += a1_.z * (wv); acc[7]  += a1_.w * (wv); \
    acc[8]  += a2_.x * (wv); acc[9]  += a2_.y * (wv); acc[10] += a2_.z * (wv); acc[11] += a2_.w * (wv); \
    acc[12] += a3_.x * (wv); acc[13] += a3_.y * (wv); acc[14] += a3_.z * (wv); acc[15] += a3_.w * (wv); }

__global__ __launch_bounds__(256) void k_gates(const float* __restrict__ x, int xs, int Kx,
                                               const float* __restrict__ h, int hs,
                                               const float* __restrict__ W, int N, int chunk,
                                               float* __restrict__ part) {
    __shared__ float As[12288];                 // up to chunk(384) * 32 floats = 48KB
    int k0 = blockIdx.y * chunk;
    int tot = chunk * 32;
    for (int idx = threadIdx.x; idx < tot; idx += 256) {
        int k = idx >> 5, m = idx & 31;
        int kk = k0 + k;
        As[idx] = (kk < Kx) ? x[(size_t)m * xs + kk] : h[(size_t)m * hs + (kk - Kx)];
    }
    __syncthreads();
    int col = blockIdx.x * 128 + (threadIdx.x & 127);
    int m0 = (threadIdx.x >> 7) << 4;           // 0 or 16
    float acc[16];
#pragma unroll
    for (int i = 0; i < 16; i++) acc[i] = 0.f;
    const float* Wp = W + (size_t)k0 * N + col;
    int k = 0;
    for (; k + 4 <= chunk; k += 4) {
        float w0 = Wp[(size_t)(k + 0) * N];
        float w1 = Wp[(size_t)(k + 1) * N];
        float w2 = Wp[(size_t)(k + 2) * N];
        float w3 = Wp[(size_t)(k + 3) * N];
        GFMA(w0, k); GFMA(w1, k + 1); GFMA(w2, k + 2); GFMA(w3, k + 3);
    }
    for (; k < chunk; k++) { float w = Wp[(size_t)k * N]; GFMA(w, k); }
    float* P = part + ((size_t)blockIdx.y * 32 + m0) * N + col;
#pragma unroll
    for (int i = 0; i < 16; i++) P[(size_t)i * N] = acc[i];
}

// ---------------- GRU combine (reduce 4 split-K partials + nonlinearity) ----------------
__global__ void k_gru_combine(const float* __restrict__ part,
                              const float* __restrict__ bx, const float* __restrict__ bh,
                              const float* __restrict__ h_old, float* __restrict__ h_new,
                              float* __restrict__ feat_out, int featStride) {
    int idx = blockIdx.x * 256 + threadIdx.x;   // 0..16383
    int b = idx >> 9, j = idx & 511;
    const float* p = part + (size_t)b * 2048;
    float Sr = 0.f, Sz = 0.f, Xn = 0.f, Hn = 0.f;
#pragma unroll
    for (int kc = 0; kc < 4; kc++) {
        const float* q = p + (size_t)kc * 32 * 2048;
        Sr += q[j]; Sz += q[512 + j]; Xn += q[1024 + j]; Hn += q[1536 + j];
    }
    float r = 1.f / (1.f + expf(-(Sr + bx[j] + bh[j])));
    float z = 1.f / (1.f + expf(-(Sz + bx[512 + j] + bh[512 + j])));
    float n = tanhf(Xn + bx[1024 + j] + r * (Hn + bh[1024 + j]));
    float out = (1.f - z) * n + z * h_old[idx];
    h_new[idx] = out;
    if (feat_out) feat_out[(size_t)b * featStride + j] = out;
}

// ---------------- linear reduce (Wf epilogue -> feat ctx slot) ----------------
__global__ void k_lin_reduce(const float* __restrict__ part, int N,
                             const float* __restrict__ bias,
                             float* __restrict__ out, int outStride) {
    int idx = blockIdx.x * 256 + threadIdx.x;   // 32*N
    int b = idx / N, n = idx % N;
    float s = 0.f;
#pragma unroll
    for (int kc = 0; kc < 4; kc++) s += part[(size_t)kc * 32 * N + (size_t)b * N + n];
    out[(size_t)b * outStride + n] = s + bias[n];
}

// ---------------- fused attention: q-proj + tanh-additive scores + softmax + ctx ----------------
__global__ __launch_bounds__(128) void k_attn(const float* __restrict__ tmp,
                                              const float* __restrict__ WqT,
                                              const float* __restrict__ bq,
                                              const float* __restrict__ keyup,
                                              const float* __restrict__ Ww,
                                              const float* __restrict__ bw,
                                              const float* __restrict__ enc_out,
                                              const unsigned char* __restrict__ mask,
                                              float* __restrict__ ctxv) {
    int b = blockIdx.x >> 3, nh = blockIdx.x & 7;
    int tid = threadIdx.x;
    __shared__ float st[512];
    __shared__ float sq[64];
    __shared__ float sa[64];
    for (int i = tid; i < 512; i += 128) st[i] = tmp[b * 512 + i];
    __syncthreads();
    if (tid < 64) {
        float acc = bq[nh * 64 + tid];
        const float* wp = WqT + nh * 64 + tid;
        for (int k = 0; k < 512; k++) acc += st[k] * wp[(size_t)k * 512];
        sq[tid] = acc;
    }
    __syncthreads();
    if (tid < 64) {
        int s = tid;
        const float* kp = keyup + (((size_t)(b * 8 + nh)) * 64 + s) * 64;
        float sc = bw[0];
#pragma unroll 8
        for (int d = 0; d < 64; d++) sc += tanhf(sq[d] + kp[d]) * Ww[d];
        if (mask[b * S_ + s]) sc -= 1e9f;
        sa[s] = sc;
    }
    __syncthreads();
    if (tid == 0) {
        float mx = -1e30f;
        for (int s = 0; s < 64; s++) mx = fmaxf(mx, sa[s]);
        float sum = 0.f;
        for (int s = 0; s < 64; s++) { float e = expf(sa[s] - mx); sa[s] = e; sum += e; }
        float inv = 1.f / sum;
        for (int s = 0; s < 64; s++) sa[s] *= inv;
    }
    __syncthreads();
    float acc = 0.f;
    const float* vp = enc_out + (size_t)b * U_ + nh * 128 + tid;
#pragma unroll
    for (int s = 0; s < 64; s++) acc += sa[s] * vp[(size_t)s * B_ * U_];
    ctxv[b * U_ + nh * 128 + tid] = acc;
}

// ---------------- tiled SGEMM-NT: C[M,N] = A[M,K] @ B[N,K]^T ----------------
// mode 0: plain (+bias), mode 1: tanh(+bias), mode 2: key_up remap (+bias)
#define BM 128
#define BN 128
#define BKk 16
__global__ __launch_bounds__(256) void sgemm_nt(const float* __restrict__ A,
                                                const float* __restrict__ Bm,
                                                const float* __restrict__ bias,
                                                float* __restrict__ C,
                                                int M, int N, int K, int mode) {
    __shared__ float As[BKk][BM];
    __shared__ float Bs[BKk][BN];
    const int bm = blockIdx.y * BM, bn = blockIdx.x * BN;
    const int tid = threadIdx.x;
    const int tm = (tid >> 4) << 3;
    const int tn = (tid & 15) << 3;
    float acc[8][8];
#pragma unroll
    for (int i = 0; i < 8; i++)
#pragma unroll
        for (int j = 0; j < 8; j++) acc[i][j] = 0.f;

    for (int k0 = 0; k0 < K; k0 += BKk) {
#pragma unroll
        for (int i = 0; i < 2; i++) {
            int idx = tid + i * 256;
            int r = idx >> 2, c = (idx & 3) << 2;
            float4 v = *reinterpret_cast<const float4*>(A + (size_t)(bm + r) * K + k0 + c);
            As[c][r] = v.x; As[c + 1][r] = v.y; As[c + 2][r] = v.z; As[c + 3][r] = v.w;
            float4 w = *reinterpret_cast<const float4*>(Bm + (size_t)(bn + r) * K + k0 + c);
            Bs[c][r] = w.x; Bs[c + 1][r] = w.y; Bs[c + 2][r] = w.z; Bs[c + 3][r] = w.w;
        }
        __syncthreads();
#pragma unroll
        for (int k = 0; k < BKk; k++) {
            float a[8], bb[8];
            *reinterpret_cast<float4*>(&a[0]) = *reinterpret_cast<const float4*>(&As[k][tm]);
            *reinterpret_cast<float4*>(&a[4]) = *reinterpret_cast<const float4*>(&As[k][tm + 4]);
            *reinterpret_cast<float4*>(&bb[0]) = *reinterpret_cast<const float4*>(&Bs[k][tn]);
            *reinterpret_cast<float4*>(&bb[4]) = *reinterpret_cast<const float4*>(&Bs[k][tn + 4]);
#pragma unroll
            for (int i = 0; i < 8; i++)
#pragma unroll
                for (int j = 0; j < 8; j++) acc[i][j] += a[i] * bb[j];
        }
        __syncthreads();
    }
#pragma unroll
    for (int i = 0; i < 8; i++) {
        int m = bm + tm + i;
#pragma unroll
        for (int j = 0; j < 8; j++) {
            int n = bn + tn + j;
            float v = acc[i][j];
            if (bias) v += bias[n];
            if (mode == 1) v = tanhf(v);
            if (mode == 2) {
                int s_ = m >> 5, b_ = m & 31, nh_ = n >> 6, d_ = n & 63;
                C[(((size_t)(b_ * 8 + nh_) * 64) + s_) * 64 + d_] = v;
            } else {
                C[(size_t)m * N + n] = v;
            }
        }
    }
}

// ---------------- host orchestration ----------------
extern "C" void kernel_launch(void* const* d_in, const int* in_sizes, int n_in,
                              void* d_out, int out_size) {
    const int*   tokens  = (const int*)d_in[0];
    const unsigned char* enc_mask = (const unsigned char*)d_in[1];
    const float* enc_out = (const float*)d_in[2];
    const float* embed_w = (const float*)d_in[3];
    const float* g1Wx = (const float*)d_in[4];
    const float* g1Wh = (const float*)d_in[5];
    const float* g1bx = (const float*)d_in[6];
    const float* g1bh = (const float*)d_in[7];
    const float* g2Wx = (const float*)d_in[8];
    const float* g2Wh = (const float*)d_in[9];
    const float* g2bx = (const float*)d_in[10];
    const float* g2bh = (const float*)d_in[11];
    const float* brW  = (const float*)d_in[12];
    const float* brB  = (const float*)d_in[13];
    const float* Wk   = (const float*)d_in[14];
    const float* bk   = (const float*)d_in[15];
    const float* Wq   = (const float*)d_in[16];
    const float* bq   = (const float*)d_in[17];
    const float* Ww   = (const float*)d_in[18];
    const float* bw   = (const float*)d_in[19];
    const float* Wf   = (const float*)d_in[20];
    const float* bf   = (const float*)d_in[21];
    const float* Wo   = (const float*)d_in[22];
    const float* bo   = (const float*)d_in[23];
    float* out = (float*)d_out;

    float* S = nullptr;
    cudaGetSymbolAddress((void**)&S, g_scratch);
    float* feat   = S + OFF_FEAT;
    float* keyup  = S + OFF_KEYUP;
    float* logits = S + OFF_LOGITS;
    float* hbuf   = S + OFF_H;
    float* tmpb   = S + OFF_TMP;
    float* ctxv   = S + OFF_CTXV;
    float* part   = S + OFF_PART;
    float* W1cat  = S + OFF_W1;
    float* W2cat  = S + OFF_W2;
    float* WqT    = S + OFF_WQT;
    float* WfT    = S + OFF_WFT;

    // prep
    k_pack1<<<(1024 * 2048 + 255) / 256, 256>>>(g1Wx, g1Wh, W1cat);
    k_pack2<<<(1536 * 2048 + 255) / 256, 256>>>(g2Wx, g2Wh, W2cat);
    k_transpose<<<(512 * 512 + 255) / 256, 256>>>(Wq, WqT, 512, 512);
    k_transpose<<<(1024 * 1024 + 255) / 256, 256>>>(Wf, WfT, 1024, 1024);
    k_embed<<<B_ * T_, 128>>>(tokens, embed_w, feat);
    k_bridge<<<B_, 512>>>(enc_mask, enc_out, brW, brB, hbuf);
    {   // key_up = enc @ Wk^T + bk  (A rows = (s,b) of enc_out, remap epilogue)
        dim3 g(512 / BN, 2048 / BM);
        sgemm_nt<<<g, 256>>>(enc_out, Wk, bk, keyup, 2048, 512, 1024, 2);
    }

    const int featStride = T_ * FEATW;
    dim3 gGRU(2048 / 128, 4);
    dim3 gWf(1024 / 128, 4);
    for (int t = 0; t < T_; t++) {
        const float* x1 = feat + (size_t)t * FEATW;                 // emb slice
        k_gates<<<gGRU, 256>>>(x1, featStride, 512, hbuf, 512, W1cat, 2048, 256, part);
        k_gru_combine<<<64, 256>>>(part, g1bx, g1bh, hbuf, tmpb, nullptr, 0);
        k_attn<<<B_ * NH_, 128>>>(tmpb, WqT, bq, keyup, Ww, bw, enc_out, enc_mask, ctxv);
        k_gates<<<gWf, 256>>>(ctxv, 1024, 1024, nullptr, 0, WfT, 1024, 256, part);
        k_lin_reduce<<<(32 * 1024) / 256, 256>>>(part, 1024, bf,
                                                 feat + (size_t)t * FEATW + 1024, featStride);
        const float* x2 = feat + (size_t)t * FEATW + 1024;          // ctx slice
        k_gates<<<gGRU, 256>>>(x2, featStride, 1024, tmpb, 512, W2cat, 2048, 384, part);
        k_gru_combine<<<64, 256>>>(part, g2bx, g2bh, tmpb, hbuf,
                                   feat + (size_t)t * FEATW + 512, featStride);
    }

    {   // logits = tanh(feat @ Wo^T + bo)
        dim3 g(512 / BN, 2048 / BM);
        sgemm_nt<<<g, 256>>>(feat, Wo, bo, logits, 2048, 512, 2048, 1);
    }
    {   // out = logits @ embed_w^T
        dim3 g(V_ / BN, 2048 / BM);
        sgemm_nt<<<g, 256>>>(logits, embed_w, nullptr, out, 2048, V_, 512, 0);
    }
}

// round 3
// speedup vs baseline: 1.1504x; 1.1504x over previous
#include <cuda_runtime.h>
#include <cuda_bf16.h>
#include <math.h>
#include <stdint.h>

// Problem dims
#define B_ 32
#define T_ 64
#define S_ 64
#define V_ 32000
#define E_ 512
#define H_ 512
#define U_ 1024
#define NH_ 8
#define D_ 64
#define DV_ 128
#define FEATW 2048   // E + H + U

// ---------------- scratch (one big device global, no allocations) ----------------
#define OFF_FEAT   0ull                         // [B,T,2048]
#define OFF_KEYUP  4194304ull                   // [B,NH,S,D]
#define OFF_LOGITS 5242880ull                   // [B,T,512]
#define OFF_H      6291456ull
#define OFF_TMP    6307840ull
#define OFF_CTXV   6324224ull
#define OFF_PART   6356992ull                   // [4][32][2048]
#define OFF_W1     6619136ull                   // [1024,2048]
#define OFF_W2     8716288ull                   // [1536,2048]
#define OFF_WQT   11862016ull                   // [512,512]
#define OFF_WFT   12124160ull                   // [1024,1024]
#define OFF_AHL   13172736ull                   // [2048,1536] bf16
#define OFF_BHL   14745600ull                   // [32000,1536] bf16
#define SCRATCH_FLOATS 39321600ull

__device__ float g_scratch[SCRATCH_FLOATS];

// ======================= helpers =======================
__device__ __forceinline__ uint32_t smem_to_u32(const void* p) {
    uint32_t a;
    asm("{ .reg .u64 t; cvta.to.shared.u64 t, %1; cvt.u32.u64 %0, t; }" : "=r"(a) : "l"(p));
    return a;
}
__device__ __forceinline__ void cp_async16(uint32_t dst, const void* src) {
    asm volatile("cp.async.cg.shared.global [%0], [%1], 16;" :: "r"(dst), "l"(src));
}
#define CP_COMMIT() asm volatile("cp.async.commit_group;" ::: "memory")
#define CP_WAIT(n)  asm volatile("cp.async.wait_group %0;" :: "n"(n) : "memory")
#define SW128(x) ((x) ^ (((x) >> 3) & 0x70))

__device__ __forceinline__ void ldsm_x4(uint32_t& r0, uint32_t& r1, uint32_t& r2, uint32_t& r3,
                                        uint32_t addr) {
    asm volatile("ldmatrix.sync.aligned.m8n8.x4.shared.b16 {%0,%1,%2,%3}, [%4];"
                 : "=r"(r0), "=r"(r1), "=r"(r2), "=r"(r3) : "r"(addr));
}
__device__ __forceinline__ void mma16816(float& c0, float& c1, float& c2, float& c3,
                                         uint32_t a0, uint32_t a1, uint32_t a2, uint32_t a3,
                                         uint32_t b0, uint32_t b1) {
    asm volatile("mma.sync.aligned.m16n8k16.row.col.f32.bf16.bf16.f32 "
                 "{%0,%1,%2,%3}, {%4,%5,%6,%7}, {%8,%9}, {%0,%1,%2,%3};"
                 : "+f"(c0), "+f"(c1), "+f"(c2), "+f"(c3)
                 : "r"(a0), "r"(a1), "r"(a2), "r"(a3), "r"(b0), "r"(b1));
}

// ---------------- embedding gather ----------------
__global__ void k_embed(const int* __restrict__ tokens, const float* __restrict__ embed_w,
                        float* __restrict__ feat) {
    int bt = blockIdx.x;
    int tok = tokens[bt];
    const float4* src = reinterpret_cast<const float4*>(embed_w + (size_t)tok * E_);
    float4* dst = reinterpret_cast<float4*>(feat + (size_t)bt * FEATW);
    dst[threadIdx.x] = src[threadIdx.x];
}

// ---------------- bridge ----------------
__global__ __launch_bounds__(512) void k_bridge(const unsigned char* __restrict__ mask,
                                                const float* __restrict__ enc_out,
                                                const float* __restrict__ Wb,
                                                const float* __restrict__ bb,
                                                float* __restrict__ h0) {
    int b = blockIdx.x;
    int j = threadIdx.x;
    __shared__ float fn[512];
    __shared__ int sL;
    if (j == 0) {
        int L = S_;
        for (int s = 0; s < S_; s++) if (mask[b * S_ + s]) L--;
        sL = L;
    }
    __syncthreads();
    int L = sL;
    fn[j] = enc_out[((size_t)(L - 1) * B_ + b) * U_ + j];
    __syncthreads();
    float acc = bb[j];
    const float* wr = Wb + (size_t)j * 512;
    for (int k = 0; k < 512; k++) acc += fn[k] * wr[k];
    h0[b * H_ + j] = tanhf(acc);
}

// ---------------- weight packing ----------------
__global__ void k_pack1(const float* __restrict__ Wx, const float* __restrict__ Wh,
                        float* __restrict__ Wc) {
    int idx = blockIdx.x * 256 + threadIdx.x;
    if (idx >= 1024 * 2048) return;
    int k = idx >> 11, col = idx & 2047;
    int g = col >> 9, j = col & 511;
    float v = 0.f;
    if (k < 512) {
        if (g == 0)      v = Wx[(size_t)j * 512 + k];
        else if (g == 1) v = Wx[(size_t)(512 + j) * 512 + k];
        else if (g == 2) v = Wx[(size_t)(1024 + j) * 512 + k];
    } else {
        int kh = k - 512;
        if (g == 0)      v = Wh[(size_t)j * 512 + kh];
        else if (g == 1) v = Wh[(size_t)(512 + j) * 512 + kh];
        else if (g == 3) v = Wh[(size_t)(1024 + j) * 512 + kh];
    }
    Wc[idx] = v;
}
__global__ void k_pack2(const float* __restrict__ Wx, const float* __restrict__ Wh,
                        float* __restrict__ Wc) {
    int idx = blockIdx.x * 256 + threadIdx.x;
    if (idx >= 1536 * 2048) return;
    int k = idx >> 11, col = idx & 2047;
    int g = col >> 9, j = col & 511;
    float v = 0.f;
    if (k < 1024) {
        if (g == 0)      v = Wx[(size_t)j * 1024 + k];
        else if (g == 1) v = Wx[(size_t)(512 + j) * 1024 + k];
        else if (g == 2) v = Wx[(size_t)(1024 + j) * 1024 + k];
    } else {
        int kh = k - 1024;
        if (g == 0)      v = Wh[(size_t)j * 512 + kh];
        else if (g == 1) v = Wh[(size_t)(512 + j) * 512 + kh];
        else if (g == 3) v = Wh[(size_t)(1024 + j) * 512 + kh];
    }
    Wc[idx] = v;
}
__global__ void k_transpose(const float* __restrict__ W, float* __restrict__ WT, int R, int C) {
    int idx = blockIdx.x * 256 + threadIdx.x;
    if (idx >= R * C) return;
    int n = idx / C, k = idx % C;
    WT[(size_t)k * R + n] = W[idx];
}

// ---------------- split-K skinny gates GEMM ----------------
#define GFMA(wv, kk) { \
    const float4* ap_ = reinterpret_cast<const float4*>(&As[(kk) * 32 + m0]); \
    float4 a0_ = ap_[0], a1_ = ap_[1], a2_ = ap_[2], a3_ = ap_[3]; \
    acc[0]  += a0_.x * (wv); acc[1]  += a0_.y * (wv); acc[2]  += a0_.z * (wv); acc[3]  += a0_.w * (wv); \
    acc[4]  += a1_.x * (wv); acc[5]  += a1_.y * (wv); acc[6]  += a1_.z * (wv); acc[7]  += a1_.w * (wv); \
    acc[8]  += a2_.x * (wv); acc[9]  += a2_.y * (wv); acc[10] += a2_.z * (wv); acc[11] += a2_.w * (wv); \
    acc[12] += a3_.x * (wv); acc[13] += a3_.y * (wv); acc[14] += a3_.z * (wv); acc[15] += a3_.w * (wv); }

__global__ __launch_bounds__(256) void k_gates(const float* __restrict__ x, int xs, int Kx,
                                               const float* __restrict__ h, int hs,
                                               const float* __restrict__ W, int N, int chunk,
                                               float* __restrict__ part) {
    __shared__ float As[12288];
    int k0 = blockIdx.y * chunk;
    int tot = chunk * 32;
    for (int idx = threadIdx.x; idx < tot; idx += 256) {
        int k = idx >> 5, m = idx & 31;
        int kk = k0 + k;
        As[idx] = (kk < Kx) ? x[(size_t)m * xs + kk] : h[(size_t)m * hs + (kk - Kx)];
    }
    __syncthreads();
    int col = blockIdx.x * 128 + (threadIdx.x & 127);
    int m0 = (threadIdx.x >> 7) << 4;
    float acc[16];
#pragma unroll
    for (int i = 0; i < 16; i++) acc[i] = 0.f;
    const float* Wp = W + (size_t)k0 * N + col;
    int k = 0;
    for (; k + 4 <= chunk; k += 4) {
        float w0 = Wp[(size_t)(k + 0) * N];
        float w1 = Wp[(size_t)(k + 1) * N];
        float w2 = Wp[(size_t)(k + 2) * N];
        float w3 = Wp[(size_t)(k + 3) * N];
        GFMA(w0, k); GFMA(w1, k + 1); GFMA(w2, k + 2); GFMA(w3, k + 3);
    }
    for (; k < chunk; k++) { float w = Wp[(size_t)k * N]; GFMA(w, k); }
    float* P = part + ((size_t)blockIdx.y * 32 + m0) * N + col;
#pragma unroll
    for (int i = 0; i < 16; i++) P[(size_t)i * N] = acc[i];
}

// ---------------- GRU combine ----------------
__global__ void k_gru_combine(const float* __restrict__ part,
                              const float* __restrict__ bx, const float* __restrict__ bh,
                              const float* __restrict__ h_old, float* __restrict__ h_new,
                              float* __restrict__ feat_out, int featStride) {
    int idx = blockIdx.x * 256 + threadIdx.x;
    int b = idx >> 9, j = idx & 511;
    const float* p = part + (size_t)b * 2048;
    float Sr = 0.f, Sz = 0.f, Xn = 0.f, Hn = 0.f;
#pragma unroll
    for (int kc = 0; kc < 4; kc++) {
        const float* q = p + (size_t)kc * 32 * 2048;
        Sr += q[j]; Sz += q[512 + j]; Xn += q[1024 + j]; Hn += q[1536 + j];
    }
    float r = 1.f / (1.f + expf(-(Sr + bx[j] + bh[j])));
    float z = 1.f / (1.f + expf(-(Sz + bx[512 + j] + bh[512 + j])));
    float n = tanhf(Xn + bx[1024 + j] + r * (Hn + bh[1024 + j]));
    float out = (1.f - z) * n + z * h_old[idx];
    h_new[idx] = out;
    if (feat_out) feat_out[(size_t)b * featStride + j] = out;
}

// ---------------- linear reduce ----------------
__global__ void k_lin_reduce(const float* __restrict__ part, int N,
                             const float* __restrict__ bias,
                             float* __restrict__ out, int outStride) {
    int idx = blockIdx.x * 256 + threadIdx.x;
    int b = idx / N, n = idx % N;
    float s = 0.f;
#pragma unroll
    for (int kc = 0; kc < 4; kc++) s += part[(size_t)kc * 32 * N + (size_t)b * N + n];
    out[(size_t)b * outStride + n] = s + bias[n];
}

// ---------------- fused attention ----------------
__global__ __launch_bounds__(128) void k_attn(const float* __restrict__ tmp,
                                              const float* __restrict__ WqT,
                                              const float* __restrict__ bq,
                                              const float* __restrict__ keyup,
                                              const float* __restrict__ Ww,
                                              const float* __restrict__ bw,
                                              const float* __restrict__ enc_out,
                                              const unsigned char* __restrict__ mask,
                                              float* __restrict__ ctxv) {
    int b = blockIdx.x >> 3, nh = blockIdx.x & 7;
    int tid = threadIdx.x;
    __shared__ float st[512];
    __shared__ float sq[64];
    __shared__ float sa[64];
    for (int i = tid; i < 512; i += 128) st[i] = tmp[b * 512 + i];
    __syncthreads();
    if (tid < 64) {
        float acc = bq[nh * 64 + tid];
        const float* wp = WqT + nh * 64 + tid;
        for (int k = 0; k < 512; k++) acc += st[k] * wp[(size_t)k * 512];
        sq[tid] = acc;
    }
    __syncthreads();
    if (tid < 64) {
        int s = tid;
        const float* kp = keyup + (((size_t)(b * 8 + nh)) * 64 + s) * 64;
        float sc = bw[0];
#pragma unroll 8
        for (int d = 0; d < 64; d++) sc += tanhf(sq[d] + kp[d]) * Ww[d];
        if (mask[b * S_ + s]) sc -= 1e9f;
        sa[s] = sc;
    }
    __syncthreads();
    if (tid == 0) {
        float mx = -1e30f;
        for (int s = 0; s < 64; s++) mx = fmaxf(mx, sa[s]);
        float sum = 0.f;
        for (int s = 0; s < 64; s++) { float e = expf(sa[s] - mx); sa[s] = e; sum += e; }
        float inv = 1.f / sum;
        for (int s = 0; s < 64; s++) sa[s] *= inv;
    }
    __syncthreads();
    float acc = 0.f;
    const float* vp = enc_out + (size_t)b * U_ + nh * 128 + tid;
#pragma unroll
    for (int s = 0; s < 64; s++) acc += sa[s] * vp[(size_t)s * B_ * U_];
    ctxv[b * U_ + nh * 128 + tid] = acc;
}

// ---------------- tiled SGEMM-NT (keyup / logits) ----------------
#define BM 128
#define BN 128
#define BKk 16
__global__ __launch_bounds__(256) void sgemm_nt(const float* __restrict__ A,
                                                const float* __restrict__ Bm,
                                                const float* __restrict__ bias,
                                                float* __restrict__ C,
                                                int M, int N, int K, int mode) {
    __shared__ float As[BKk][BM];
    __shared__ float Bs[BKk][BN];
    const int bm = blockIdx.y * BM, bn = blockIdx.x * BN;
    const int tid = threadIdx.x;
    const int tm = (tid >> 4) << 3;
    const int tn = (tid & 15) << 3;
    float acc[8][8];
#pragma unroll
    for (int i = 0; i < 8; i++)
#pragma unroll
        for (int j = 0; j < 8; j++) acc[i][j] = 0.f;

    for (int k0 = 0; k0 < K; k0 += BKk) {
#pragma unroll
        for (int i = 0; i < 2; i++) {
            int idx = tid + i * 256;
            int r = idx >> 2, c = (idx & 3) << 2;
            float4 v = *reinterpret_cast<const float4*>(A + (size_t)(bm + r) * K + k0 + c);
            As[c][r] = v.x; As[c + 1][r] = v.y; As[c + 2][r] = v.z; As[c + 3][r] = v.w;
            float4 w = *reinterpret_cast<const float4*>(Bm + (size_t)(bn + r) * K + k0 + c);
            Bs[c][r] = w.x; Bs[c + 1][r] = w.y; Bs[c + 2][r] = w.z; Bs[c + 3][r] = w.w;
        }
        __syncthreads();
#pragma unroll
        for (int k = 0; k < BKk; k++) {
            float a[8], bb[8];
            *reinterpret_cast<float4*>(&a[0]) = *reinterpret_cast<const float4*>(&As[k][tm]);
            *reinterpret_cast<float4*>(&a[4]) = *reinterpret_cast<const float4*>(&As[k][tm + 4]);
            *reinterpret_cast<float4*>(&bb[0]) = *reinterpret_cast<const float4*>(&Bs[k][tn]);
            *reinterpret_cast<float4*>(&bb[4]) = *reinterpret_cast<const float4*>(&Bs[k][tn + 4]);
#pragma unroll
            for (int i = 0; i < 8; i++)
#pragma unroll
                for (int j = 0; j < 8; j++) acc[i][j] += a[i] * bb[j];
        }
        __syncthreads();
    }
#pragma unroll
    for (int i = 0; i < 8; i++) {
        int m = bm + tm + i;
#pragma unroll
        for (int j = 0; j < 8; j++) {
            int n = bn + tn + j;
            float v = acc[i][j];
            if (bias) v += bias[n];
            if (mode == 1) v = tanhf(v);
            if (mode == 2) {
                int s_ = m >> 5, b_ = m & 31, nh_ = n >> 6, d_ = n & 63;
                C[(((size_t)(b_ * 8 + nh_) * 64) + s_) * 64 + d_] = v;
            } else {
                C[(size_t)m * N + n] = v;
            }
        }
    }
}

// ============ bf16 hi/lo split conversion ============
// A' rows (K=1536): [hi | hi | lo]   (logits)
// B' rows (K=1536): [hi | lo | hi]   (embed_w)
__global__ void k_convA(const float* __restrict__ L, __nv_bfloat16* __restrict__ A) {
    int idx = blockIdx.x * 256 + threadIdx.x;
    if (idx >= 2048 * 128) return;
    int m = idx >> 7, kg = (idx & 127) << 2;
    float4 v = *reinterpret_cast<const float4*>(L + (size_t)m * 512 + kg);
    __nv_bfloat16 h[4], l[4];
    float x[4] = {v.x, v.y, v.z, v.w};
#pragma unroll
    for (int i = 0; i < 4; i++) {
        h[i] = __float2bfloat16(x[i]);
        l[i] = __float2bfloat16(x[i] - __bfloat162float(h[i]));
    }
    __nv_bfloat162* p0 = reinterpret_cast<__nv_bfloat162*>(A + (size_t)m * 1536 + kg);
    __nv_bfloat162* p1 = reinterpret_cast<__nv_bfloat162*>(A + (size_t)m * 1536 + 512 + kg);
    __nv_bfloat162* p2 = reinterpret_cast<__nv_bfloat162*>(A + (size_t)m * 1536 + 1024 + kg);
    p0[0] = __nv_bfloat162(h[0], h[1]); p0[1] = __nv_bfloat162(h[2], h[3]);
    p1[0] = __nv_bfloat162(h[0], h[1]); p1[1] = __nv_bfloat162(h[2], h[3]);
    p2[0] = __nv_bfloat162(l[0], l[1]); p2[1] = __nv_bfloat162(l[2], l[3]);
}
__global__ void k_convB(const float* __restrict__ W, __nv_bfloat16* __restrict__ Bp) {
    int idx = blockIdx.x * 256 + threadIdx.x;
    if (idx >= 32000 * 128) return;
    int n = idx >> 7, kg = (idx & 127) << 2;
    float4 v = *reinterpret_cast<const float4*>(W + (size_t)n * 512 + kg);
    __nv_bfloat16 h[4], l[4];
    float x[4] = {v.x, v.y, v.z, v.w};
#pragma unroll
    for (int i = 0; i < 4; i++) {
        h[i] = __float2bfloat16(x[i]);
        l[i] = __float2bfloat16(x[i] - __bfloat162float(h[i]));
    }
    __nv_bfloat162* p0 = reinterpret_cast<__nv_bfloat162*>(Bp + (size_t)n * 1536 + kg);
    __nv_bfloat162* p1 = reinterpret_cast<__nv_bfloat162*>(Bp + (size_t)n * 1536 + 512 + kg);
    __nv_bfloat162* p2 = reinterpret_cast<__nv_bfloat162*>(Bp + (size_t)n * 1536 + 1024 + kg);
    p0[0] = __nv_bfloat162(h[0], h[1]); p0[1] = __nv_bfloat162(h[2], h[3]);
    p1[0] = __nv_bfloat162(l[0], l[1]); p1[1] = __nv_bfloat162(l[2], l[3]);
    p2[0] = __nv_bfloat162(h[0], h[1]); p2[1] = __nv_bfloat162(h[2], h[3]);
}

// ============ HMMA bf16 GEMM: C[2048,32000] = A'[2048,1536] @ B'[32000,1536]^T ============
// Block 128x128, 8 warps (4m x 2n), warp tile 32x64, mma m16n8k16.
// K slabs of 64 bf16 (128B SW128 rows), double-buffered cp.async, prefetch distance 2.
#define HG_A_BYTES 16384
#define HG_B_BYTES 16384
#define HG_SMEM_TOTAL (2 * (HG_A_BYTES + HG_B_BYTES))   // 64 KB

__global__ __launch_bounds__(256, 2)
void mma_gemm_hmma(const __nv_bfloat16* __restrict__ Ap, const __nv_bfloat16* __restrict__ Bp,
                   float* __restrict__ C) {
    extern __shared__ char smem[];
    uint32_t sb_a = smem_to_u32(smem);                    // A: 2 x 16KB
    uint32_t sb_b = sb_a + 2 * HG_A_BYTES;                // B: 2 x 16KB
    const int tid = threadIdx.x, lane = tid & 31, wid = tid >> 5;
    const int mt = blockIdx.y, nt = blockIdx.x;
    const int m0 = (wid & 3) * 32;     // warp m-offset in tile
    const int n0 = (wid >> 2) * 64;    // warp n-offset in tile

    const __nv_bfloat16* Ag = Ap + (size_t)mt * 128 * 1536;
    const __nv_bfloat16* Bg = Bp + (size_t)nt * 128 * 1536;

#define HLOAD(s, buf) { \
    uint32_t ab_ = sb_a + (buf) * HG_A_BYTES; \
    uint32_t bb_ = sb_b + (buf) * HG_B_BYTES; \
    const __nv_bfloat16* As_ = Ag + (s) * 64; \
    const __nv_bfloat16* Bs_ = Bg + (s) * 64; \
    _Pragma("unroll") \
    for (int i_ = 0; i_ < 4; i_++) { int ix_ = tid + i_ * 256; int r_ = ix_ >> 3, c_ = ix_ & 7; \
        cp_async16(ab_ + SW128(r_ * 128 + c_ * 16), As_ + (size_t)r_ * 1536 + c_ * 8); } \
    _Pragma("unroll") \
    for (int i_ = 0; i_ < 4; i_++) { int ix_ = tid + i_ * 256; int r_ = ix_ >> 3, c_ = ix_ & 7; \
        cp_async16(bb_ + SW128(r_ * 128 + c_ * 16), Bs_ + (size_t)r_ * 1536 + c_ * 8); } \
    CP_COMMIT(); }

    float acc[2][8][4];
#pragma unroll
    for (int i = 0; i < 2; i++)
#pragma unroll
        for (int j = 0; j < 8; j++)
#pragma unroll
            for (int v = 0; v < 4; v++) acc[i][j][v] = 0.f;

    HLOAD(0, 0);
    HLOAD(1, 1);

    // per-lane ldmatrix address components
    const int a_row_off = ((lane >> 3) & 1) * 8 + (lane & 7);   // + m base
    const int a_kb_off  = ((lane >> 4) & 1) * 16;
    const int b_row_off = ((lane >> 4) & 1) * 8 + (lane & 7);   // + n base
    const int b_kb_off  = ((lane >> 3) & 1) * 16;

    for (int s = 0; s < 24; s++) {
        int buf = s & 1;
        CP_WAIT(1);
        __syncthreads();
        uint32_t abase = sb_a + buf * HG_A_BYTES;
        uint32_t bbase = sb_b + buf * HG_B_BYTES;
#pragma unroll
        for (int kk = 0; kk < 4; kk++) {
            uint32_t a[2][4];
#pragma unroll
            for (int mi = 0; mi < 2; mi++) {
                int row = m0 + mi * 16 + a_row_off;
                int kb = kk * 32 + a_kb_off;
                ldsm_x4(a[mi][0], a[mi][1], a[mi][2], a[mi][3], abase + SW128(row * 128 + kb));
            }
            uint32_t bf[4][4];
#pragma unroll
            for (int ng = 0; ng < 4; ng++) {
                int row = n0 + ng * 16 + b_row_off;
                int kb = kk * 32 + b_kb_off;
                ldsm_x4(bf[ng][0], bf[ng][1], bf[ng][2], bf[ng][3], bbase + SW128(row * 128 + kb));
            }
#pragma unroll
            for (int mi = 0; mi < 2; mi++)
#pragma unroll
                for (int nj = 0; nj < 8; nj++) {
                    uint32_t b0 = bf[nj >> 1][(nj & 1) * 2];
                    uint32_t b1 = bf[nj >> 1][(nj & 1) * 2 + 1];
                    mma16816(acc[mi][nj][0], acc[mi][nj][1], acc[mi][nj][2], acc[mi][nj][3],
                             a[mi][0], a[mi][1], a[mi][2], a[mi][3], b0, b1);
                }
        }
        __syncthreads();
        if (s + 2 < 24) HLOAD(s + 2, buf);
    }

    // epilogue: direct float2 stores
    int gr = mt * 128 + m0 + (lane >> 2);
    int gc = nt * 128 + n0 + (lane & 3) * 2;
#pragma unroll
    for (int mi = 0; mi < 2; mi++) {
#pragma unroll
        for (int nj = 0; nj < 8; nj++) {
            float* p0 = C + (size_t)(gr + mi * 16) * V_ + gc + nj * 8;
            float* p1 = C + (size_t)(gr + mi * 16 + 8) * V_ + gc + nj * 8;
            *reinterpret_cast<float2*>(p0) = make_float2(acc[mi][nj][0], acc[mi][nj][1]);
            *reinterpret_cast<float2*>(p1) = make_float2(acc[mi][nj][2], acc[mi][nj][3]);
        }
    }
}

// ---------------- host orchestration ----------------
extern "C" void kernel_launch(void* const* d_in, const int* in_sizes, int n_in,
                              void* d_out, int out_size) {
    const int*   tokens  = (const int*)d_in[0];
    const unsigned char* enc_mask = (const unsigned char*)d_in[1];
    const float* enc_out = (const float*)d_in[2];
    const float* embed_w = (const float*)d_in[3];
    const float* g1Wx = (const float*)d_in[4];
    const float* g1Wh = (const float*)d_in[5];
    const float* g1bx = (const float*)d_in[6];
    const float* g1bh = (const float*)d_in[7];
    const float* g2Wx = (const float*)d_in[8];
    const float* g2Wh = (const float*)d_in[9];
    const float* g2bx = (const float*)d_in[10];
    const float* g2bh = (const float*)d_in[11];
    const float* brW  = (const float*)d_in[12];
    const float* brB  = (const float*)d_in[13];
    const float* Wk   = (const float*)d_in[14];
    const float* bk   = (const float*)d_in[15];
    const float* Wq   = (const float*)d_in[16];
    const float* bq   = (const float*)d_in[17];
    const float* Ww   = (const float*)d_in[18];
    const float* bw   = (const float*)d_in[19];
    const float* Wf   = (const float*)d_in[20];
    const float* bf   = (const float*)d_in[21];
    const float* Wo   = (const float*)d_in[22];
    const float* bo   = (const float*)d_in[23];
    float* out = (float*)d_out;

    float* S = nullptr;
    cudaGetSymbolAddress((void**)&S, g_scratch);
    float* feat   = S + OFF_FEAT;
    float* keyup  = S + OFF_KEYUP;
    float* logits = S + OFF_LOGITS;
    float* hbuf   = S + OFF_H;
    float* tmpb   = S + OFF_TMP;
    float* ctxv   = S + OFF_CTXV;
    float* part   = S + OFF_PART;
    float* W1cat  = S + OFF_W1;
    float* W2cat  = S + OFF_W2;
    float* WqT    = S + OFF_WQT;
    float* WfT    = S + OFF_WFT;
    __nv_bfloat16* Ahl = (__nv_bfloat16*)(S + OFF_AHL);
    __nv_bfloat16* Bhl = (__nv_bfloat16*)(S + OFF_BHL);

    // prep
    k_pack1<<<(1024 * 2048 + 255) / 256, 256>>>(g1Wx, g1Wh, W1cat);
    k_pack2<<<(1536 * 2048 + 255) / 256, 256>>>(g2Wx, g2Wh, W2cat);
    k_transpose<<<(512 * 512 + 255) / 256, 256>>>(Wq, WqT, 512, 512);
    k_transpose<<<(1024 * 1024 + 255) / 256, 256>>>(Wf, WfT, 1024, 1024);
    k_embed<<<B_ * T_, 128>>>(tokens, embed_w, feat);
    k_bridge<<<B_, 512>>>(enc_mask, enc_out, brW, brB, hbuf);
    k_convB<<<(32000 * 128 + 255) / 256, 256>>>(embed_w, Bhl);
    {   // key_up = enc @ Wk^T + bk
        dim3 g(512 / BN, 2048 / BM);
        sgemm_nt<<<g, 256>>>(enc_out, Wk, bk, keyup, 2048, 512, 1024, 2);
    }

    const int featStride = T_ * FEATW;
    dim3 gGRU(2048 / 128, 4);
    dim3 gWf(1024 / 128, 4);
    for (int t = 0; t < T_; t++) {
        const float* x1 = feat + (size_t)t * FEATW;
        k_gates<<<gGRU, 256>>>(x1, featStride, 512, hbuf, 512, W1cat, 2048, 256, part);
        k_gru_combine<<<64, 256>>>(part, g1bx, g1bh, hbuf, tmpb, nullptr, 0);
        k_attn<<<B_ * NH_, 128>>>(tmpb, WqT, bq, keyup, Ww, bw, enc_out, enc_mask, ctxv);
        k_gates<<<gWf, 256>>>(ctxv, 1024, 1024, nullptr, 0, WfT, 1024, 256, part);
        k_lin_reduce<<<(32 * 1024) / 256, 256>>>(part, 1024, bf,
                                                 feat + (size_t)t * FEATW + 1024, featStride);
        const float* x2 = feat + (size_t)t * FEATW + 1024;
        k_gates<<<gGRU, 256>>>(x2, featStride, 1024, tmpb, 512, W2cat, 2048, 384, part);
        k_gru_combine<<<64, 256>>>(part, g2bx, g2bh, tmpb, hbuf,
                                   feat + (size_t)t * FEATW + 512, featStride);
    }

    {   // logits = tanh(feat @ Wo^T + bo)
        dim3 g(512 / BN, 2048 / BM);
        sgemm_nt<<<g, 256>>>(feat, Wo, bo, logits, 2048, 512, 2048, 1);
    }
    // out = logits @ embed_w^T via HMMA bf16 hi/lo K-extended GEMM
    k_convA<<<(2048 * 128 + 255) / 256, 256>>>(logits, Ahl);
    cudaFuncSetAttribute(mma_gemm_hmma, cudaFuncAttributeMaxDynamicSharedMemorySize, HG_SMEM_TOTAL);
    {
        dim3 g(V_ / 128, 2048 / 128);
        mma_gemm_hmma<<<g, 256, HG_SMEM_TOTAL>>>(Ahl, Bhl, out);
    }
}

// round 4
// speedup vs baseline: 1.5468x; 1.3446x over previous
#include <cuda_runtime.h>
#include <cuda_bf16.h>
#include <math.h>
#include <stdint.h>

// Problem dims
#define B_ 32
#define T_ 64
#define S_ 64
#define V_ 32000
#define E_ 512
#define H_ 512
#define U_ 1024
#define NH_ 8
#define D_ 64
#define DV_ 128
#define FEATW 2048   // E + H + U
#define NB 148       // persistent grid size (<= SM count)

// ---------------- scratch ----------------
#define OFF_FEAT   0ull
#define OFF_KEYUP  4194304ull
#define OFF_LOGITS 5242880ull
#define OFF_H      6291456ull
#define OFF_TMP    6307840ull
#define OFF_CTXV   6324224ull
#define OFF_PART   6356992ull                   // [8][32][2048] = 524288
#define OFF_W1     6881280ull                   // [1024,2048]
#define OFF_W2     8978432ull                   // [1536,2048]
#define OFF_WQT   12124160ull                   // [512,512]
#define OFF_WFT   12386304ull                   // [1024,1024]
#define OFF_AHL   13434880ull                   // [2048,1536] bf16
#define OFF_BHL   15007744ull                   // [32000,1536] bf16
#define SCRATCH_FLOATS 39583744ull

__device__ float g_scratch[SCRATCH_FLOATS];
__device__ unsigned g_bar_ctr;

// ======================= helpers =======================
__device__ __forceinline__ uint32_t smem_to_u32(const void* p) {
    uint32_t a;
    asm("{ .reg .u64 t; cvta.to.shared.u64 t, %1; cvt.u32.u64 %0, t; }" : "=r"(a) : "l"(p));
    return a;
}
__device__ __forceinline__ void cp_async16(uint32_t dst, const void* src) {
    asm volatile("cp.async.cg.shared.global [%0], [%1], 16;" :: "r"(dst), "l"(src));
}
#define CP_COMMIT() asm volatile("cp.async.commit_group;" ::: "memory")
#define CP_WAIT(n)  asm volatile("cp.async.wait_group %0;" :: "n"(n) : "memory")
#define SW128(x) ((x) ^ (((x) >> 3) & 0x70))

__device__ __forceinline__ void ldsm_x4(uint32_t& r0, uint32_t& r1, uint32_t& r2, uint32_t& r3,
                                        uint32_t addr) {
    asm volatile("ldmatrix.sync.aligned.m8n8.x4.shared.b16 {%0,%1,%2,%3}, [%4];"
                 : "=r"(r0), "=r"(r1), "=r"(r2), "=r"(r3) : "r"(addr));
}
__device__ __forceinline__ void mma16816(float& c0, float& c1, float& c2, float& c3,
                                         uint32_t a0, uint32_t a1, uint32_t a2, uint32_t a3,
                                         uint32_t b0, uint32_t b1) {
    asm volatile("mma.sync.aligned.m16n8k16.row.col.f32.bf16.bf16.f32 "
                 "{%0,%1,%2,%3}, {%4,%5,%6,%7}, {%8,%9}, {%0,%1,%2,%3};"
                 : "+f"(c0), "+f"(c1), "+f"(c2), "+f"(c3)
                 : "r"(a0), "r"(a1), "r"(a2), "r"(a3), "r"(b0), "r"(b1));
}

// grid barrier: monotonic counter, zeroed by k_zero before each launch
__device__ __forceinline__ void gsync(unsigned& gen) {
    __syncthreads();
    if (threadIdx.x == 0) {
        __threadfence();
        atomicAdd(&g_bar_ctr, 1u);
        unsigned target = (gen + 1u) * (unsigned)NB;
        unsigned v;
        do {
            asm volatile("ld.acquire.gpu.u32 %0, [%1];" : "=r"(v) : "l"(&g_bar_ctr) : "memory");
        } while (v < target);
    }
    gen++;
    __syncthreads();
}

__global__ void k_zero() { g_bar_ctr = 0u; }

// ---------------- prep kernels ----------------
__global__ void k_embed(const int* __restrict__ tokens, const float* __restrict__ embed_w,
                        float* __restrict__ feat) {
    int bt = blockIdx.x;
    int tok = tokens[bt];
    const float4* src = reinterpret_cast<const float4*>(embed_w + (size_t)tok * E_);
    float4* dst = reinterpret_cast<float4*>(feat + (size_t)bt * FEATW);
    dst[threadIdx.x] = src[threadIdx.x];
}

__global__ __launch_bounds__(512) void k_bridge(const unsigned char* __restrict__ mask,
                                                const float* __restrict__ enc_out,
                                                const float* __restrict__ Wb,
                                                const float* __restrict__ bb,
                                                float* __restrict__ h0) {
    int b = blockIdx.x;
    int j = threadIdx.x;
    __shared__ float fn[512];
    __shared__ int sL;
    if (j == 0) {
        int L = S_;
        for (int s = 0; s < S_; s++) if (mask[b * S_ + s]) L--;
        sL = L;
    }
    __syncthreads();
    int L = sL;
    fn[j] = enc_out[((size_t)(L - 1) * B_ + b) * U_ + j];
    __syncthreads();
    float acc = bb[j];
    const float* wr = Wb + (size_t)j * 512;
    for (int k = 0; k < 512; k++) acc += fn[k] * wr[k];
    h0[b * H_ + j] = tanhf(acc);
}

__global__ void k_pack1(const float* __restrict__ Wx, const float* __restrict__ Wh,
                        float* __restrict__ Wc) {
    int idx = blockIdx.x * 256 + threadIdx.x;
    if (idx >= 1024 * 2048) return;
    int k = idx >> 11, col = idx & 2047;
    int g = col >> 9, j = col & 511;
    float v = 0.f;
    if (k < 512) {
        if (g == 0)      v = Wx[(size_t)j * 512 + k];
        else if (g == 1) v = Wx[(size_t)(512 + j) * 512 + k];
        else if (g == 2) v = Wx[(size_t)(1024 + j) * 512 + k];
    } else {
        int kh = k - 512;
        if (g == 0)      v = Wh[(size_t)j * 512 + kh];
        else if (g == 1) v = Wh[(size_t)(512 + j) * 512 + kh];
        else if (g == 3) v = Wh[(size_t)(1024 + j) * 512 + kh];
    }
    Wc[idx] = v;
}
__global__ void k_pack2(const float* __restrict__ Wx, const float* __restrict__ Wh,
                        float* __restrict__ Wc) {
    int idx = blockIdx.x * 256 + threadIdx.x;
    if (idx >= 1536 * 2048) return;
    int k = idx >> 11, col = idx & 2047;
    int g = col >> 9, j = col & 511;
    float v = 0.f;
    if (k < 1024) {
        if (g == 0)      v = Wx[(size_t)j * 1024 + k];
        else if (g == 1) v = Wx[(size_t)(512 + j) * 1024 + k];
        else if (g == 2) v = Wx[(size_t)(1024 + j) * 1024 + k];
    } else {
        int kh = k - 1024;
        if (g == 0)      v = Wh[(size_t)j * 512 + kh];
        else if (g == 1) v = Wh[(size_t)(512 + j) * 512 + kh];
        else if (g == 3) v = Wh[(size_t)(1024 + j) * 512 + kh];
    }
    Wc[idx] = v;
}
__global__ void k_transpose(const float* __restrict__ W, float* __restrict__ WT, int R, int C) {
    int idx = blockIdx.x * 256 + threadIdx.x;
    if (idx >= R * C) return;
    int n = idx / C, k = idx % C;
    WT[(size_t)k * R + n] = W[idx];
}

// ---------------- persistent recurrence kernel ----------------
#define GFMA(wv, kk) { \
    const float4* ap_ = reinterpret_cast<const float4*>(&sAs[(kk) * 32 + m0]); \
    float4 a0_ = ap_[0], a1_ = ap_[1], a2_ = ap_[2], a3_ = ap_[3]; \
    acc[0]  += a0_.x * (wv); acc[1]  += a0_.y * (wv); acc[2]  += a0_.z * (wv); acc[3]  += a0_.w * (wv); \
    acc[4]  += a1_.x * (wv); acc[5]  += a1_.y * (wv); acc[6]  += a1_.z * (wv); acc[7]  += a1_.w * (wv); \
    acc[8]  += a2_.x * (wv); acc[9]  += a2_.y * (wv); acc[10] += a2_.z * (wv); acc[11] += a2_.w * (wv); \
    acc[12] += a3_.x * (wv); acc[13] += a3_.y * (wv); acc[14] += a3_.z * (wv); acc[15] += a3_.w * (wv); }

__device__ __forceinline__ void phase_gates(const float* __restrict__ x, int xs, int Kx,
                                            const float* __restrict__ h, int hs,
                                            const float* __restrict__ W, int N,
                                            int chunk, int nkc, int ncb,
                                            float* __restrict__ part, float* sAs,
                                            int bid, int tid) {
    for (int v = bid; v < ncb * nkc; v += NB) {
        int cb = v % ncb, kc = v / ncb;
        int k0 = kc * chunk;
        int tot = chunk * 32;
        for (int idx = tid; idx < tot; idx += 256) {
            int k = idx >> 5, m = idx & 31;
            int kk = k0 + k;
            sAs[idx] = (kk < Kx) ? x[(size_t)m * xs + kk] : h[(size_t)m * hs + (kk - Kx)];
        }
        __syncthreads();
        int col = cb * 128 + (tid & 127);
        int m0 = (tid >> 7) << 4;
        float acc[16];
#pragma unroll
        for (int i = 0; i < 16; i++) acc[i] = 0.f;
        const float* Wp = W + (size_t)k0 * N + col;
        int k = 0;
        for (; k + 4 <= chunk; k += 4) {
            float w0 = Wp[(size_t)(k + 0) * N];
            float w1 = Wp[(size_t)(k + 1) * N];
            float w2 = Wp[(size_t)(k + 2) * N];
            float w3 = Wp[(size_t)(k + 3) * N];
            GFMA(w0, k); GFMA(w1, k + 1); GFMA(w2, k + 2); GFMA(w3, k + 3);
        }
        float* P = part + ((size_t)kc * 32 + m0) * N + col;
#pragma unroll
        for (int i = 0; i < 16; i++) P[(size_t)i * N] = acc[i];
        __syncthreads();
    }
}

__device__ __forceinline__ void phase_combine(const float* __restrict__ part,
                                              const float* __restrict__ bx,
                                              const float* __restrict__ bh,
                                              const float* __restrict__ h_old,
                                              float* __restrict__ h_new,
                                              float* __restrict__ feat_out, int fs,
                                              int bid, int tid) {
    int idx = bid * 256 + tid;
    if (idx < 16384) {
        int b = idx >> 9, j = idx & 511;
        const float* p = part + (size_t)b * 2048;
        float Sr = 0.f, Sz = 0.f, Xn = 0.f, Hn = 0.f;
#pragma unroll
        for (int kc = 0; kc < 8; kc++) {
            const float* q = p + (size_t)kc * 32 * 2048;
            Sr += q[j]; Sz += q[512 + j]; Xn += q[1024 + j]; Hn += q[1536 + j];
        }
        float r = 1.f / (1.f + expf(-(Sr + bx[j] + bh[j])));
        float z = 1.f / (1.f + expf(-(Sz + bx[512 + j] + bh[512 + j])));
        float n = tanhf(Xn + bx[1024 + j] + r * (Hn + bh[1024 + j]));
        float outv = (1.f - z) * n + z * h_old[idx];
        h_new[idx] = outv;
        if (feat_out) feat_out[(size_t)b * fs + j] = outv;
    }
}

__global__ __launch_bounds__(256, 1)
void k_persistent(const float* __restrict__ W1cat, const float* __restrict__ W2cat,
                  const float* __restrict__ WqT, const float* __restrict__ WfT,
                  const float* __restrict__ g1bx, const float* __restrict__ g1bh,
                  const float* __restrict__ g2bx, const float* __restrict__ g2bh,
                  const float* __restrict__ bq, const float* __restrict__ Ww,
                  const float* __restrict__ bw, const float* __restrict__ bf,
                  const float* __restrict__ enc_out, const unsigned char* __restrict__ mask,
                  const float* __restrict__ keyup,
                  float* __restrict__ feat, float* __restrict__ hbuf,
                  float* __restrict__ tmpb, float* __restrict__ ctxv,
                  float* __restrict__ part) {
    __shared__ float sbuf[6144];   // 24KB: gates staging / attention scratch
    const int bid = blockIdx.x, tid = threadIdx.x;
    const int featStride = T_ * FEATW;
    unsigned gen = 0;

    for (int t = 0; t < T_; t++) {
        // --- GRU1 gates: [emb_t | h] @ W1cat ---
        const float* x1 = feat + (size_t)t * FEATW;
        phase_gates(x1, featStride, 512, hbuf, 512, W1cat, 2048, 128, 8, 16, part, sbuf, bid, tid);
        gsync(gen);
        phase_combine(part, g1bx, g1bh, hbuf, tmpb, nullptr, 0, bid, tid);
        gsync(gen);

        // --- attention: 256 (b,nh) pairs ---
        for (int p = bid; p < 256; p += NB) {
            int b = p >> 3, nh = p & 7;
            float* st = sbuf;          // 512
            float* sq = sbuf + 512;    // 64
            float* sa = sbuf + 576;    // 64
            for (int i = tid; i < 512; i += 256) st[i] = tmpb[b * 512 + i];
            __syncthreads();
            if (tid < 64) {
                float acc = bq[nh * 64 + tid];
                const float* wp = WqT + nh * 64 + tid;
                for (int k = 0; k < 512; k++) acc += st[k] * wp[(size_t)k * 512];
                sq[tid] = acc;
            }
            __syncthreads();
            if (tid < 64) {
                int s = tid;
                const float* kp = keyup + (((size_t)(b * 8 + nh)) * 64 + s) * 64;
                float sc = bw[0];
#pragma unroll 8
                for (int d = 0; d < 64; d++) sc += tanhf(sq[d] + kp[d]) * Ww[d];
                if (mask[b * S_ + s]) sc -= 1e9f;
                sa[s] = sc;
            }
            __syncthreads();
            if (tid == 0) {
                float mx = -1e30f;
                for (int s = 0; s < 64; s++) mx = fmaxf(mx, sa[s]);
                float sum = 0.f;
                for (int s = 0; s < 64; s++) { float e = expf(sa[s] - mx); sa[s] = e; sum += e; }
                float inv = 1.f / sum;
                for (int s = 0; s < 64; s++) sa[s] *= inv;
            }
            __syncthreads();
            if (tid < 128) {
                float acc = 0.f;
                const float* vp = enc_out + (size_t)b * U_ + nh * 128 + tid;
#pragma unroll
                for (int s = 0; s < 64; s++) acc += sa[s] * vp[(size_t)s * B_ * U_];
                ctxv[b * U_ + nh * 128 + tid] = acc;
            }
            __syncthreads();
        }
        gsync(gen);

        // --- Wf: ctx = attn_ctx @ WfT (split-K partials) ---
        phase_gates(ctxv, 1024, 1024, nullptr, 0, WfT, 1024, 128, 8, 8, part, sbuf, bid, tid);
        gsync(gen);

        // --- lin reduce: ctx final (+bias) -> ctxv and feat ctx slot ---
        {
            int idx = bid * 256 + tid;
            if (idx < 32768) {
                int b = idx >> 10, n = idx & 1023;
                float s = bf[n];
#pragma unroll
                for (int kc = 0; kc < 8; kc++) s += part[(size_t)kc * 32 * 1024 + (size_t)b * 1024 + n];
                ctxv[b * 1024 + n] = s;
                feat[((size_t)b * T_ + t) * FEATW + 1024 + n] = s;
            }
        }
        gsync(gen);

        // --- GRU2 gates: [ctx | tmp] @ W2cat ---
        phase_gates(ctxv, 1024, 1024, tmpb, 512, W2cat, 2048, 192, 8, 16, part, sbuf, bid, tid);
        gsync(gen);
        phase_combine(part, g2bx, g2bh, tmpb, hbuf,
                      feat + (size_t)t * FEATW + 512, featStride, bid, tid);
        gsync(gen);
    }
}

// ---------------- tiled SGEMM-NT (keyup / logits) ----------------
#define BM 128
#define BN 128
#define BKk 16
__global__ __launch_bounds__(256) void sgemm_nt(const float* __restrict__ A,
                                                const float* __restrict__ Bm,
                                                const float* __restrict__ bias,
                                                float* __restrict__ C,
                                                int M, int N, int K, int mode) {
    __shared__ float As[BKk][BM];
    __shared__ float Bs[BKk][BN];
    const int bm = blockIdx.y * BM, bn = blockIdx.x * BN;
    const int tid = threadIdx.x;
    const int tm = (tid >> 4) << 3;
    const int tn = (tid & 15) << 3;
    float acc[8][8];
#pragma unroll
    for (int i = 0; i < 8; i++)
#pragma unroll
        for (int j = 0; j < 8; j++) acc[i][j] = 0.f;

    for (int k0 = 0; k0 < K; k0 += BKk) {
#pragma unroll
        for (int i = 0; i < 2; i++) {
            int idx = tid + i * 256;
            int r = idx >> 2, c = (idx & 3) << 2;
            float4 v = *reinterpret_cast<const float4*>(A + (size_t)(bm + r) * K + k0 + c);
            As[c][r] = v.x; As[c + 1][r] = v.y; As[c + 2][r] = v.z; As[c + 3][r] = v.w;
            float4 w = *reinterpret_cast<const float4*>(Bm + (size_t)(bn + r) * K + k0 + c);
            Bs[c][r] = w.x; Bs[c + 1][r] = w.y; Bs[c + 2][r] = w.z; Bs[c + 3][r] = w.w;
        }
        __syncthreads();
#pragma unroll
        for (int k = 0; k < BKk; k++) {
            float a[8], bb[8];
            *reinterpret_cast<float4*>(&a[0]) = *reinterpret_cast<const float4*>(&As[k][tm]);
            *reinterpret_cast<float4*>(&a[4]) = *reinterpret_cast<const float4*>(&As[k][tm + 4]);
            *reinterpret_cast<float4*>(&bb[0]) = *reinterpret_cast<const float4*>(&Bs[k][tn]);
            *reinterpret_cast<float4*>(&bb[4]) = *reinterpret_cast<const float4*>(&Bs[k][tn + 4]);
#pragma unroll
            for (int i = 0; i < 8; i++)
#pragma unroll
                for (int j = 0; j < 8; j++) acc[i][j] += a[i] * bb[j];
        }
        __syncthreads();
    }
#pragma unroll
    for (int i = 0; i < 8; i++) {
        int m = bm + tm + i;
#pragma unroll
        for (int j = 0; j < 8; j++) {
            int n = bn + tn + j;
            float v = acc[i][j];
            if (bias) v += bias[n];
            if (mode == 1) v = tanhf(v);
            if (mode == 2) {
                int s_ = m >> 5, b_ = m & 31, nh_ = n >> 6, d_ = n & 63;
                C[(((size_t)(b_ * 8 + nh_) * 64) + s_) * 64 + d_] = v;
            } else {
                C[(size_t)m * N + n] = v;
            }
        }
    }
}

// ============ bf16 hi/lo split conversion ============
__global__ void k_convA(const float* __restrict__ L, __nv_bfloat16* __restrict__ A) {
    int idx = blockIdx.x * 256 + threadIdx.x;
    if (idx >= 2048 * 128) return;
    int m = idx >> 7, kg = (idx & 127) << 2;
    float4 v = *reinterpret_cast<const float4*>(L + (size_t)m * 512 + kg);
    __nv_bfloat16 h[4], l[4];
    float x[4] = {v.x, v.y, v.z, v.w};
#pragma unroll
    for (int i = 0; i < 4; i++) {
        h[i] = __float2bfloat16(x[i]);
        l[i] = __float2bfloat16(x[i] - __bfloat162float(h[i]));
    }
    __nv_bfloat162* p0 = reinterpret_cast<__nv_bfloat162*>(A + (size_t)m * 1536 + kg);
    __nv_bfloat162* p1 = reinterpret_cast<__nv_bfloat162*>(A + (size_t)m * 1536 + 512 + kg);
    __nv_bfloat162* p2 = reinterpret_cast<__nv_bfloat162*>(A + (size_t)m * 1536 + 1024 + kg);
    p0[0] = __nv_bfloat162(h[0], h[1]); p0[1] = __nv_bfloat162(h[2], h[3]);
    p1[0] = __nv_bfloat162(h[0], h[1]); p1[1] = __nv_bfloat162(h[2], h[3]);
    p2[0] = __nv_bfloat162(l[0], l[1]); p2[1] = __nv_bfloat162(l[2], l[3]);
}
__global__ void k_convB(const float* __restrict__ W, __nv_bfloat16* __restrict__ Bp) {
    int idx = blockIdx.x * 256 + threadIdx.x;
    if (idx >= 32000 * 128) return;
    int n = idx >> 7, kg = (idx & 127) << 2;
    float4 v = *reinterpret_cast<const float4*>(W + (size_t)n * 512 + kg);
    __nv_bfloat16 h[4], l[4];
    float x[4] = {v.x, v.y, v.z, v.w};
#pragma unroll
    for (int i = 0; i < 4; i++) {
        h[i] = __float2bfloat16(x[i]);
        l[i] = __float2bfloat16(x[i] - __bfloat162float(h[i]));
    }
    __nv_bfloat162* p0 = reinterpret_cast<__nv_bfloat162*>(Bp + (size_t)n * 1536 + kg);
    __nv_bfloat162* p1 = reinterpret_cast<__nv_bfloat162*>(Bp + (size_t)n * 1536 + 512 + kg);
    __nv_bfloat162* p2 = reinterpret_cast<__nv_bfloat162*>(Bp + (size_t)n * 1536 + 1024 + kg);
    p0[0] = __nv_bfloat162(h[0], h[1]); p0[1] = __nv_bfloat162(h[2], h[3]);
    p1[0] = __nv_bfloat162(l[0], l[1]); p1[1] = __nv_bfloat162(l[2], l[3]);
    p2[0] = __nv_bfloat162(h[0], h[1]); p2[1] = __nv_bfloat162(h[2], h[3]);
}

// ============ HMMA bf16 GEMM: C[2048,32000] = A'[2048,1536] @ B'[32000,1536]^T ============
#define HG_A_BYTES 16384
#define HG_B_BYTES 16384
#define HG_SMEM_TOTAL (2 * (HG_A_BYTES + HG_B_BYTES))   // 64 KB

__global__ __launch_bounds__(256, 2)
void mma_gemm_hmma(const __nv_bfloat16* __restrict__ Ap, const __nv_bfloat16* __restrict__ Bp,
                   float* __restrict__ C) {
    extern __shared__ char smem[];
    uint32_t sb_a = smem_to_u32(smem);
    uint32_t sb_b = sb_a + 2 * HG_A_BYTES;
    const int tid = threadIdx.x, lane = tid & 31, wid = tid >> 5;
    const int mt = blockIdx.y, nt = blockIdx.x;
    const int m0 = (wid & 3) * 32;
    const int n0 = (wid >> 2) * 64;

    const __nv_bfloat16* Ag = Ap + (size_t)mt * 128 * 1536;
    const __nv_bfloat16* Bg = Bp + (size_t)nt * 128 * 1536;

#define HLOAD(s, buf) { \
    uint32_t ab_ = sb_a + (buf) * HG_A_BYTES; \
    uint32_t bb_ = sb_b + (buf) * HG_B_BYTES; \
    const __nv_bfloat16* As_ = Ag + (s) * 64; \
    const __nv_bfloat16* Bs_ = Bg + (s) * 64; \
    _Pragma("unroll") \
    for (int i_ = 0; i_ < 4; i_++) { int ix_ = tid + i_ * 256; int r_ = ix_ >> 3, c_ = ix_ & 7; \
        cp_async16(ab_ + SW128(r_ * 128 + c_ * 16), As_ + (size_t)r_ * 1536 + c_ * 8); } \
    _Pragma("unroll") \
    for (int i_ = 0; i_ < 4; i_++) { int ix_ = tid + i_ * 256; int r_ = ix_ >> 3, c_ = ix_ & 7; \
        cp_async16(bb_ + SW128(r_ * 128 + c_ * 16), Bs_ + (size_t)r_ * 1536 + c_ * 8); } \
    CP_COMMIT(); }

    float acc[2][8][4];
#pragma unroll
    for (int i = 0; i < 2; i++)
#pragma unroll
        for (int j = 0; j < 8; j++)
#pragma unroll
            for (int v = 0; v < 4; v++) acc[i][j][v] = 0.f;

    HLOAD(0, 0);
    HLOAD(1, 1);

    const int a_row_off = ((lane >> 3) & 1) * 8 + (lane & 7);
    const int a_kb_off  = ((lane >> 4) & 1) * 16;
    const int b_row_off = ((lane >> 4) & 1) * 8 + (lane & 7);
    const int b_kb_off  = ((lane >> 3) & 1) * 16;

    for (int s = 0; s < 24; s++) {
        int buf = s & 1;
        CP_WAIT(1);
        __syncthreads();
        uint32_t abase = sb_a + buf * HG_A_BYTES;
        uint32_t bbase = sb_b + buf * HG_B_BYTES;
#pragma unroll
        for (int kk = 0; kk < 4; kk++) {
            uint32_t a[2][4];
#pragma unroll
            for (int mi = 0; mi < 2; mi++) {
                int row = m0 + mi * 16 + a_row_off;
                int kb = kk * 32 + a_kb_off;
                ldsm_x4(a[mi][0], a[mi][1], a[mi][2], a[mi][3], abase + SW128(row * 128 + kb));
            }
            uint32_t bfr[4][4];
#pragma unroll
            for (int ng = 0; ng < 4; ng++) {
                int row = n0 + ng * 16 + b_row_off;
                int kb = kk * 32 + b_kb_off;
                ldsm_x4(bfr[ng][0], bfr[ng][1], bfr[ng][2], bfr[ng][3], bbase + SW128(row * 128 + kb));
            }
#pragma unroll
            for (int mi = 0; mi < 2; mi++)
#pragma unroll
                for (int nj = 0; nj < 8; nj++) {
                    uint32_t b0 = bfr[nj >> 1][(nj & 1) * 2];
                    uint32_t b1 = bfr[nj >> 1][(nj & 1) * 2 + 1];
                    mma16816(acc[mi][nj][0], acc[mi][nj][1], acc[mi][nj][2], acc[mi][nj][3],
                             a[mi][0], a[mi][1], a[mi][2], a[mi][3], b0, b1);
                }
        }
        __syncthreads();
        if (s + 2 < 24) HLOAD(s + 2, buf);
    }

    int gr = mt * 128 + m0 + (lane >> 2);
    int gc = nt * 128 + n0 + (lane & 3) * 2;
#pragma unroll
    for (int mi = 0; mi < 2; mi++) {
#pragma unroll
        for (int nj = 0; nj < 8; nj++) {
            float* p0 = C + (size_t)(gr + mi * 16) * V_ + gc + nj * 8;
            float* p1 = C + (size_t)(gr + mi * 16 + 8) * V_ + gc + nj * 8;
            *reinterpret_cast<float2*>(p0) = make_float2(acc[mi][nj][0], acc[mi][nj][1]);
            *reinterpret_cast<float2*>(p1) = make_float2(acc[mi][nj][2], acc[mi][nj][3]);
        }
    }
}

// ---------------- host orchestration ----------------
extern "C" void kernel_launch(void* const* d_in, const int* in_sizes, int n_in,
                              void* d_out, int out_size) {
    const int*   tokens  = (const int*)d_in[0];
    const unsigned char* enc_mask = (const unsigned char*)d_in[1];
    const float* enc_out = (const float*)d_in[2];
    const float* embed_w = (const float*)d_in[3];
    const float* g1Wx = (const float*)d_in[4];
    const float* g1Wh = (const float*)d_in[5];
    const float* g1bx = (const float*)d_in[6];
    const float* g1bh = (const float*)d_in[7];
    const float* g2Wx = (const float*)d_in[8];
    const float* g2Wh = (const float*)d_in[9];
    const float* g2bx = (const float*)d_in[10];
    const float* g2bh = (const float*)d_in[11];
    const float* brW  = (const float*)d_in[12];
    const float* brB  = (const float*)d_in[13];
    const float* Wk   = (const float*)d_in[14];
    const float* bk   = (const float*)d_in[15];
    const float* Wq   = (const float*)d_in[16];
    const float* bq   = (const float*)d_in[17];
    const float* Ww   = (const float*)d_in[18];
    const float* bw   = (const float*)d_in[19];
    const float* Wf   = (const float*)d_in[20];
    const float* bf   = (const float*)d_in[21];
    const float* Wo   = (const float*)d_in[22];
    const float* bo   = (const float*)d_in[23];
    float* out = (float*)d_out;

    float* S = nullptr;
    cudaGetSymbolAddress((void**)&S, g_scratch);
    float* feat   = S + OFF_FEAT;
    float* keyup  = S + OFF_KEYUP;
    float* logits = S + OFF_LOGITS;
    float* hbuf   = S + OFF_H;
    float* tmpb   = S + OFF_TMP;
    float* ctxv   = S + OFF_CTXV;
    float* part   = S + OFF_PART;
    float* W1cat  = S + OFF_W1;
    float* W2cat  = S + OFF_W2;
    float* WqT    = S + OFF_WQT;
    float* WfT    = S + OFF_WFT;
    __nv_bfloat16* Ahl = (__nv_bfloat16*)(S + OFF_AHL);
    __nv_bfloat16* Bhl = (__nv_bfloat16*)(S + OFF_BHL);

    // prep
    k_pack1<<<(1024 * 2048 + 255) / 256, 256>>>(g1Wx, g1Wh, W1cat);
    k_pack2<<<(1536 * 2048 + 255) / 256, 256>>>(g2Wx, g2Wh, W2cat);
    k_transpose<<<(512 * 512 + 255) / 256, 256>>>(Wq, WqT, 512, 512);
    k_transpose<<<(1024 * 1024 + 255) / 256, 256>>>(Wf, WfT, 1024, 1024);
    k_embed<<<B_ * T_, 128>>>(tokens, embed_w, feat);
    k_bridge<<<B_, 512>>>(enc_mask, enc_out, brW, brB, hbuf);
    k_convB<<<(32000 * 128 + 255) / 256, 256>>>(embed_w, Bhl);
    {   // key_up = enc @ Wk^T + bk
        dim3 g(512 / BN, 2048 / BM);
        sgemm_nt<<<g, 256>>>(enc_out, Wk, bk, keyup, 2048, 512, 1024, 2);
    }

    // persistent recurrence (one kernel for all 64 steps)
    k_zero<<<1, 1>>>();
    k_persistent<<<NB, 256>>>(W1cat, W2cat, WqT, WfT,
                              g1bx, g1bh, g2bx, g2bh,
                              bq, Ww, bw, bf,
                              enc_out, enc_mask, keyup,
                              feat, hbuf, tmpb, ctxv, part);

    {   // logits = tanh(feat @ Wo^T + bo)
        dim3 g(512 / BN, 2048 / BM);
        sgemm_nt<<<g, 256>>>(feat, Wo, bo, logits, 2048, 512, 2048, 1);
    }
    // out = logits @ embed_w^T via HMMA bf16 hi/lo K-extended GEMM
    k_convA<<<(2048 * 128 + 255) / 256, 256>>>(logits, Ahl);
    cudaFuncSetAttribute(mma_gemm_hmma, cudaFuncAttributeMaxDynamicSharedMemorySize, HG_SMEM_TOTAL);
    {
        dim3 g(V_ / 128, 2048 / 128);
        mma_gemm_hmma<<<g, 256, HG_SMEM_TOTAL>>>(Ahl, Bhl, out);
    }
}

// round 5
// speedup vs baseline: 1.9507x; 1.2611x over previous
#include <cuda_runtime.h>
#include <cuda_bf16.h>
#include <math.h>
#include <stdint.h>

// Problem dims
#define B_ 32
#define T_ 64
#define S_ 64
#define V_ 32000
#define E_ 512
#define H_ 512
#define U_ 1024
#define NH_ 8
#define D_ 64
#define DV_ 128
#define FEATW 2048
#define NB 148

// ---------------- scratch offsets (floats) ----------------
#define OFF_FEAT   0ull
#define OFF_KEYUP  4194304ull
#define OFF_LOGITS 5242880ull
#define OFF_HT     6291456ull     // [512][32]
#define OFF_TMP    6307840ull     // [32][512]
#define OFF_TMPT   6324224ull     // [512][32]
#define OFF_CTXRT  6340608ull     // [1024][32]
#define OFF_X1ALL  6373376ull     // [2048][1536]
#define OFF_WFX2   9519104ull     // [1536][1024]
#define OFF_BFX2   11091968ull    // [1536]
#define OFF_WQT    11094016ull    // [512][512]
#define OFF_WFT    11356160ull    // [1024][1024]
#define OFF_AHL    12404736ull    // [2048,1536] bf16
#define OFF_BHL    13977600ull    // [32000,1536] bf16
#define SCRATCH_FLOATS 38553600ull

__device__ float g_scratch[SCRATCH_FLOATS];
__device__ unsigned g_bar_ctr;

// ======================= helpers =======================
__device__ __forceinline__ uint32_t smem_to_u32(const void* p) {
    uint32_t a;
    asm("{ .reg .u64 t; cvta.to.shared.u64 t, %1; cvt.u32.u64 %0, t; }" : "=r"(a) : "l"(p));
    return a;
}
__device__ __forceinline__ void cp_async16(uint32_t dst, const void* src) {
    asm volatile("cp.async.cg.shared.global [%0], [%1], 16;" :: "r"(dst), "l"(src));
}
#define CP_COMMIT() asm volatile("cp.async.commit_group;" ::: "memory")
#define CP_WAIT(n)  asm volatile("cp.async.wait_group %0;" :: "n"(n) : "memory")
#define SW128(x) ((x) ^ (((x) >> 3) & 0x70))

__device__ __forceinline__ void ldsm_x4(uint32_t& r0, uint32_t& r1, uint32_t& r2, uint32_t& r3,
                                        uint32_t addr) {
    asm volatile("ldmatrix.sync.aligned.m8n8.x4.shared.b16 {%0,%1,%2,%3}, [%4];"
                 : "=r"(r0), "=r"(r1), "=r"(r2), "=r"(r3) : "r"(addr));
}
__device__ __forceinline__ void mma16816(float& c0, float& c1, float& c2, float& c3,
                                         uint32_t a0, uint32_t a1, uint32_t a2, uint32_t a3,
                                         uint32_t b0, uint32_t b1) {
    asm volatile("mma.sync.aligned.m16n8k16.row.col.f32.bf16.bf16.f32 "
                 "{%0,%1,%2,%3}, {%4,%5,%6,%7}, {%8,%9}, {%0,%1,%2,%3};"
                 : "+f"(c0), "+f"(c1), "+f"(c2), "+f"(c3)
                 : "r"(a0), "r"(a1), "r"(a2), "r"(a3), "r"(b0), "r"(b1));
}

__device__ __forceinline__ void gsync(unsigned& gen) {
    __syncthreads();
    if (threadIdx.x == 0) {
        __threadfence();
        atomicAdd(&g_bar_ctr, 1u);
        unsigned target = (gen + 1u) * (unsigned)NB;
        unsigned v;
        do {
            asm volatile("ld.acquire.gpu.u32 %0, [%1];" : "=r"(v) : "l"(&g_bar_ctr) : "memory");
        } while (v < target);
    }
    gen++;
    __syncthreads();
}
__global__ void k_zero() { g_bar_ctr = 0u; }

// ---------------- prep kernels ----------------
__global__ void k_embed(const int* __restrict__ tokens, const float* __restrict__ embed_w,
                        float* __restrict__ feat) {
    int bt = blockIdx.x;
    int tok = tokens[bt];
    const float4* src = reinterpret_cast<const float4*>(embed_w + (size_t)tok * E_);
    float4* dst = reinterpret_cast<float4*>(feat + (size_t)bt * FEATW);
    dst[threadIdx.x] = src[threadIdx.x];
}

// bridge -> h0 transposed: hT[j*32+b]
__global__ __launch_bounds__(512) void k_bridge(const unsigned char* __restrict__ mask,
                                                const float* __restrict__ enc_out,
                                                const float* __restrict__ Wb,
                                                const float* __restrict__ bb,
                                                float* __restrict__ hT) {
    int b = blockIdx.x;
    int j = threadIdx.x;
    __shared__ float fn[512];
    __shared__ int sL;
    if (j == 0) {
        int L = S_;
        for (int s = 0; s < S_; s++) if (mask[b * S_ + s]) L--;
        sL = L;
    }
    __syncthreads();
    int L = sL;
    fn[j] = enc_out[((size_t)(L - 1) * B_ + b) * U_ + j];
    __syncthreads();
    float acc = bb[j];
    const float* wr = Wb + (size_t)j * 512;
    for (int k = 0; k < 512; k++) acc += fn[k] * wr[k];
    hT[j * 32 + b] = tanhf(acc);
}

__global__ void k_transpose(const float* __restrict__ W, float* __restrict__ WT, int R, int C) {
    int idx = blockIdx.x * 256 + threadIdx.x;
    if (idx >= R * C) return;
    int n = idx / C, k = idx % C;
    WT[(size_t)k * R + n] = W[idx];
}

// bfx2[g] = g2bx[g] + dot(bf, g2Wx[g,:])
__global__ void k_bfx2(const float* __restrict__ g2Wx, const float* __restrict__ bf,
                       const float* __restrict__ g2bx, float* __restrict__ bfx2) {
    int g = blockIdx.x * 256 + threadIdx.x;
    if (g >= 1536) return;
    float a = g2bx[g];
    const float4* w4 = reinterpret_cast<const float4*>(g2Wx + (size_t)g * 1024);
    const float4* b4 = reinterpret_cast<const float4*>(bf);
    for (int k = 0; k < 256; k++) {
        float4 w = w4[k], b = b4[k];
        a += w.x * b.x + w.y * b.y + w.z * b.z + w.w * b.w;
    }
    bfx2[g] = a;
}

// ---------------- tiled SGEMM-NT with lda: C[M,N] = A[M,K](lda) @ B[N,K]^T ----------------
#define BM 128
#define BN 128
#define BKk 16
__global__ __launch_bounds__(256) void sgemm_nt(const float* __restrict__ A,
                                                const float* __restrict__ Bm,
                                                const float* __restrict__ bias,
                                                float* __restrict__ C,
                                                int M, int N, int K, int lda, int mode) {
    __shared__ float As[BKk][BM];
    __shared__ float Bs[BKk][BN];
    const int bm = blockIdx.y * BM, bn = blockIdx.x * BN;
    const int tid = threadIdx.x;
    const int tm = (tid >> 4) << 3;
    const int tn = (tid & 15) << 3;
    float acc[8][8];
#pragma unroll
    for (int i = 0; i < 8; i++)
#pragma unroll
        for (int j = 0; j < 8; j++) acc[i][j] = 0.f;

    for (int k0 = 0; k0 < K; k0 += BKk) {
#pragma unroll
        for (int i = 0; i < 2; i++) {
            int idx = tid + i * 256;
            int r = idx >> 2, c = (idx & 3) << 2;
            float4 v = *reinterpret_cast<const float4*>(A + (size_t)(bm + r) * lda + k0 + c);
            As[c][r] = v.x; As[c + 1][r] = v.y; As[c + 2][r] = v.z; As[c + 3][r] = v.w;
            float4 w = *reinterpret_cast<const float4*>(Bm + (size_t)(bn + r) * K + k0 + c);
            Bs[c][r] = w.x; Bs[c + 1][r] = w.y; Bs[c + 2][r] = w.z; Bs[c + 3][r] = w.w;
        }
        __syncthreads();
#pragma unroll
        for (int k = 0; k < BKk; k++) {
            float a[8], bb[8];
            *reinterpret_cast<float4*>(&a[0]) = *reinterpret_cast<const float4*>(&As[k][tm]);
            *reinterpret_cast<float4*>(&a[4]) = *reinterpret_cast<const float4*>(&As[k][tm + 4]);
            *reinterpret_cast<float4*>(&bb[0]) = *reinterpret_cast<const float4*>(&Bs[k][tn]);
            *reinterpret_cast<float4*>(&bb[4]) = *reinterpret_cast<const float4*>(&Bs[k][tn + 4]);
#pragma unroll
            for (int i = 0; i < 8; i++)
#pragma unroll
                for (int j = 0; j < 8; j++) acc[i][j] += a[i] * bb[j];
        }
        __syncthreads();
    }
#pragma unroll
    for (int i = 0; i < 8; i++) {
        int m = bm + tm + i;
#pragma unroll
        for (int j = 0; j < 8; j++) {
            int n = bn + tn + j;
            float v = acc[i][j];
            if (bias) v += bias[n];
            if (mode == 1) v = tanhf(v);
            if (mode == 2) {
                int s_ = m >> 5, b_ = m & 31, nh_ = n >> 6, d_ = n & 63;
                C[(((size_t)(b_ * 8 + nh_) * 64) + s_) * 64 + d_] = v;
            } else {
                C[(size_t)m * N + n] = v;
            }
        }
    }
}

// ---------------- persistent recurrence kernel ----------------
__global__ __launch_bounds__(512, 1)
void k_persistent(const float* __restrict__ X1all, const float* __restrict__ g1Wh,
                  const float* __restrict__ g1bh,
                  const float* __restrict__ Wfx2, const float* __restrict__ bfx2,
                  const float* __restrict__ g2Wh, const float* __restrict__ g2bh,
                  const float* __restrict__ Wf, const float* __restrict__ bf,
                  const float* __restrict__ WqT, const float* __restrict__ bq,
                  const float* __restrict__ Ww, const float* __restrict__ bw,
                  const float* __restrict__ enc_out, const unsigned char* __restrict__ mask,
                  const float* __restrict__ keyup,
                  float* __restrict__ feat, float* __restrict__ hT,
                  float* __restrict__ tmp, float* __restrict__ tmpT,
                  float* __restrict__ ctxrawT) {
    extern __shared__ float sm[];
    const int bid = blockIdx.x, tid = threadIdx.x;
    unsigned gen = 0;

    for (int t = 0; t < T_; t++) {
        // ============ P1: GRU1 fused (h-gates + combine) ============
        for (int v = bid; v < 64; v += NB) {
            // stage hT (16384 floats) + 8j x 3 rows of g1Wh (12288 floats)
            float4* xs4 = reinterpret_cast<float4*>(sm);
            const float4* h4 = reinterpret_cast<const float4*>(hT);
            for (int i = tid; i < 4096; i += 512) xs4[i] = h4[i];
            int j0 = v * 8;
            float4* ws4 = reinterpret_cast<float4*>(sm + 16384);
            for (int i = tid; i < 3072; i += 512) {
                int jl = i / 384, rem = i % 384, g = rem >> 7, k4 = rem & 127;
                ws4[i] = *reinterpret_cast<const float4*>(
                    g1Wh + ((size_t)(g * 512 + j0 + jl)) * 512 + k4 * 4);
            }
            __syncthreads();
            int b = tid & 31, jl = (tid >> 5) & 7, half = tid >> 8;
            float ar = 0.f, az = 0.f, an = 0.f;
            const float4* wr4 = reinterpret_cast<const float4*>(sm + 16384 + (jl * 3 + 0) * 512) + half * 64;
            const float4* wz4 = reinterpret_cast<const float4*>(sm + 16384 + (jl * 3 + 1) * 512) + half * 64;
            const float4* wn4 = reinterpret_cast<const float4*>(sm + 16384 + (jl * 3 + 2) * 512) + half * 64;
            const float* xsl = sm + half * 256 * 32 + b;
#pragma unroll 4
            for (int kk = 0; kk < 64; kk++) {
                float4 wr = wr4[kk], wz = wz4[kk], wn = wn4[kk];
                float x0 = xsl[(kk * 4 + 0) * 32];
                float x1 = xsl[(kk * 4 + 1) * 32];
                float x2 = xsl[(kk * 4 + 2) * 32];
                float x3 = xsl[(kk * 4 + 3) * 32];
                ar += x0 * wr.x + x1 * wr.y + x2 * wr.z + x3 * wr.w;
                az += x0 * wz.x + x1 * wz.y + x2 * wz.z + x3 * wz.w;
                an += x0 * wn.x + x1 * wn.y + x2 * wn.z + x3 * wn.w;
            }
            float* ps = sm + 28672;
            if (half) {
                int o = (jl * 32 + b) * 3;
                ps[o] = ar; ps[o + 1] = az; ps[o + 2] = an;
            }
            __syncthreads();
            if (!half) {
                int o = (jl * 32 + b) * 3;
                ar += ps[o]; az += ps[o + 1]; an += ps[o + 2];
                int j = j0 + jl, m = b * T_ + t;
                const float* X1 = X1all + (size_t)m * 1536;
                float r = 1.f / (1.f + expf(-(X1[j] + g1bh[j] + ar)));
                float z = 1.f / (1.f + expf(-(X1[512 + j] + g1bh[512 + j] + az)));
                float n = tanhf(X1[1024 + j] + r * (an + g1bh[1024 + j]));
                float hp = sm[j * 32 + b];
                float o2 = (1.f - z) * n + z * hp;
                tmp[b * 512 + j] = o2;
                tmpT[j * 32 + b] = o2;
            }
            __syncthreads();
        }
        gsync(gen);

        // ============ P2: attention (2 (b,nh) pairs per block) ============
        for (int v = bid; v < 128; v += NB) {
            int pr = tid >> 8, tid2 = tid & 255;
            int p = v * 2 + pr, b = p >> 3, nh = p & 7;
            float* st  = sm + pr * 512;
            float* sq  = sm + 1024 + pr * 64;
            float* sa  = sm + 1152 + pr * 64;
            float* qp  = sm + 1280 + pr * 256;
            float* scp = sm + 1792 + pr * 128;
            for (int i = tid2; i < 512; i += 256) st[i] = tmp[b * 512 + i];
            __syncthreads();
            {
                int d = tid2 & 63, kq = tid2 >> 6;
                float a = 0.f;
                const float* wp = WqT + nh * 64 + d;
                int k0 = kq * 128;
                for (int k = k0; k < k0 + 128; k++) a += st[k] * wp[(size_t)k * 512];
                qp[kq * 64 + d] = a;
            }
            __syncthreads();
            if (tid2 < 64)
                sq[tid2] = bq[nh * 64 + tid2] + qp[tid2] + qp[64 + tid2] + qp[128 + tid2] + qp[192 + tid2];
            __syncthreads();
            if (tid2 < 128) {
                int s = tid2 & 63, dh = tid2 >> 6;
                float a = 0.f;
                const float* kp = keyup + (((size_t)(b * 8 + nh)) * 64 + s) * 64 + dh * 32;
                const float* sqh = sq + dh * 32;
                const float* wwh = Ww + dh * 32;
#pragma unroll 8
                for (int d = 0; d < 32; d++) a += tanhf(sqh[d] + kp[d]) * wwh[d];
                scp[dh * 64 + s] = a;
            }
            __syncthreads();
            if (tid2 < 64) {
                float sc = scp[tid2] + scp[64 + tid2] + bw[0];
                if (mask[b * S_ + tid2]) sc -= 1e9f;
                sa[tid2] = sc;
            }
            __syncthreads();
            if (tid2 == 0) {
                float mx = -1e30f;
                for (int s = 0; s < 64; s++) mx = fmaxf(mx, sa[s]);
                float sum = 0.f;
                for (int s = 0; s < 64; s++) { float e = expf(sa[s] - mx); sa[s] = e; sum += e; }
                float inv = 1.f / sum;
                for (int s = 0; s < 64; s++) sa[s] *= inv;
            }
            __syncthreads();
            if (tid2 < 128) {
                float a = 0.f;
                const float* vp = enc_out + (size_t)b * U_ + nh * 128 + tid2;
#pragma unroll
                for (int s = 0; s < 64; s++) a += sa[s] * vp[(size_t)s * B_ * U_];
                ctxrawT[(nh * 128 + tid2) * 32 + b] = a;
            }
            __syncthreads();
        }
        gsync(gen);

        // ============ P3: GRU2 gates+combine (blocks 0..63) | ctx_final (blocks 64..127) ============
        for (int v = bid; v < 128; v += NB) {
            if (v < 64) {
                int j0 = v * 8;
                int b = tid & 31, jl = (tid >> 5) & 7, half = tid >> 8;
                float a_r = 0.f, a_z = 0.f, a_xn = 0.f, a_hn = 0.f;
                // x-part: 8 chunks of K=128 over ctxrawT with Wfx2
                for (int c = 0; c < 8; c++) {
                    float4* xs4 = reinterpret_cast<float4*>(sm);
                    const float4* src4 = reinterpret_cast<const float4*>(ctxrawT + c * 4096);
                    for (int i = tid; i < 1024; i += 512) xs4[i] = src4[i];
                    float4* ws4 = reinterpret_cast<float4*>(sm + 4096);
                    for (int i = tid; i < 768; i += 512) {
                        int jj = i / 96, rem = i % 96, g = rem >> 5, k4 = rem & 31;
                        ws4[i] = *reinterpret_cast<const float4*>(
                            Wfx2 + ((size_t)(g * 512 + j0 + jj)) * 1024 + c * 128 + k4 * 4);
                    }
                    __syncthreads();
                    const float4* wr4 = reinterpret_cast<const float4*>(sm + 4096 + (jl * 3 + 0) * 128) + half * 16;
                    const float4* wz4 = reinterpret_cast<const float4*>(sm + 4096 + (jl * 3 + 1) * 128) + half * 16;
                    const float4* wn4 = reinterpret_cast<const float4*>(sm + 4096 + (jl * 3 + 2) * 128) + half * 16;
                    const float* xsl = sm + half * 64 * 32 + b;
#pragma unroll 4
                    for (int kk = 0; kk < 16; kk++) {
                        float4 wr = wr4[kk], wz = wz4[kk], wn = wn4[kk];
                        float x0 = xsl[(kk * 4 + 0) * 32];
                        float x1 = xsl[(kk * 4 + 1) * 32];
                        float x2 = xsl[(kk * 4 + 2) * 32];
                        float x3 = xsl[(kk * 4 + 3) * 32];
                        a_r  += x0 * wr.x + x1 * wr.y + x2 * wr.z + x3 * wr.w;
                        a_z  += x0 * wz.x + x1 * wz.y + x2 * wz.z + x3 * wz.w;
                        a_xn += x0 * wn.x + x1 * wn.y + x2 * wn.z + x3 * wn.w;
                    }
                    __syncthreads();
                }
                // h-part: 4 chunks of K=128 over tmpT with g2Wh
                for (int c = 0; c < 4; c++) {
                    float4* xs4 = reinterpret_cast<float4*>(sm);
                    const float4* src4 = reinterpret_cast<const float4*>(tmpT + c * 4096);
                    for (int i = tid; i < 1024; i += 512) xs4[i] = src4[i];
                    float4* ws4 = reinterpret_cast<float4*>(sm + 4096);
                    for (int i = tid; i < 768; i += 512) {
                        int jj = i / 96, rem = i % 96, g = rem >> 5, k4 = rem & 31;
                        ws4[i] = *reinterpret_cast<const float4*>(
                            g2Wh + ((size_t)(g * 512 + j0 + jj)) * 512 + c * 128 + k4 * 4);
                    }
                    __syncthreads();
                    const float4* wr4 = reinterpret_cast<const float4*>(sm + 4096 + (jl * 3 + 0) * 128) + half * 16;
                    const float4* wz4 = reinterpret_cast<const float4*>(sm + 4096 + (jl * 3 + 1) * 128) + half * 16;
                    const float4* wn4 = reinterpret_cast<const float4*>(sm + 4096 + (jl * 3 + 2) * 128) + half * 16;
                    const float* xsl = sm + half * 64 * 32 + b;
#pragma unroll 4
                    for (int kk = 0; kk < 16; kk++) {
                        float4 wr = wr4[kk], wz = wz4[kk], wn = wn4[kk];
                        float x0 = xsl[(kk * 4 + 0) * 32];
                        float x1 = xsl[(kk * 4 + 1) * 32];
                        float x2 = xsl[(kk * 4 + 2) * 32];
                        float x3 = xsl[(kk * 4 + 3) * 32];
                        a_r  += x0 * wr.x + x1 * wr.y + x2 * wr.z + x3 * wr.w;
                        a_z  += x0 * wz.x + x1 * wz.y + x2 * wz.z + x3 * wz.w;
                        a_hn += x0 * wn.x + x1 * wn.y + x2 * wn.z + x3 * wn.w;
                    }
                    __syncthreads();
                }
                float* ps = sm + 7168;
                if (half) {
                    int o = (jl * 32 + b) * 4;
                    ps[o] = a_r; ps[o + 1] = a_z; ps[o + 2] = a_xn; ps[o + 3] = a_hn;
                }
                __syncthreads();
                if (!half) {
                    int o = (jl * 32 + b) * 4;
                    a_r += ps[o]; a_z += ps[o + 1]; a_xn += ps[o + 2]; a_hn += ps[o + 3];
                    int j = j0 + jl, m = b * T_ + t;
                    float r = 1.f / (1.f + expf(-(a_r + bfx2[j] + g2bh[j])));
                    float z = 1.f / (1.f + expf(-(a_z + bfx2[512 + j] + g2bh[512 + j])));
                    float n = tanhf(a_xn + bfx2[1024 + j] + r * (a_hn + g2bh[1024 + j]));
                    float hp = tmpT[j * 32 + b];
                    float o2 = (1.f - z) * n + z * hp;
                    hT[j * 32 + b] = o2;
                    feat[(size_t)m * FEATW + 512 + j] = o2;
                }
                __syncthreads();
            } else {
                // ctx_final: 16 n x 32 b per block, K=1024
                int v2 = v - 64, n0 = v2 * 16;
                int b = tid & 31, nl = tid >> 5;
                float a = 0.f;
                for (int c = 0; c < 8; c++) {
                    float4* xs4 = reinterpret_cast<float4*>(sm);
                    const float4* src4 = reinterpret_cast<const float4*>(ctxrawT + c * 4096);
                    for (int i = tid; i < 1024; i += 512) xs4[i] = src4[i];
                    float4* ws4 = reinterpret_cast<float4*>(sm + 4096);
                    {
                        int i = tid;
                        if (i < 512) {
                            int nn = i >> 5, k4 = i & 31;
                            ws4[i] = *reinterpret_cast<const float4*>(
                                Wf + ((size_t)(n0 + nn)) * 1024 + c * 128 + k4 * 4);
                        }
                    }
                    __syncthreads();
                    const float4* w4 = reinterpret_cast<const float4*>(sm + 4096 + nl * 128);
                    const float* xsl = sm + b;
#pragma unroll 4
                    for (int kk = 0; kk < 32; kk++) {
                        float4 w = w4[kk];
                        float x0 = xsl[(kk * 4 + 0) * 32];
                        float x1 = xsl[(kk * 4 + 1) * 32];
                        float x2 = xsl[(kk * 4 + 2) * 32];
                        float x3 = xsl[(kk * 4 + 3) * 32];
                        a += x0 * w.x + x1 * w.y + x2 * w.z + x3 * w.w;
                    }
                    __syncthreads();
                }
                int m = b * T_ + t;
                feat[(size_t)m * FEATW + 1024 + n0 + nl] = a + bf[n0 + nl];
            }
        }
        gsync(gen);
    }
}

// ============ bf16 hi/lo split conversion ============
__global__ void k_convA(const float* __restrict__ L, __nv_bfloat16* __restrict__ A) {
    int idx = blockIdx.x * 256 + threadIdx.x;
    if (idx >= 2048 * 128) return;
    int m = idx >> 7, kg = (idx & 127) << 2;
    float4 v = *reinterpret_cast<const float4*>(L + (size_t)m * 512 + kg);
    __nv_bfloat16 h[4], l[4];
    float x[4] = {v.x, v.y, v.z, v.w};
#pragma unroll
    for (int i = 0; i < 4; i++) {
        h[i] = __float2bfloat16(x[i]);
        l[i] = __float2bfloat16(x[i] - __bfloat162float(h[i]));
    }
    __nv_bfloat162* p0 = reinterpret_cast<__nv_bfloat162*>(A + (size_t)m * 1536 + kg);
    __nv_bfloat162* p1 = reinterpret_cast<__nv_bfloat162*>(A + (size_t)m * 1536 + 512 + kg);
    __nv_bfloat162* p2 = reinterpret_cast<__nv_bfloat162*>(A + (size_t)m * 1536 + 1024 + kg);
    p0[0] = __nv_bfloat162(h[0], h[1]); p0[1] = __nv_bfloat162(h[2], h[3]);
    p1[0] = __nv_bfloat162(h[0], h[1]); p1[1] = __nv_bfloat162(h[2], h[3]);
    p2[0] = __nv_bfloat162(l[0], l[1]); p2[1] = __nv_bfloat162(l[2], l[3]);
}
__global__ void k_convB(const float* __restrict__ W, __nv_bfloat16* __restrict__ Bp) {
    int idx = blockIdx.x * 256 + threadIdx.x;
    if (idx >= 32000 * 128) return;
    int n = idx >> 7, kg = (idx & 127) << 2;
    float4 v = *reinterpret_cast<const float4*>(W + (size_t)n * 512 + kg);
    __nv_bfloat16 h[4], l[4];
    float x[4] = {v.x, v.y, v.z, v.w};
#pragma unroll
    for (int i = 0; i < 4; i++) {
        h[i] = __float2bfloat16(x[i]);
        l[i] = __float2bfloat16(x[i] - __bfloat162float(h[i]));
    }
    __nv_bfloat162* p0 = reinterpret_cast<__nv_bfloat162*>(Bp + (size_t)n * 1536 + kg);
    __nv_bfloat162* p1 = reinterpret_cast<__nv_bfloat162*>(Bp + (size_t)n * 1536 + 512 + kg);
    __nv_bfloat162* p2 = reinterpret_cast<__nv_bfloat162*>(Bp + (size_t)n * 1536 + 1024 + kg);
    p0[0] = __nv_bfloat162(h[0], h[1]); p0[1] = __nv_bfloat162(h[2], h[3]);
    p1[0] = __nv_bfloat162(l[0], l[1]); p1[1] = __nv_bfloat162(l[2], l[3]);
    p2[0] = __nv_bfloat162(h[0], h[1]); p2[1] = __nv_bfloat162(h[2], h[3]);
}

// ============ HMMA bf16 GEMM: C[2048,32000] = A'[2048,1536] @ B'[32000,1536]^T ============
#define HG_A_BYTES 16384
#define HG_B_BYTES 16384
#define HG_SMEM_TOTAL (2 * (HG_A_BYTES + HG_B_BYTES))

__global__ __launch_bounds__(256, 2)
void mma_gemm_hmma(const __nv_bfloat16* __restrict__ Ap, const __nv_bfloat16* __restrict__ Bp,
                   float* __restrict__ C) {
    extern __shared__ char smemc[];
    uint32_t sb_a = smem_to_u32(smemc);
    uint32_t sb_b = sb_a + 2 * HG_A_BYTES;
    const int tid = threadIdx.x, lane = tid & 31, wid = tid >> 5;
    const int mt = blockIdx.y, nt = blockIdx.x;
    const int m0 = (wid & 3) * 32;
    const int n0 = (wid >> 2) * 64;

    const __nv_bfloat16* Ag = Ap + (size_t)mt * 128 * 1536;
    const __nv_bfloat16* Bg = Bp + (size_t)nt * 128 * 1536;

#define HLOAD(s, buf) { \
    uint32_t ab_ = sb_a + (buf) * HG_A_BYTES; \
    uint32_t bb_ = sb_b + (buf) * HG_B_BYTES; \
    const __nv_bfloat16* As_ = Ag + (s) * 64; \
    const __nv_bfloat16* Bs_ = Bg + (s) * 64; \
    _Pragma("unroll") \
    for (int i_ = 0; i_ < 4; i_++) { int ix_ = tid + i_ * 256; int r_ = ix_ >> 3, c_ = ix_ & 7; \
        cp_async16(ab_ + SW128(r_ * 128 + c_ * 16), As_ + (size_t)r_ * 1536 + c_ * 8); } \
    _Pragma("unroll") \
    for (int i_ = 0; i_ < 4; i_++) { int ix_ = tid + i_ * 256; int r_ = ix_ >> 3, c_ = ix_ & 7; \
        cp_async16(bb_ + SW128(r_ * 128 + c_ * 16), Bs_ + (size_t)r_ * 1536 + c_ * 8); } \
    CP_COMMIT(); }

    float acc[2][8][4];
#pragma unroll
    for (int i = 0; i < 2; i++)
#pragma unroll
        for (int j = 0; j < 8; j++)
#pragma unroll
            for (int v = 0; v < 4; v++) acc[i][j][v] = 0.f;

    HLOAD(0, 0);
    HLOAD(1, 1);

    const int a_row_off = ((lane >> 3) & 1) * 8 + (lane & 7);
    const int a_kb_off  = ((lane >> 4) & 1) * 16;
    const int b_row_off = ((lane >> 4) & 1) * 8 + (lane & 7);
    const int b_kb_off  = ((lane >> 3) & 1) * 16;

    for (int s = 0; s < 24; s++) {
        int buf = s & 1;
        CP_WAIT(1);
        __syncthreads();
        uint32_t abase = sb_a + buf * HG_A_BYTES;
        uint32_t bbase = sb_b + buf * HG_B_BYTES;
#pragma unroll
        for (int kk = 0; kk < 4; kk++) {
            uint32_t a[2][4];
#pragma unroll
            for (int mi = 0; mi < 2; mi++) {
                int row = m0 + mi * 16 + a_row_off;
                int kb = kk * 32 + a_kb_off;
                ldsm_x4(a[mi][0], a[mi][1], a[mi][2], a[mi][3], abase + SW128(row * 128 + kb));
            }
            uint32_t bfr[4][4];
#pragma unroll
            for (int ng = 0; ng < 4; ng++) {
                int row = n0 + ng * 16 + b_row_off;
                int kb = kk * 32 + b_kb_off;
                ldsm_x4(bfr[ng][0], bfr[ng][1], bfr[ng][2], bfr[ng][3], bbase + SW128(row * 128 + kb));
            }
#pragma unroll
            for (int mi = 0; mi < 2; mi++)
#pragma unroll
                for (int nj = 0; nj < 8; nj++) {
                    uint32_t b0 = bfr[nj >> 1][(nj & 1) * 2];
                    uint32_t b1 = bfr[nj >> 1][(nj & 1) * 2 + 1];
                    mma16816(acc[mi][nj][0], acc[mi][nj][1], acc[mi][nj][2], acc[mi][nj][3],
                             a[mi][0], a[mi][1], a[mi][2], a[mi][3], b0, b1);
                }
        }
        __syncthreads();
        if (s + 2 < 24) HLOAD(s + 2, buf);
    }

    int gr = mt * 128 + m0 + (lane >> 2);
    int gc = nt * 128 + n0 + (lane & 3) * 2;
#pragma unroll
    for (int mi = 0; mi < 2; mi++) {
#pragma unroll
        for (int nj = 0; nj < 8; nj++) {
            float* p0 = C + (size_t)(gr + mi * 16) * V_ + gc + nj * 8;
            float* p1 = C + (size_t)(gr + mi * 16 + 8) * V_ + gc + nj * 8;
            *reinterpret_cast<float2*>(p0) = make_float2(acc[mi][nj][0], acc[mi][nj][1]);
            *reinterpret_cast<float2*>(p1) = make_float2(acc[mi][nj][2], acc[mi][nj][3]);
        }
    }
}

// ---------------- host orchestration ----------------
#define PERS_SMEM (29440 * 4)

extern "C" void kernel_launch(void* const* d_in, const int* in_sizes, int n_in,
                              void* d_out, int out_size) {
    const int*   tokens  = (const int*)d_in[0];
    const unsigned char* enc_mask = (const unsigned char*)d_in[1];
    const float* enc_out = (const float*)d_in[2];
    const float* embed_w = (const float*)d_in[3];
    const float* g1Wx = (const float*)d_in[4];
    const float* g1Wh = (const float*)d_in[5];
    const float* g1bx = (const float*)d_in[6];
    const float* g1bh = (const float*)d_in[7];
    const float* g2Wx = (const float*)d_in[8];
    const float* g2Wh = (const float*)d_in[9];
    const float* g2bx = (const float*)d_in[10];
    const float* g2bh = (const float*)d_in[11];
    const float* brW  = (const float*)d_in[12];
    const float* brB  = (const float*)d_in[13];
    const float* Wk   = (const float*)d_in[14];
    const float* bk   = (const float*)d_in[15];
    const float* Wq   = (const float*)d_in[16];
    const float* bq   = (const float*)d_in[17];
    const float* Ww   = (const float*)d_in[18];
    const float* bw   = (const float*)d_in[19];
    const float* Wf   = (const float*)d_in[20];
    const float* bf   = (const float*)d_in[21];
    const float* Wo   = (const float*)d_in[22];
    const float* bo   = (const float*)d_in[23];
    float* out = (float*)d_out;

    float* S = nullptr;
    cudaGetSymbolAddress((void**)&S, g_scratch);
    float* feat    = S + OFF_FEAT;
    float* keyup   = S + OFF_KEYUP;
    float* logits  = S + OFF_LOGITS;
    float* hT      = S + OFF_HT;
    float* tmp     = S + OFF_TMP;
    float* tmpT    = S + OFF_TMPT;
    float* ctxrawT = S + OFF_CTXRT;
    float* X1all   = S + OFF_X1ALL;
    float* Wfx2    = S + OFF_WFX2;
    float* bfx2    = S + OFF_BFX2;
    float* WqT     = S + OFF_WQT;
    float* WfT     = S + OFF_WFT;
    __nv_bfloat16* Ahl = (__nv_bfloat16*)(S + OFF_AHL);
    __nv_bfloat16* Bhl = (__nv_bfloat16*)(S + OFF_BHL);

    // ---- prep ----
    k_embed<<<B_ * T_, 128>>>(tokens, embed_w, feat);
    k_bridge<<<B_, 512>>>(enc_mask, enc_out, brW, brB, hT);
    k_transpose<<<(512 * 512 + 255) / 256, 256>>>(Wq, WqT, 512, 512);
    k_transpose<<<(1024 * 1024 + 255) / 256, 256>>>(Wf, WfT, 1024, 1024);
    k_bfx2<<<6, 256>>>(g2Wx, bf, g2bx, bfx2);
    k_convB<<<(32000 * 128 + 255) / 256, 256>>>(embed_w, Bhl);
    {   // keyup = enc @ Wk^T + bk
        dim3 g(512 / BN, 2048 / BM);
        sgemm_nt<<<g, 256>>>(enc_out, Wk, bk, keyup, 2048, 512, 1024, 1024, 2);
    }
    {   // X1all = emb @ g1Wx^T + g1bx   (emb strided inside feat)
        dim3 g(1536 / BN, 2048 / BM);
        sgemm_nt<<<g, 256>>>(feat, g1Wx, g1bx, X1all, 2048, 1536, 512, 2048, 0);
    }
    {   // Wfx2 = g2Wx @ WfT^T  (i.e., Wfx2[g][m] = sum_n g2Wx[g][n] * Wf[n][m])
        dim3 g(1024 / BN, 1536 / BM);
        sgemm_nt<<<g, 256>>>(g2Wx, WfT, nullptr, Wfx2, 1536, 1024, 1024, 1024, 0);
    }

    // ---- persistent recurrence ----
    k_zero<<<1, 1>>>();
    cudaFuncSetAttribute(k_persistent, cudaFuncAttributeMaxDynamicSharedMemorySize, PERS_SMEM);
    k_persistent<<<NB, 512, PERS_SMEM>>>(X1all, g1Wh, g1bh, Wfx2, bfx2, g2Wh, g2bh,
                                         Wf, bf, WqT, bq, Ww, bw,
                                         enc_out, enc_mask, keyup,
                                         feat, hT, tmp, tmpT, ctxrawT);

    {   // logits = tanh(feat @ Wo^T + bo)
        dim3 g(512 / BN, 2048 / BM);
        sgemm_nt<<<g, 256>>>(feat, Wo, bo, logits, 2048, 512, 2048, 2048, 1);
    }
    // out = logits @ embed_w^T via HMMA bf16 hi/lo K-extended GEMM
    k_convA<<<(2048 * 128 + 255) / 256, 256>>>(logits, Ahl);
    cudaFuncSetAttribute(mma_gemm_hmma, cudaFuncAttributeMaxDynamicSharedMemorySize, HG_SMEM_TOTAL);
    {
        dim3 g(V_ / 128, 2048 / 128);
        mma_gemm_hmma<<<g, 256, HG_SMEM_TOTAL>>>(Ahl, Bhl, out);
    }
}

// round 6
// speedup vs baseline: 2.1816x; 1.1184x over previous
#include <cuda_runtime.h>
#include <cuda_bf16.h>
#include <math.h>
#include <stdint.h>

// Problem dims
#define B_ 32
#define T_ 64
#define S_ 64
#define V_ 32000
#define E_ 512
#define H_ 512
#define U_ 1024
#define NH_ 8
#define D_ 64
#define DV_ 128
#define FEATW 2048
#define NB 148

// ---------------- scratch offsets (floats) ----------------
#define OFF_FEAT   0ull
#define OFF_KEYUP  4194304ull
#define OFF_LOGITS 5242880ull
#define OFF_HT     6291456ull     // [512][32]
#define OFF_TMP    6307840ull     // [32][512]
#define OFF_TMPT   6324224ull     // [512][32]
#define OFF_CTXRT  6340608ull     // [1024][32]
#define OFF_X1ALL  6373376ull     // [2048][1536]
#define OFF_WFX2   9519104ull     // [1536][1024]
#define OFF_BFX2   11091968ull    // [1536] (pad 2048)
#define OFF_WQT    11094016ull    // [512][512]
#define OFF_WFT    11356160ull    // [1024][1024]
#define OFF_WO2F   12404736ull    // [512][1024]
#define OFF_WOPK   12929024ull    // [512][2048]
#define OFF_BO2    13977600ull    // [512] (pad 1024)
#define OFF_AHL    13978624ull    // [2048,1536] bf16
#define OFF_BHL    15551488ull    // [32000,1536] bf16
#define SCRATCH_FLOATS 40127488ull

__device__ float g_scratch[SCRATCH_FLOATS];
__device__ unsigned g_bar_ctr;

// ======================= helpers =======================
__device__ __forceinline__ uint32_t smem_to_u32(const void* p) {
    uint32_t a;
    asm("{ .reg .u64 t; cvta.to.shared.u64 t, %1; cvt.u32.u64 %0, t; }" : "=r"(a) : "l"(p));
    return a;
}
__device__ __forceinline__ void cp_async16(uint32_t dst, const void* src) {
    asm volatile("cp.async.cg.shared.global [%0], [%1], 16;" :: "r"(dst), "l"(src));
}
#define CP_COMMIT() asm volatile("cp.async.commit_group;" ::: "memory")
#define CP_WAIT(n)  asm volatile("cp.async.wait_group %0;" :: "n"(n) : "memory")
#define SW128(x) ((x) ^ (((x) >> 3) & 0x70))

__device__ __forceinline__ void ldsm_x4(uint32_t& r0, uint32_t& r1, uint32_t& r2, uint32_t& r3,
                                        uint32_t addr) {
    asm volatile("ldmatrix.sync.aligned.m8n8.x4.shared.b16 {%0,%1,%2,%3}, [%4];"
                 : "=r"(r0), "=r"(r1), "=r"(r2), "=r"(r3) : "r"(addr));
}
__device__ __forceinline__ void mma16816(float& c0, float& c1, float& c2, float& c3,
                                         uint32_t a0, uint32_t a1, uint32_t a2, uint32_t a3,
                                         uint32_t b0, uint32_t b1) {
    asm volatile("mma.sync.aligned.m16n8k16.row.col.f32.bf16.bf16.f32 "
                 "{%0,%1,%2,%3}, {%4,%5,%6,%7}, {%8,%9}, {%0,%1,%2,%3};"
                 : "+f"(c0), "+f"(c1), "+f"(c2), "+f"(c3)
                 : "r"(a0), "r"(a1), "r"(a2), "r"(a3), "r"(b0), "r"(b1));
}

__device__ __forceinline__ void gsync(unsigned& gen) {
    __syncthreads();
    if (threadIdx.x == 0) {
        __threadfence();
        atomicAdd(&g_bar_ctr, 1u);
        unsigned target = (gen + 1u) * (unsigned)NB;
        unsigned v;
        do {
            asm volatile("ld.acquire.gpu.u32 %0, [%1];" : "=r"(v) : "l"(&g_bar_ctr) : "memory");
        } while (v < target);
    }
    gen++;
    __syncthreads();
}
__global__ void k_zero() { g_bar_ctr = 0u; }

// ---------------- prep kernels ----------------
__global__ void k_embed(const int* __restrict__ tokens, const float* __restrict__ embed_w,
                        float* __restrict__ feat) {
    int bt = blockIdx.x;
    int tok = tokens[bt];
    const float4* src = reinterpret_cast<const float4*>(embed_w + (size_t)tok * E_);
    float4* dst = reinterpret_cast<float4*>(feat + (size_t)bt * FEATW);
    dst[threadIdx.x] = src[threadIdx.x];
}

__global__ __launch_bounds__(512) void k_bridge(const unsigned char* __restrict__ mask,
                                                const float* __restrict__ enc_out,
                                                const float* __restrict__ Wb,
                                                const float* __restrict__ bb,
                                                float* __restrict__ hT) {
    int b = blockIdx.x;
    int j = threadIdx.x;
    __shared__ float fn[512];
    __shared__ int sL;
    if (j == 0) {
        int L = S_;
        for (int s = 0; s < S_; s++) if (mask[b * S_ + s]) L--;
        sL = L;
    }
    __syncthreads();
    int L = sL;
    fn[j] = enc_out[((size_t)(L - 1) * B_ + b) * U_ + j];
    __syncthreads();
    float acc = bb[j];
    const float* wr = Wb + (size_t)j * 512;
    for (int k = 0; k < 512; k++) acc += fn[k] * wr[k];
    hT[j * 32 + b] = tanhf(acc);
}

__global__ void k_transpose(const float* __restrict__ W, float* __restrict__ WT, int R, int C) {
    int idx = blockIdx.x * 256 + threadIdx.x;
    if (idx >= R * C) return;
    int n = idx / C, k = idx % C;
    WT[(size_t)k * R + n] = W[idx];
}

__global__ void k_bfx2(const float* __restrict__ g2Wx, const float* __restrict__ bf,
                       const float* __restrict__ g2bx, float* __restrict__ bfx2) {
    int g = blockIdx.x * 256 + threadIdx.x;
    if (g >= 1536) return;
    float a = g2bx[g];
    const float4* w4 = reinterpret_cast<const float4*>(g2Wx + (size_t)g * 1024);
    const float4* b4 = reinterpret_cast<const float4*>(bf);
    for (int k = 0; k < 256; k++) {
        float4 w = w4[k], b = b4[k];
        a += w.x * b.x + w.y * b.y + w.z * b.z + w.w * b.w;
    }
    bfx2[g] = a;
}

__global__ void k_wopack(const float* __restrict__ Wo, const float* __restrict__ Wo2f,
                         float* __restrict__ Wp) {
    int idx = blockIdx.x * 256 + threadIdx.x;
    if (idx >= 512 * 2048) return;
    int e = idx >> 11, c = idx & 2047;
    Wp[idx] = (c < 1024) ? Wo[(size_t)e * 2048 + c] : Wo2f[(size_t)e * 1024 + (c - 1024)];
}
__global__ void k_bo2(const float* __restrict__ Wo, const float* __restrict__ bf,
                      const float* __restrict__ bo, float* __restrict__ bo2) {
    int e = blockIdx.x * 256 + threadIdx.x;
    if (e >= 512) return;
    float a = bo[e];
    const float* w = Wo + (size_t)e * 2048 + 1024;
    for (int m = 0; m < 1024; m++) a += w[m] * bf[m];
    bo2[e] = a;
}

// ---------------- tiled SGEMM-NT with lda ----------------
#define BM 128
#define BN 128
#define BKk 16
__global__ __launch_bounds__(256) void sgemm_nt(const float* __restrict__ A,
                                                const float* __restrict__ Bm,
                                                const float* __restrict__ bias,
                                                float* __restrict__ C,
                                                int M, int N, int K, int lda, int mode) {
    __shared__ float As[BKk][BM];
    __shared__ float Bs[BKk][BN];
    const int bm = blockIdx.y * BM, bn = blockIdx.x * BN;
    const int tid = threadIdx.x;
    const int tm = (tid >> 4) << 3;
    const int tn = (tid & 15) << 3;
    float acc[8][8];
#pragma unroll
    for (int i = 0; i < 8; i++)
#pragma unroll
        for (int j = 0; j < 8; j++) acc[i][j] = 0.f;

    for (int k0 = 0; k0 < K; k0 += BKk) {
#pragma unroll
        for (int i = 0; i < 2; i++) {
            int idx = tid + i * 256;
            int r = idx >> 2, c = (idx & 3) << 2;
            float4 v = *reinterpret_cast<const float4*>(A + (size_t)(bm + r) * lda + k0 + c);
            As[c][r] = v.x; As[c + 1][r] = v.y; As[c + 2][r] = v.z; As[c + 3][r] = v.w;
            float4 w = *reinterpret_cast<const float4*>(Bm + (size_t)(bn + r) * K + k0 + c);
            Bs[c][r] = w.x; Bs[c + 1][r] = w.y; Bs[c + 2][r] = w.z; Bs[c + 3][r] = w.w;
        }
        __syncthreads();
#pragma unroll
        for (int k = 0; k < BKk; k++) {
            float a[8], bb[8];
            *reinterpret_cast<float4*>(&a[0]) = *reinterpret_cast<const float4*>(&As[k][tm]);
            *reinterpret_cast<float4*>(&a[4]) = *reinterpret_cast<const float4*>(&As[k][tm + 4]);
            *reinterpret_cast<float4*>(&bb[0]) = *reinterpret_cast<const float4*>(&Bs[k][tn]);
            *reinterpret_cast<float4*>(&bb[4]) = *reinterpret_cast<const float4*>(&Bs[k][tn + 4]);
#pragma unroll
            for (int i = 0; i < 8; i++)
#pragma unroll
                for (int j = 0; j < 8; j++) acc[i][j] += a[i] * bb[j];
        }
        __syncthreads();
    }
#pragma unroll
    for (int i = 0; i < 8; i++) {
        int m = bm + tm + i;
#pragma unroll
        for (int j = 0; j < 8; j++) {
            int n = bn + tn + j;
            float v = acc[i][j];
            if (bias) v += bias[n];
            if (mode == 1) v = tanhf(v);
            if (mode == 2) {
                int s_ = m >> 5, b_ = m & 31, nh_ = n >> 6, d_ = n & 63;
                C[(((size_t)(b_ * 8 + nh_) * 64) + s_) * 64 + d_] = v;
            } else {
                C[(size_t)m * N + n] = v;
            }
        }
    }
}

// ---------------- persistent recurrence kernel ----------------
__global__ __launch_bounds__(512, 1)
void k_persistent(const float* __restrict__ X1all, const float* __restrict__ g1Wh,
                  const float* __restrict__ g1bh,
                  const float* __restrict__ Wfx2, const float* __restrict__ bfx2,
                  const float* __restrict__ g2Wh, const float* __restrict__ g2bh,
                  const float* __restrict__ WqT, const float* __restrict__ bq,
                  const float* __restrict__ Ww, const float* __restrict__ bw,
                  const float* __restrict__ enc_out, const unsigned char* __restrict__ mask,
                  const float* __restrict__ keyup,
                  float* __restrict__ feat, float* __restrict__ hT,
                  float* __restrict__ tmp, float* __restrict__ tmpT,
                  float* __restrict__ ctxrawT) {
    extern __shared__ float sm[];
    const int bid = blockIdx.x, tid = threadIdx.x;
    unsigned gen = 0;
    const int bl = tid & 15, jl = (tid >> 4) & 7, q = tid >> 7;

    for (int t = 0; t < T_; t++) {
        // ============ P1: GRU1 (128 vblocks: 64 j x 2 b-halves, 4-way K split) ============
        for (int v = bid; v < 128; v += NB) {
            int jb = v >> 1, bh = v & 1;
            int j0 = jb * 8, b0 = bh * 16;
            // stage hT half: [512 j][16 b] = 8192 floats
            {
                float4* dst4 = reinterpret_cast<float4*>(sm);
                const float4* src4 = reinterpret_cast<const float4*>(hT);
                for (int i = tid; i < 2048; i += 512) {
                    int j = i >> 2, qd = i & 3;
                    dst4[i] = src4[j * 8 + bh * 4 + qd];
                }
            }
            // stage weights: 8j x 3g x 512k = 12288 floats
            {
                float4* ws4 = reinterpret_cast<float4*>(sm + 8192);
                for (int i = tid; i < 3072; i += 512) {
                    int jj = i / 384, rem = i % 384, g = rem >> 7, k4 = rem & 127;
                    ws4[i] = *reinterpret_cast<const float4*>(
                        g1Wh + ((size_t)(g * 512 + j0 + jj)) * 512 + k4 * 4);
                }
            }
            __syncthreads();
            float ar = 0.f, az = 0.f, an = 0.f;
            const float4* wr4 = reinterpret_cast<const float4*>(sm + 8192 + (jl * 3 + 0) * 512) + q * 32;
            const float4* wz4 = reinterpret_cast<const float4*>(sm + 8192 + (jl * 3 + 1) * 512) + q * 32;
            const float4* wn4 = reinterpret_cast<const float4*>(sm + 8192 + (jl * 3 + 2) * 512) + q * 32;
            const float* xs = sm + q * 128 * 16 + bl;
#pragma unroll 4
            for (int kk = 0; kk < 32; kk++) {
                float4 wr = wr4[kk], wz = wz4[kk], wn = wn4[kk];
                float x0 = xs[(kk * 4 + 0) * 16];
                float x1 = xs[(kk * 4 + 1) * 16];
                float x2 = xs[(kk * 4 + 2) * 16];
                float x3 = xs[(kk * 4 + 3) * 16];
                ar += x0 * wr.x + x1 * wr.y + x2 * wr.z + x3 * wr.w;
                az += x0 * wz.x + x1 * wz.y + x2 * wz.z + x3 * wz.w;
                an += x0 * wn.x + x1 * wn.y + x2 * wn.z + x3 * wn.w;
            }
            float* ps = sm + 20480;
            if (q) {
                int o = (q - 1) * 384 + (jl * 16 + bl) * 3;
                ps[o] = ar; ps[o + 1] = az; ps[o + 2] = an;
            }
            __syncthreads();
            if (q == 0) {
                int o = (jl * 16 + bl) * 3;
                ar += ps[o] + ps[384 + o] + ps[768 + o];
                az += ps[o + 1] + ps[384 + o + 1] + ps[768 + o + 1];
                an += ps[o + 2] + ps[384 + o + 2] + ps[768 + o + 2];
                int j = j0 + jl, b = b0 + bl, m = b * T_ + t;
                const float* X1 = X1all + (size_t)m * 1536;
                float r = 1.f / (1.f + expf(-(X1[j] + g1bh[j] + ar)));
                float z = 1.f / (1.f + expf(-(X1[512 + j] + g1bh[512 + j] + az)));
                float n = tanhf(X1[1024 + j] + r * (an + g1bh[1024 + j]));
                float hp = sm[j * 16 + bl];
                float o2 = (1.f - z) * n + z * hp;
                tmp[b * 512 + j] = o2;
                tmpT[j * 32 + b] = o2;
            }
            __syncthreads();
        }
        gsync(gen);

        // ============ P2: attention (2 (b,nh) pairs per block) ============
        for (int v = bid; v < 128; v += NB) {
            int pr = tid >> 8, tid2 = tid & 255;
            int p = v * 2 + pr, b = p >> 3, nh = p & 7;
            float* st  = sm + pr * 512;
            float* sq  = sm + 1024 + pr * 64;
            float* sa  = sm + 1152 + pr * 64;
            float* qp  = sm + 1280 + pr * 256;
            float* scp = sm + 1792 + pr * 128;
            for (int i = tid2; i < 512; i += 256) st[i] = tmp[b * 512 + i];
            __syncthreads();
            {
                int d = tid2 & 63, kq = tid2 >> 6;
                float a = 0.f;
                const float* wp = WqT + nh * 64 + d;
                int k0 = kq * 128;
                for (int k = k0; k < k0 + 128; k++) a += st[k] * wp[(size_t)k * 512];
                qp[kq * 64 + d] = a;
            }
            __syncthreads();
            if (tid2 < 64)
                sq[tid2] = bq[nh * 64 + tid2] + qp[tid2] + qp[64 + tid2] + qp[128 + tid2] + qp[192 + tid2];
            __syncthreads();
            if (tid2 < 128) {
                int s = tid2 & 63, dh = tid2 >> 6;
                float a = 0.f;
                const float* kp = keyup + (((size_t)(b * 8 + nh)) * 64 + s) * 64 + dh * 32;
                const float* sqh = sq + dh * 32;
                const float* wwh = Ww + dh * 32;
#pragma unroll 8
                for (int d = 0; d < 32; d++) a += tanhf(sqh[d] + kp[d]) * wwh[d];
                scp[dh * 64 + s] = a;
            }
            __syncthreads();
            if (tid2 < 64) {
                float sc = scp[tid2] + scp[64 + tid2] + bw[0];
                if (mask[b * S_ + tid2]) sc -= 1e9f;
                sa[tid2] = sc;
            }
            __syncthreads();
            if (tid2 == 0) {
                float mx = -1e30f;
                for (int s = 0; s < 64; s++) mx = fmaxf(mx, sa[s]);
                float sum = 0.f;
                for (int s = 0; s < 64; s++) { float e = expf(sa[s] - mx); sa[s] = e; sum += e; }
                float inv = 1.f / sum;
                for (int s = 0; s < 64; s++) sa[s] *= inv;
            }
            __syncthreads();
            if (tid2 < 128) {
                float a = 0.f;
                const float* vp = enc_out + (size_t)b * U_ + nh * 128 + tid2;
#pragma unroll
                for (int s = 0; s < 64; s++) a += sa[s] * vp[(size_t)s * B_ * U_];
                ctxrawT[(nh * 128 + tid2) * 32 + b] = a;
                feat[((size_t)b * T_ + t) * FEATW + 1024 + nh * 128 + tid2] = a;
            }
            __syncthreads();
        }
        gsync(gen);

        // ============ P3: GRU2 (128 vblocks: 64 j x 2 b-halves, 4-way K split, chunked) ============
        for (int v = bid; v < 128; v += NB) {
            int jb = v >> 1, bh = v & 1;
            int j0 = jb * 8, b0 = bh * 16;
            float a_r = 0.f, a_z = 0.f, a_xn = 0.f, a_hn = 0.f;
            // x-part: 8 chunks of 128k over ctxrawT with Wfx2
            for (int c = 0; c < 8; c++) {
                {
                    float4* dx = reinterpret_cast<float4*>(sm);
                    const float4* sx = reinterpret_cast<const float4*>(ctxrawT);
                    int k = tid >> 2, qd = tid & 3;
                    dx[tid] = sx[(c * 128 + k) * 8 + bh * 4 + qd];
                    float4* dw = reinterpret_cast<float4*>(sm + 2048);
                    for (int i = tid; i < 768; i += 512) {
                        int jj = i / 96, rem = i % 96, g = rem >> 5, k4 = rem & 31;
                        dw[i] = *reinterpret_cast<const float4*>(
                            Wfx2 + ((size_t)(g * 512 + j0 + jj)) * 1024 + c * 128 + k4 * 4);
                    }
                }
                __syncthreads();
                const float4* wr4 = reinterpret_cast<const float4*>(sm + 2048 + (jl * 3 + 0) * 128) + q * 8;
                const float4* wz4 = reinterpret_cast<const float4*>(sm + 2048 + (jl * 3 + 1) * 128) + q * 8;
                const float4* wn4 = reinterpret_cast<const float4*>(sm + 2048 + (jl * 3 + 2) * 128) + q * 8;
                const float* xs = sm + q * 32 * 16 + bl;
#pragma unroll
                for (int kk = 0; kk < 8; kk++) {
                    float4 wr = wr4[kk], wz = wz4[kk], wn = wn4[kk];
                    float x0 = xs[(kk * 4 + 0) * 16];
                    float x1 = xs[(kk * 4 + 1) * 16];
                    float x2 = xs[(kk * 4 + 2) * 16];
                    float x3 = xs[(kk * 4 + 3) * 16];
                    a_r  += x0 * wr.x + x1 * wr.y + x2 * wr.z + x3 * wr.w;
                    a_z  += x0 * wz.x + x1 * wz.y + x2 * wz.z + x3 * wz.w;
                    a_xn += x0 * wn.x + x1 * wn.y + x2 * wn.z + x3 * wn.w;
                }
                __syncthreads();
            }
            // h-part: 4 chunks of 128k over tmpT with g2Wh
            for (int c = 0; c < 4; c++) {
                {
                    float4* dx = reinterpret_cast<float4*>(sm);
                    const float4* sx = reinterpret_cast<const float4*>(tmpT);
                    int k = tid >> 2, qd = tid & 3;
                    dx[tid] = sx[(c * 128 + k) * 8 + bh * 4 + qd];
                    float4* dw = reinterpret_cast<float4*>(sm + 2048);
                    for (int i = tid; i < 768; i += 512) {
                        int jj = i / 96, rem = i % 96, g = rem >> 5, k4 = rem & 31;
                        dw[i] = *reinterpret_cast<const float4*>(
                            g2Wh + ((size_t)(g * 512 + j0 + jj)) * 512 + c * 128 + k4 * 4);
                    }
                }
                __syncthreads();
                const float4* wr4 = reinterpret_cast<const float4*>(sm + 2048 + (jl * 3 + 0) * 128) + q * 8;
                const float4* wz4 = reinterpret_cast<const float4*>(sm + 2048 + (jl * 3 + 1) * 128) + q * 8;
                const float4* wn4 = reinterpret_cast<const float4*>(sm + 2048 + (jl * 3 + 2) * 128) + q * 8;
                const float* xs = sm + q * 32 * 16 + bl;
#pragma unroll
                for (int kk = 0; kk < 8; kk++) {
                    float4 wr = wr4[kk], wz = wz4[kk], wn = wn4[kk];
                    float x0 = xs[(kk * 4 + 0) * 16];
                    float x1 = xs[(kk * 4 + 1) * 16];
                    float x2 = xs[(kk * 4 + 2) * 16];
                    float x3 = xs[(kk * 4 + 3) * 16];
                    a_r  += x0 * wr.x + x1 * wr.y + x2 * wr.z + x3 * wr.w;
                    a_z  += x0 * wz.x + x1 * wz.y + x2 * wz.z + x3 * wz.w;
                    a_hn += x0 * wn.x + x1 * wn.y + x2 * wn.z + x3 * wn.w;
                }
                __syncthreads();
            }
            float* ps = sm + 5120;
            if (q) {
                int o = (q - 1) * 512 + (jl * 16 + bl) * 4;
                ps[o] = a_r; ps[o + 1] = a_z; ps[o + 2] = a_xn; ps[o + 3] = a_hn;
            }
            __syncthreads();
            if (q == 0) {
                int o = (jl * 16 + bl) * 4;
                a_r  += ps[o] + ps[512 + o] + ps[1024 + o];
                a_z  += ps[o + 1] + ps[512 + o + 1] + ps[1024 + o + 1];
                a_xn += ps[o + 2] + ps[512 + o + 2] + ps[1024 + o + 2];
                a_hn += ps[o + 3] + ps[512 + o + 3] + ps[1024 + o + 3];
                int j = j0 + jl, b = b0 + bl, m = b * T_ + t;
                float r = 1.f / (1.f + expf(-(a_r + bfx2[j] + g2bh[j])));
                float z = 1.f / (1.f + expf(-(a_z + bfx2[512 + j] + g2bh[512 + j])));
                float n = tanhf(a_xn + bfx2[1024 + j] + r * (a_hn + g2bh[1024 + j]));
                float hp = tmpT[j * 32 + b];
                float o2 = (1.f - z) * n + z * hp;
                hT[j * 32 + b] = o2;
                feat[(size_t)m * FEATW + 512 + j] = o2;
            }
            __syncthreads();
        }
        gsync(gen);
    }
}

// ============ bf16 hi/lo split conversion ============
__global__ void k_convA(const float* __restrict__ L, __nv_bfloat16* __restrict__ A) {
    int idx = blockIdx.x * 256 + threadIdx.x;
    if (idx >= 2048 * 128) return;
    int m = idx >> 7, kg = (idx & 127) << 2;
    float4 v = *reinterpret_cast<const float4*>(L + (size_t)m * 512 + kg);
    __nv_bfloat16 h[4], l[4];
    float x[4] = {v.x, v.y, v.z, v.w};
#pragma unroll
    for (int i = 0; i < 4; i++) {
        h[i] = __float2bfloat16(x[i]);
        l[i] = __float2bfloat16(x[i] - __bfloat162float(h[i]));
    }
    __nv_bfloat162* p0 = reinterpret_cast<__nv_bfloat162*>(A + (size_t)m * 1536 + kg);
    __nv_bfloat162* p1 = reinterpret_cast<__nv_bfloat162*>(A + (size_t)m * 1536 + 512 + kg);
    __nv_bfloat162* p2 = reinterpret_cast<__nv_bfloat162*>(A + (size_t)m * 1536 + 1024 + kg);
    p0[0] = __nv_bfloat162(h[0], h[1]); p0[1] = __nv_bfloat162(h[2], h[3]);
    p1[0] = __nv_bfloat162(h[0], h[1]); p1[1] = __nv_bfloat162(h[2], h[3]);
    p2[0] = __nv_bfloat162(l[0], l[1]); p2[1] = __nv_bfloat162(l[2], l[3]);
}
__global__ void k_convB(const float* __restrict__ W, __nv_bfloat16* __restrict__ Bp) {
    int idx = blockIdx.x * 256 + threadIdx.x;
    if (idx >= 32000 * 128) return;
    int n = idx >> 7, kg = (idx & 127) << 2;
    float4 v = *reinterpret_cast<const float4*>(W + (size_t)n * 512 + kg);
    __nv_bfloat16 h[4], l[4];
    float x[4] = {v.x, v.y, v.z, v.w};
#pragma unroll
    for (int i = 0; i < 4; i++) {
        h[i] = __float2bfloat16(x[i]);
        l[i] = __float2bfloat16(x[i] - __bfloat162float(h[i]));
    }
    __nv_bfloat162* p0 = reinterpret_cast<__nv_bfloat162*>(Bp + (size_t)n * 1536 + kg);
    __nv_bfloat162* p1 = reinterpret_cast<__nv_bfloat162*>(Bp + (size_t)n * 1536 + 512 + kg);
    __nv_bfloat162* p2 = reinterpret_cast<__nv_bfloat162*>(Bp + (size_t)n * 1536 + 1024 + kg);
    p0[0] = __nv_bfloat162(h[0], h[1]); p0[1] = __nv_bfloat162(h[2], h[3]);
    p1[0] = __nv_bfloat162(l[0], l[1]); p1[1] = __nv_bfloat162(l[2], l[3]);
    p2[0] = __nv_bfloat162(h[0], h[1]); p2[1] = __nv_bfloat162(h[2], h[3]);
}

// ============ HMMA bf16 GEMM ============
#define HG_A_BYTES 16384
#define HG_B_BYTES 16384
#define HG_SMEM_TOTAL (2 * (HG_A_BYTES + HG_B_BYTES))

__global__ __launch_bounds__(256, 2)
void mma_gemm_hmma(const __nv_bfloat16* __restrict__ Ap, const __nv_bfloat16* __restrict__ Bp,
                   float* __restrict__ C) {
    extern __shared__ char smemc[];
    uint32_t sb_a = smem_to_u32(smemc);
    uint32_t sb_b = sb_a + 2 * HG_A_BYTES;
    const int tid = threadIdx.x, lane = tid & 31, wid = tid >> 5;
    const int mt = blockIdx.y, nt = blockIdx.x;
    const int m0 = (wid & 3) * 32;
    const int n0 = (wid >> 2) * 64;

    const __nv_bfloat16* Ag = Ap + (size_t)mt * 128 * 1536;
    const __nv_bfloat16* Bg = Bp + (size_t)nt * 128 * 1536;

#define HLOAD(s, buf) { \
    uint32_t ab_ = sb_a + (buf) * HG_A_BYTES; \
    uint32_t bb_ = sb_b + (buf) * HG_B_BYTES; \
    const __nv_bfloat16* As_ = Ag + (s) * 64; \
    const __nv_bfloat16* Bs_ = Bg + (s) * 64; \
    _Pragma("unroll") \
    for (int i_ = 0; i_ < 4; i_++) { int ix_ = tid + i_ * 256; int r_ = ix_ >> 3, c_ = ix_ & 7; \
        cp_async16(ab_ + SW128(r_ * 128 + c_ * 16), As_ + (size_t)r_ * 1536 + c_ * 8); } \
    _Pragma("unroll") \
    for (int i_ = 0; i_ < 4; i_++) { int ix_ = tid + i_ * 256; int r_ = ix_ >> 3, c_ = ix_ & 7; \
        cp_async16(bb_ + SW128(r_ * 128 + c_ * 16), Bs_ + (size_t)r_ * 1536 + c_ * 8); } \
    CP_COMMIT(); }

    float acc[2][8][4];
#pragma unroll
    for (int i = 0; i < 2; i++)
#pragma unroll
        for (int j = 0; j < 8; j++)
#pragma unroll
            for (int v = 0; v < 4; v++) acc[i][j][v] = 0.f;

    HLOAD(0, 0);
    HLOAD(1, 1);

    const int a_row_off = ((lane >> 3) & 1) * 8 + (lane & 7);
    const int a_kb_off  = ((lane >> 4) & 1) * 16;
    const int b_row_off = ((lane >> 4) & 1) * 8 + (lane & 7);
    const int b_kb_off  = ((lane >> 3) & 1) * 16;

    for (int s = 0; s < 24; s++) {
        int buf = s & 1;
        CP_WAIT(1);
        __syncthreads();
        uint32_t abase = sb_a + buf * HG_A_BYTES;
        uint32_t bbase = sb_b + buf * HG_B_BYTES;
#pragma unroll
        for (int kk = 0; kk < 4; kk++) {
            uint32_t a[2][4];
#pragma unroll
            for (int mi = 0; mi < 2; mi++) {
                int row = m0 + mi * 16 + a_row_off;
                int kb = kk * 32 + a_kb_off;
                ldsm_x4(a[mi][0], a[mi][1], a[mi][2], a[mi][3], abase + SW128(row * 128 + kb));
            }
            uint32_t bfr[4][4];
#pragma unroll
            for (int ng = 0; ng < 4; ng++) {
                int row = n0 + ng * 16 + b_row_off;
                int kb = kk * 32 + b_kb_off;
                ldsm_x4(bfr[ng][0], bfr[ng][1], bfr[ng][2], bfr[ng][3], bbase + SW128(row * 128 + kb));
            }
#pragma unroll
            for (int mi = 0; mi < 2; mi++)
#pragma unroll
                for (int nj = 0; nj < 8; nj++) {
                    uint32_t b0 = bfr[nj >> 1][(nj & 1) * 2];
                    uint32_t b1 = bfr[nj >> 1][(nj & 1) * 2 + 1];
                    mma16816(acc[mi][nj][0], acc[mi][nj][1], acc[mi][nj][2], acc[mi][nj][3],
                             a[mi][0], a[mi][1], a[mi][2], a[mi][3], b0, b1);
                }
        }
        __syncthreads();
        if (s + 2 < 24) HLOAD(s + 2, buf);
    }

    int gr = mt * 128 + m0 + (lane >> 2);
    int gc = nt * 128 + n0 + (lane & 3) * 2;
#pragma unroll
    for (int mi = 0; mi < 2; mi++) {
#pragma unroll
        for (int nj = 0; nj < 8; nj++) {
            float* p0 = C + (size_t)(gr + mi * 16) * V_ + gc + nj * 8;
            float* p1 = C + (size_t)(gr + mi * 16 + 8) * V_ + gc + nj * 8;
            *reinterpret_cast<float2*>(p0) = make_float2(acc[mi][nj][0], acc[mi][nj][1]);
            *reinterpret_cast<float2*>(p1) = make_float2(acc[mi][nj][2], acc[mi][nj][3]);
        }
    }
}

// ---------------- host orchestration ----------------
#define PERS_SMEM (21760 * 4)

extern "C" void kernel_launch(void* const* d_in, const int* in_sizes, int n_in,
                              void* d_out, int out_size) {
    const int*   tokens  = (const int*)d_in[0];
    const unsigned char* enc_mask = (const unsigned char*)d_in[1];
    const float* enc_out = (const float*)d_in[2];
    const float* embed_w = (const float*)d_in[3];
    const float* g1Wx = (const float*)d_in[4];
    const float* g1Wh = (const float*)d_in[5];
    const float* g1bx = (const float*)d_in[6];
    const float* g1bh = (const float*)d_in[7];
    const float* g2Wx = (const float*)d_in[8];
    const float* g2Wh = (const float*)d_in[9];
    const float* g2bx = (const float*)d_in[10];
    const float* g2bh = (const float*)d_in[11];
    const float* brW  = (const float*)d_in[12];
    const float* brB  = (const float*)d_in[13];
    const float* Wk   = (const float*)d_in[14];
    const float* bk   = (const float*)d_in[15];
    const float* Wq   = (const float*)d_in[16];
    const float* bq   = (const float*)d_in[17];
    const float* Ww   = (const float*)d_in[18];
    const float* bw   = (const float*)d_in[19];
    const float* Wf   = (const float*)d_in[20];
    const float* bf   = (const float*)d_in[21];
    const float* Wo   = (const float*)d_in[22];
    const float* bo   = (const float*)d_in[23];
    float* out = (float*)d_out;

    float* S = nullptr;
    cudaGetSymbolAddress((void**)&S, g_scratch);
    float* feat    = S + OFF_FEAT;
    float* keyup   = S + OFF_KEYUP;
    float* logits  = S + OFF_LOGITS;
    float* hT      = S + OFF_HT;
    float* tmp     = S + OFF_TMP;
    float* tmpT    = S + OFF_TMPT;
    float* ctxrawT = S + OFF_CTXRT;
    float* X1all   = S + OFF_X1ALL;
    float* Wfx2    = S + OFF_WFX2;
    float* bfx2    = S + OFF_BFX2;
    float* WqT     = S + OFF_WQT;
    float* WfT     = S + OFF_WFT;
    float* Wo2f    = S + OFF_WO2F;
    float* Wopk    = S + OFF_WOPK;
    float* bo2     = S + OFF_BO2;
    __nv_bfloat16* Ahl = (__nv_bfloat16*)(S + OFF_AHL);
    __nv_bfloat16* Bhl = (__nv_bfloat16*)(S + OFF_BHL);

    // ---- prep ----
    k_embed<<<B_ * T_, 128>>>(tokens, embed_w, feat);
    k_bridge<<<B_, 512>>>(enc_mask, enc_out, brW, brB, hT);
    k_transpose<<<(512 * 512 + 255) / 256, 256>>>(Wq, WqT, 512, 512);
    k_transpose<<<(1024 * 1024 + 255) / 256, 256>>>(Wf, WfT, 1024, 1024);
    k_bfx2<<<6, 256>>>(g2Wx, bf, g2bx, bfx2);
    k_bo2<<<2, 256>>>(Wo, bf, bo, bo2);
    k_convB<<<(32000 * 128 + 255) / 256, 256>>>(embed_w, Bhl);
    {   // keyup = enc @ Wk^T + bk
        dim3 g(512 / BN, 2048 / BM);
        sgemm_nt<<<g, 256>>>(enc_out, Wk, bk, keyup, 2048, 512, 1024, 1024, 2);
    }
    {   // X1all = emb @ g1Wx^T + g1bx
        dim3 g(1536 / BN, 2048 / BM);
        sgemm_nt<<<g, 256>>>(feat, g1Wx, g1bx, X1all, 2048, 1536, 512, 2048, 0);
    }
    {   // Wfx2 = g2Wx (x) Wf   (Wfx2[g][n] = sum_k g2Wx[g][k] Wf[k][n])
        dim3 g(1024 / BN, 1536 / BM);
        sgemm_nt<<<g, 256>>>(g2Wx, WfT, nullptr, Wfx2, 1536, 1024, 1024, 1024, 0);
    }
    {   // Wo2f[e][n] = sum_m Wo[e][1024+m] Wf[m][n]
        dim3 g(1024 / BN, 512 / BM);
        sgemm_nt<<<g, 256>>>(Wo + 1024, WfT, nullptr, Wo2f, 512, 1024, 1024, 2048, 0);
    }
    k_wopack<<<(512 * 2048 + 255) / 256, 256>>>(Wo, Wo2f, Wopk);

    // ---- persistent recurrence ----
    k_zero<<<1, 1>>>();
    cudaFuncSetAttribute(k_persistent, cudaFuncAttributeMaxDynamicSharedMemorySize, PERS_SMEM);
    k_persistent<<<NB, 512, PERS_SMEM>>>(X1all, g1Wh, g1bh, Wfx2, bfx2, g2Wh, g2bh,
                                         WqT, bq, Ww, bw,
                                         enc_out, enc_mask, keyup,
                                         feat, hT, tmp, tmpT, ctxrawT);

    {   // logits = tanh(feat_pack @ Wopk^T + bo2)
        dim3 g(512 / BN, 2048 / BM);
        sgemm_nt<<<g, 256>>>(feat, Wopk, bo2, logits, 2048, 512, 2048, 2048, 1);
    }
    // out = logits @ embed_w^T via HMMA bf16 hi/lo K-extended GEMM
    k_convA<<<(2048 * 128 + 255) / 256, 256>>>(logits, Ahl);
    cudaFuncSetAttribute(mma_gemm_hmma, cudaFuncAttributeMaxDynamicSharedMemorySize, HG_SMEM_TOTAL);
    {
        dim3 g(V_ / 128, 2048 / 128);
        mma_gemm_hmma<<<g, 256, HG_SMEM_TOTAL>>>(Ahl, Bhl, out);
    }
}

// round 7
// speedup vs baseline: 2.5724x; 1.1792x over previous
#include <cuda_runtime.h>
#include <cuda_bf16.h>
#include <math.h>
#include <stdint.h>

// Problem dims
#define B_ 32
#define T_ 64
#define S_ 64
#define V_ 32000
#define E_ 512
#define H_ 512
#define U_ 1024
#define NH_ 8
#define D_ 64
#define DV_ 128
#define FEATW 2048
#define NB 148

// ---------------- scratch offsets (floats) ----------------
#define OFF_FEAT   0ull
#define OFF_KEYUP  4194304ull
#define OFF_LOGITS 5242880ull
#define OFF_HT     6291456ull     // hT4 [128 kg][32 b][4] = 16384
#define OFF_TMP    6307840ull     // t4 same layout = 16384
#define OFF_CTXRT  6340608ull     // c4 [256 kg][32 b][4] = 32768
#define OFF_X1ALL  6373376ull     // [2048][1536]
#define OFF_WFX2   9519104ull     // [1536][1024]
#define OFF_BFX2   11091968ull    // [1536] (pad 2048)
#define OFF_WQT    11094016ull    // [512][512]
#define OFF_WFT    11356160ull    // [1024][1024]
#define OFF_WO2F   12404736ull    // [512][1024]
#define OFF_WOPK   12929024ull    // [512][2048]
#define OFF_BO2    13977600ull    // [512] (pad 1024)
#define OFF_AHL    13978624ull    // [2048,1536] bf16
#define OFF_BHL    15551488ull    // [32000,1536] bf16
#define SCRATCH_FLOATS 40127488ull

__device__ float g_scratch[SCRATCH_FLOATS];
__device__ unsigned g_bar_ctr;

// ======================= helpers =======================
__device__ __forceinline__ uint32_t smem_to_u32(const void* p) {
    uint32_t a;
    asm("{ .reg .u64 t; cvta.to.shared.u64 t, %1; cvt.u32.u64 %0, t; }" : "=r"(a) : "l"(p));
    return a;
}
__device__ __forceinline__ void cp_async16(uint32_t dst, const void* src) {
    asm volatile("cp.async.cg.shared.global [%0], [%1], 16;" :: "r"(dst), "l"(src));
}
#define CP_COMMIT() asm volatile("cp.async.commit_group;" ::: "memory")
#define CP_WAIT(n)  asm volatile("cp.async.wait_group %0;" :: "n"(n) : "memory")
#define SW128(x) ((x) ^ (((x) >> 3) & 0x70))

__device__ __forceinline__ void ldsm_x4(uint32_t& r0, uint32_t& r1, uint32_t& r2, uint32_t& r3,
                                        uint32_t addr) {
    asm volatile("ldmatrix.sync.aligned.m8n8.x4.shared.b16 {%0,%1,%2,%3}, [%4];"
                 : "=r"(r0), "=r"(r1), "=r"(r2), "=r"(r3) : "r"(addr));
}
__device__ __forceinline__ void mma16816(float& c0, float& c1, float& c2, float& c3,
                                         uint32_t a0, uint32_t a1, uint32_t a2, uint32_t a3,
                                         uint32_t b0, uint32_t b1) {
    asm volatile("mma.sync.aligned.m16n8k16.row.col.f32.bf16.bf16.f32 "
                 "{%0,%1,%2,%3}, {%4,%5,%6,%7}, {%8,%9}, {%0,%1,%2,%3};"
                 : "+f"(c0), "+f"(c1), "+f"(c2), "+f"(c3)
                 : "r"(a0), "r"(a1), "r"(a2), "r"(a3), "r"(b0), "r"(b1));
}

__device__ __forceinline__ void gsync(unsigned& gen) {
    __syncthreads();
    if (threadIdx.x == 0) {
        __threadfence();
        atomicAdd(&g_bar_ctr, 1u);
        unsigned target = (gen + 1u) * (unsigned)NB;
        unsigned v;
        do {
            asm volatile("ld.acquire.gpu.u32 %0, [%1];" : "=r"(v) : "l"(&g_bar_ctr) : "memory");
        } while (v < target);
    }
    gen++;
    __syncthreads();
}
__global__ void k_zero() { g_bar_ctr = 0u; }

// ---------------- prep kernels ----------------
__global__ void k_embed(const int* __restrict__ tokens, const float* __restrict__ embed_w,
                        float* __restrict__ feat) {
    int bt = blockIdx.x;
    int tok = tokens[bt];
    const float4* src = reinterpret_cast<const float4*>(embed_w + (size_t)tok * E_);
    float4* dst = reinterpret_cast<float4*>(feat + (size_t)bt * FEATW);
    dst[threadIdx.x] = src[threadIdx.x];
}

// bridge -> h0 in [kg][b][4] layout
__global__ __launch_bounds__(512) void k_bridge(const unsigned char* __restrict__ mask,
                                                const float* __restrict__ enc_out,
                                                const float* __restrict__ Wb,
                                                const float* __restrict__ bb,
                                                float* __restrict__ hT4) {
    int b = blockIdx.x;
    int j = threadIdx.x;
    __shared__ float fn[512];
    __shared__ int sL;
    if (j == 0) {
        int L = S_;
        for (int s = 0; s < S_; s++) if (mask[b * S_ + s]) L--;
        sL = L;
    }
    __syncthreads();
    int L = sL;
    fn[j] = enc_out[((size_t)(L - 1) * B_ + b) * U_ + j];
    __syncthreads();
    float acc = bb[j];
    const float* wr = Wb + (size_t)j * 512;
    for (int k = 0; k < 512; k++) acc += fn[k] * wr[k];
    hT4[(j >> 2) * 128 + b * 4 + (j & 3)] = tanhf(acc);
}

__global__ void k_transpose(const float* __restrict__ W, float* __restrict__ WT, int R, int C) {
    int idx = blockIdx.x * 256 + threadIdx.x;
    if (idx >= R * C) return;
    int n = idx / C, k = idx % C;
    WT[(size_t)k * R + n] = W[idx];
}

__global__ void k_bfx2(const float* __restrict__ g2Wx, const float* __restrict__ bf,
                       const float* __restrict__ g2bx, float* __restrict__ bfx2) {
    int g = blockIdx.x * 256 + threadIdx.x;
    if (g >= 1536) return;
    float a = g2bx[g];
    const float4* w4 = reinterpret_cast<const float4*>(g2Wx + (size_t)g * 1024);
    const float4* b4 = reinterpret_cast<const float4*>(bf);
    for (int k = 0; k < 256; k++) {
        float4 w = w4[k], b = b4[k];
        a += w.x * b.x + w.y * b.y + w.z * b.z + w.w * b.w;
    }
    bfx2[g] = a;
}

__global__ void k_wopack(const float* __restrict__ Wo, const float* __restrict__ Wo2f,
                         float* __restrict__ Wp) {
    int idx = blockIdx.x * 256 + threadIdx.x;
    if (idx >= 512 * 2048) return;
    int e = idx >> 11, c = idx & 2047;
    Wp[idx] = (c < 1024) ? Wo[(size_t)e * 2048 + c] : Wo2f[(size_t)e * 1024 + (c - 1024)];
}
__global__ void k_bo2(const float* __restrict__ Wo, const float* __restrict__ bf,
                      const float* __restrict__ bo, float* __restrict__ bo2) {
    int e = blockIdx.x * 256 + threadIdx.x;
    if (e >= 512) return;
    float a = bo[e];
    const float* w = Wo + (size_t)e * 2048 + 1024;
    for (int m = 0; m < 1024; m++) a += w[m] * bf[m];
    bo2[e] = a;
}

// ---------------- tiled SGEMM-NT with lda ----------------
#define BM 128
#define BN 128
#define BKk 16
__global__ __launch_bounds__(256) void sgemm_nt(const float* __restrict__ A,
                                                const float* __restrict__ Bm,
                                                const float* __restrict__ bias,
                                                float* __restrict__ C,
                                                int M, int N, int K, int lda, int mode) {
    __shared__ float As[BKk][BM];
    __shared__ float Bs[BKk][BN];
    const int bm = blockIdx.y * BM, bn = blockIdx.x * BN;
    const int tid = threadIdx.x;
    const int tm = (tid >> 4) << 3;
    const int tn = (tid & 15) << 3;
    float acc[8][8];
#pragma unroll
    for (int i = 0; i < 8; i++)
#pragma unroll
        for (int j = 0; j < 8; j++) acc[i][j] = 0.f;

    for (int k0 = 0; k0 < K; k0 += BKk) {
#pragma unroll
        for (int i = 0; i < 2; i++) {
            int idx = tid + i * 256;
            int r = idx >> 2, c = (idx & 3) << 2;
            float4 v = *reinterpret_cast<const float4*>(A + (size_t)(bm + r) * lda + k0 + c);
            As[c][r] = v.x; As[c + 1][r] = v.y; As[c + 2][r] = v.z; As[c + 3][r] = v.w;
            float4 w = *reinterpret_cast<const float4*>(Bm + (size_t)(bn + r) * K + k0 + c);
            Bs[c][r] = w.x; Bs[c + 1][r] = w.y; Bs[c + 2][r] = w.z; Bs[c + 3][r] = w.w;
        }
        __syncthreads();
#pragma unroll
        for (int k = 0; k < BKk; k++) {
            float a[8], bb[8];
            *reinterpret_cast<float4*>(&a[0]) = *reinterpret_cast<const float4*>(&As[k][tm]);
            *reinterpret_cast<float4*>(&a[4]) = *reinterpret_cast<const float4*>(&As[k][tm + 4]);
            *reinterpret_cast<float4*>(&bb[0]) = *reinterpret_cast<const float4*>(&Bs[k][tn]);
            *reinterpret_cast<float4*>(&bb[4]) = *reinterpret_cast<const float4*>(&Bs[k][tn + 4]);
#pragma unroll
            for (int i = 0; i < 8; i++)
#pragma unroll
                for (int j = 0; j < 8; j++) acc[i][j] += a[i] * bb[j];
        }
        __syncthreads();
    }
#pragma unroll
    for (int i = 0; i < 8; i++) {
        int m = bm + tm + i;
#pragma unroll
        for (int j = 0; j < 8; j++) {
            int n = bn + tn + j;
            float v = acc[i][j];
            if (bias) v += bias[n];
            if (mode == 1) v = tanhf(v);
            if (mode == 2) {
                int s_ = m >> 5, b_ = m & 31, nh_ = n >> 6, d_ = n & 63;
                C[(((size_t)(b_ * 8 + nh_) * 64) + s_) * 64 + d_] = v;
            } else {
                C[(size_t)m * N + n] = v;
            }
        }
    }
}

// ---------------- persistent recurrence: weights smem-resident ----------------
// smem: W1s 12288 | W2xs 24576 | W2hs 12288 | scr 2048  = 51200 floats (200 KB)
#define PERS_SMEM (51200 * 4)

__global__ __launch_bounds__(512, 1)
void k_persistent(const float* __restrict__ X1all, const float* __restrict__ g1Wh,
                  const float* __restrict__ g1bh,
                  const float* __restrict__ Wfx2, const float* __restrict__ bfx2,
                  const float* __restrict__ g2Wh, const float* __restrict__ g2bh,
                  const float* __restrict__ WqT, const float* __restrict__ bq,
                  const float* __restrict__ Ww, const float* __restrict__ bw,
                  const float* __restrict__ enc_out, const unsigned char* __restrict__ mask,
                  const float* __restrict__ keyup,
                  float* __restrict__ feat, float* __restrict__ hT4,
                  float* __restrict__ t4, float* __restrict__ c4) {
    extern __shared__ float sm[];
    float* W1s  = sm;
    float* W2xs = sm + 12288;
    float* W2hs = sm + 36864;
    float* scr  = sm + 49152;
    const int bid = blockIdx.x, tid = threadIdx.x;
    unsigned gen = 0;
    const int bl = tid & 15, jl = (tid >> 4) & 7, q = tid >> 7;
    const int jb = bid >> 1, bh = bid & 1;
    const int j0 = jb * 8, b0 = bh * 16;

    // ---- stage loop-invariant weights ONCE ----
    if (bid < 128) {
        float4* d1 = reinterpret_cast<float4*>(W1s);
        for (int i = tid; i < 3072; i += 512) {
            int jj = i / 384, rem = i % 384, g = rem >> 7, k4 = rem & 127;
            d1[i] = *reinterpret_cast<const float4*>(
                g1Wh + ((size_t)(g * 512 + j0 + jj)) * 512 + k4 * 4);
        }
        float4* d2 = reinterpret_cast<float4*>(W2xs);
        for (int i = tid; i < 6144; i += 512) {
            int jj = i / 768, rem = i % 768, g = rem >> 8, k4 = rem & 255;
            d2[i] = *reinterpret_cast<const float4*>(
                Wfx2 + ((size_t)(g * 512 + j0 + jj)) * 1024 + k4 * 4);
        }
        float4* d3 = reinterpret_cast<float4*>(W2hs);
        for (int i = tid; i < 3072; i += 512) {
            int jj = i / 384, rem = i % 384, g = rem >> 7, k4 = rem & 127;
            d3[i] = *reinterpret_cast<const float4*>(
                g2Wh + ((size_t)(g * 512 + j0 + jj)) * 512 + k4 * 4);
        }
    }
    __syncthreads();

    for (int t = 0; t < T_; t++) {
        // ============ P1: GRU1 h-gates + combine ============
        float ar = 0.f, az = 0.f, an = 0.f;
        if (bid < 128) {
            const float4* xp = reinterpret_cast<const float4*>(hT4) + q * 1024 + b0 + bl;
            const float4* wr4 = reinterpret_cast<const float4*>(W1s + (jl * 3 + 0) * 512) + q * 32;
            const float4* wz4 = reinterpret_cast<const float4*>(W1s + (jl * 3 + 1) * 512) + q * 32;
            const float4* wn4 = reinterpret_cast<const float4*>(W1s + (jl * 3 + 2) * 512) + q * 32;
#pragma unroll 8
            for (int kk = 0; kk < 32; kk++) {
                float4 x = __ldcg(xp + kk * 32);
                float4 wr = wr4[kk], wz = wz4[kk], wn = wn4[kk];
                ar += x.x * wr.x + x.y * wr.y + x.z * wr.z + x.w * wr.w;
                az += x.x * wz.x + x.y * wz.y + x.z * wz.z + x.w * wz.w;
                an += x.x * wn.x + x.y * wn.y + x.z * wn.z + x.w * wn.w;
            }
            if (q) {
                int o = (q - 1) * 384 + (jl * 16 + bl) * 3;
                scr[o] = ar; scr[o + 1] = az; scr[o + 2] = an;
            }
        }
        __syncthreads();
        if (bid < 128 && q == 0) {
            int o = (jl * 16 + bl) * 3;
            ar += scr[o] + scr[384 + o] + scr[768 + o];
            az += scr[o + 1] + scr[384 + o + 1] + scr[768 + o + 1];
            an += scr[o + 2] + scr[384 + o + 2] + scr[768 + o + 2];
            int j = j0 + jl, b = b0 + bl, m = b * T_ + t;
            const float* X1 = X1all + (size_t)m * 1536;
            float r = 1.f / (1.f + expf(-(X1[j] + g1bh[j] + ar)));
            float z = 1.f / (1.f + expf(-(X1[512 + j] + g1bh[512 + j] + az)));
            float n = tanhf(X1[1024 + j] + r * (an + g1bh[1024 + j]));
            float hp = __ldcg(hT4 + (j >> 2) * 128 + b * 4 + (j & 3));
            float o2 = (1.f - z) * n + z * hp;
            t4[(j >> 2) * 128 + b * 4 + (j & 3)] = o2;
        }
        gsync(gen);

        // ============ P2: attention (2 (b,nh) pairs per block) ============
        if (bid < 128) {
            int pr = tid >> 8, tid2 = tid & 255;
            int p = bid * 2 + pr, b = p >> 3, nh = p & 7;
            float* st  = scr + pr * 512;
            float* sq  = scr + 1024 + pr * 64;
            float* sa  = scr + 1152 + pr * 64;
            float* qp  = scr + 1280 + pr * 256;
            float* scp = scr + 1792 + pr * 128;
            for (int i = tid2; i < 512; i += 256)
                st[i] = __ldcg(t4 + (i >> 2) * 128 + b * 4 + (i & 3));
            __syncthreads();
            {
                int d = tid2 & 63, kq = tid2 >> 6;
                float a = 0.f;
                const float* wp = WqT + nh * 64 + d;
                int k0 = kq * 128;
                for (int k = k0; k < k0 + 128; k++) a += st[k] * wp[(size_t)k * 512];
                qp[kq * 64 + d] = a;
            }
            __syncthreads();
            if (tid2 < 64)
                sq[tid2] = bq[nh * 64 + tid2] + qp[tid2] + qp[64 + tid2] + qp[128 + tid2] + qp[192 + tid2];
            __syncthreads();
            if (tid2 < 128) {
                int s = tid2 & 63, dh = tid2 >> 6;
                float a = 0.f;
                const float* kp = keyup + (((size_t)(b * 8 + nh)) * 64 + s) * 64 + dh * 32;
                const float* sqh = sq + dh * 32;
                const float* wwh = Ww + dh * 32;
#pragma unroll 8
                for (int d = 0; d < 32; d++) a += tanhf(sqh[d] + kp[d]) * wwh[d];
                scp[dh * 64 + s] = a;
            }
            __syncthreads();
            if (tid2 < 64) {
                float sc = scp[tid2] + scp[64 + tid2] + bw[0];
                if (mask[b * S_ + tid2]) sc -= 1e9f;
                sa[tid2] = sc;
            }
            __syncthreads();
            if (tid2 == 0) {
                float mx = -1e30f;
                for (int s = 0; s < 64; s++) mx = fmaxf(mx, sa[s]);
                float sum = 0.f;
                for (int s = 0; s < 64; s++) { float e = expf(sa[s] - mx); sa[s] = e; sum += e; }
                float inv = 1.f / sum;
                for (int s = 0; s < 64; s++) sa[s] *= inv;
            }
            __syncthreads();
            if (tid2 < 128) {
                float a = 0.f;
                const float* vp = enc_out + (size_t)b * U_ + nh * 128 + tid2;
#pragma unroll
                for (int s = 0; s < 64; s++) a += sa[s] * vp[(size_t)s * B_ * U_];
                int n = nh * 128 + tid2;
                c4[(n >> 2) * 128 + b * 4 + (n & 3)] = a;
                feat[((size_t)b * T_ + t) * FEATW + 1024 + n] = a;
            }
        }
        gsync(gen);

        // ============ P3: GRU2 gates + combine ============
        float a_r = 0.f, a_z = 0.f, a_xn = 0.f, a_hn = 0.f;
        if (bid < 128) {
            // x-part: K=1024 over c4 with W2xs
            {
                const float4* xp = reinterpret_cast<const float4*>(c4) + q * 2048 + b0 + bl;
                const float4* wr4 = reinterpret_cast<const float4*>(W2xs + (jl * 3 + 0) * 1024) + q * 64;
                const float4* wz4 = reinterpret_cast<const float4*>(W2xs + (jl * 3 + 1) * 1024) + q * 64;
                const float4* wn4 = reinterpret_cast<const float4*>(W2xs + (jl * 3 + 2) * 1024) + q * 64;
#pragma unroll 8
                for (int kk = 0; kk < 64; kk++) {
                    float4 x = __ldcg(xp + kk * 32);
                    float4 wr = wr4[kk], wz = wz4[kk], wn = wn4[kk];
                    a_r  += x.x * wr.x + x.y * wr.y + x.z * wr.z + x.w * wr.w;
                    a_z  += x.x * wz.x + x.y * wz.y + x.z * wz.z + x.w * wz.w;
                    a_xn += x.x * wn.x + x.y * wn.y + x.z * wn.z + x.w * wn.w;
                }
            }
            // h-part: K=512 over t4 with W2hs
            {
                const float4* xp = reinterpret_cast<const float4*>(t4) + q * 1024 + b0 + bl;
                const float4* wr4 = reinterpret_cast<const float4*>(W2hs + (jl * 3 + 0) * 512) + q * 32;
                const float4* wz4 = reinterpret_cast<const float4*>(W2hs + (jl * 3 + 1) * 512) + q * 32;
                const float4* wn4 = reinterpret_cast<const float4*>(W2hs + (jl * 3 + 2) * 512) + q * 32;
#pragma unroll 8
                for (int kk = 0; kk < 32; kk++) {
                    float4 x = __ldcg(xp + kk * 32);
                    float4 wr = wr4[kk], wz = wz4[kk], wn = wn4[kk];
                    a_r  += x.x * wr.x + x.y * wr.y + x.z * wr.z + x.w * wr.w;
                    a_z  += x.x * wz.x + x.y * wz.y + x.z * wz.z + x.w * wz.w;
                    a_hn += x.x * wn.x + x.y * wn.y + x.z * wn.z + x.w * wn.w;
                }
            }
            if (q) {
                int o = (q - 1) * 512 + (jl * 16 + bl) * 4;
                scr[o] = a_r; scr[o + 1] = a_z; scr[o + 2] = a_xn; scr[o + 3] = a_hn;
            }
        }
        __syncthreads();
        if (bid < 128 && q == 0) {
            int o = (jl * 16 + bl) * 4;
            a_r  += scr[o] + scr[512 + o] + scr[1024 + o];
            a_z  += scr[o + 1] + scr[512 + o + 1] + scr[1024 + o + 1];
            a_xn += scr[o + 2] + scr[512 + o + 2] + scr[1024 + o + 2];
            a_hn += scr[o + 3] + scr[512 + o + 3] + scr[1024 + o + 3];
            int j = j0 + jl, b = b0 + bl, m = b * T_ + t;
            float r = 1.f / (1.f + expf(-(a_r + bfx2[j] + g2bh[j])));
            float z = 1.f / (1.f + expf(-(a_z + bfx2[512 + j] + g2bh[512 + j])));
            float n = tanhf(a_xn + bfx2[1024 + j] + r * (a_hn + g2bh[1024 + j]));
            float hp = __ldcg(t4 + (j >> 2) * 128 + b * 4 + (j & 3));
            float o2 = (1.f - z) * n + z * hp;
            hT4[(j >> 2) * 128 + b * 4 + (j & 3)] = o2;
            feat[(size_t)m * FEATW + 512 + j] = o2;
        }
        gsync(gen);
    }
}

// ============ bf16 hi/lo split conversion ============
__global__ void k_convA(const float* __restrict__ L, __nv_bfloat16* __restrict__ A) {
    int idx = blockIdx.x * 256 + threadIdx.x;
    if (idx >= 2048 * 128) return;
    int m = idx >> 7, kg = (idx & 127) << 2;
    float4 v = *reinterpret_cast<const float4*>(L + (size_t)m * 512 + kg);
    __nv_bfloat16 h[4], l[4];
    float x[4] = {v.x, v.y, v.z, v.w};
#pragma unroll
    for (int i = 0; i < 4; i++) {
        h[i] = __float2bfloat16(x[i]);
        l[i] = __float2bfloat16(x[i] - __bfloat162float(h[i]));
    }
    __nv_bfloat162* p0 = reinterpret_cast<__nv_bfloat162*>(A + (size_t)m * 1536 + kg);
    __nv_bfloat162* p1 = reinterpret_cast<__nv_bfloat162*>(A + (size_t)m * 1536 + 512 + kg);
    __nv_bfloat162* p2 = reinterpret_cast<__nv_bfloat162*>(A + (size_t)m * 1536 + 1024 + kg);
    p0[0] = __nv_bfloat162(h[0], h[1]); p0[1] = __nv_bfloat162(h[2], h[3]);
    p1[0] = __nv_bfloat162(h[0], h[1]); p1[1] = __nv_bfloat162(h[2], h[3]);
    p2[0] = __nv_bfloat162(l[0], l[1]); p2[1] = __nv_bfloat162(l[2], l[3]);
}
__global__ void k_convB(const float* __restrict__ W, __nv_bfloat16* __restrict__ Bp) {
    int idx = blockIdx.x * 256 + threadIdx.x;
    if (idx >= 32000 * 128) return;
    int n = idx >> 7, kg = (idx & 127) << 2;
    float4 v = *reinterpret_cast<const float4*>(W + (size_t)n * 512 + kg);
    __nv_bfloat16 h[4], l[4];
    float x[4] = {v.x, v.y, v.z, v.w};
#pragma unroll
    for (int i = 0; i < 4; i++) {
        h[i] = __float2bfloat16(x[i]);
        l[i] = __float2bfloat16(x[i] - __bfloat162float(h[i]));
    }
    __nv_bfloat162* p0 = reinterpret_cast<__nv_bfloat162*>(Bp + (size_t)n * 1536 + kg);
    __nv_bfloat162* p1 = reinterpret_cast<__nv_bfloat162*>(Bp + (size_t)n * 1536 + 512 + kg);
    __nv_bfloat162* p2 = reinterpret_cast<__nv_bfloat162*>(Bp + (size_t)n * 1536 + 1024 + kg);
    p0[0] = __nv_bfloat162(h[0], h[1]); p0[1] = __nv_bfloat162(h[2], h[3]);
    p1[0] = __nv_bfloat162(l[0], l[1]); p1[1] = __nv_bfloat162(l[2], l[3]);
    p2[0] = __nv_bfloat162(h[0], h[1]); p2[1] = __nv_bfloat162(h[2], h[3]);
}

// ============ HMMA bf16 GEMM ============
#define HG_A_BYTES 16384
#define HG_B_BYTES 16384
#define HG_SMEM_TOTAL (2 * (HG_A_BYTES + HG_B_BYTES))

__global__ __launch_bounds__(256, 2)
void mma_gemm_hmma(const __nv_bfloat16* __restrict__ Ap, const __nv_bfloat16* __restrict__ Bp,
                   float* __restrict__ C) {
    extern __shared__ char smemc[];
    uint32_t sb_a = smem_to_u32(smemc);
    uint32_t sb_b = sb_a + 2 * HG_A_BYTES;
    const int tid = threadIdx.x, lane = tid & 31, wid = tid >> 5;
    const int mt = blockIdx.y, nt = blockIdx.x;
    const int m0 = (wid & 3) * 32;
    const int n0 = (wid >> 2) * 64;

    const __nv_bfloat16* Ag = Ap + (size_t)mt * 128 * 1536;
    const __nv_bfloat16* Bg = Bp + (size_t)nt * 128 * 1536;

#define HLOAD(s, buf) { \
    uint32_t ab_ = sb_a + (buf) * HG_A_BYTES; \
    uint32_t bb_ = sb_b + (buf) * HG_B_BYTES; \
    const __nv_bfloat16* As_ = Ag + (s) * 64; \
    const __nv_bfloat16* Bs_ = Bg + (s) * 64; \
    _Pragma("unroll") \
    for (int i_ = 0; i_ < 4; i_++) { int ix_ = tid + i_ * 256; int r_ = ix_ >> 3, c_ = ix_ & 7; \
        cp_async16(ab_ + SW128(r_ * 128 + c_ * 16), As_ + (size_t)r_ * 1536 + c_ * 8); } \
    _Pragma("unroll") \
    for (int i_ = 0; i_ < 4; i_++) { int ix_ = tid + i_ * 256; int r_ = ix_ >> 3, c_ = ix_ & 7; \
        cp_async16(bb_ + SW128(r_ * 128 + c_ * 16), Bs_ + (size_t)r_ * 1536 + c_ * 8); } \
    CP_COMMIT(); }

    float acc[2][8][4];
#pragma unroll
    for (int i = 0; i < 2; i++)
#pragma unroll
        for (int j = 0; j < 8; j++)
#pragma unroll
            for (int v = 0; v < 4; v++) acc[i][j][v] = 0.f;

    HLOAD(0, 0);
    HLOAD(1, 1);

    const int a_row_off = ((lane >> 3) & 1) * 8 + (lane & 7);
    const int a_kb_off  = ((lane >> 4) & 1) * 16;
    const int b_row_off = ((lane >> 4) & 1) * 8 + (lane & 7);
    const int b_kb_off  = ((lane >> 3) & 1) * 16;

    for (int s = 0; s < 24; s++) {
        int buf = s & 1;
        CP_WAIT(1);
        __syncthreads();
        uint32_t abase = sb_a + buf * HG_A_BYTES;
        uint32_t bbase = sb_b + buf * HG_B_BYTES;
#pragma unroll
        for (int kk = 0; kk < 4; kk++) {
            uint32_t a[2][4];
#pragma unroll
            for (int mi = 0; mi < 2; mi++) {
                int row = m0 + mi * 16 + a_row_off;
                int kb = kk * 32 + a_kb_off;
                ldsm_x4(a[mi][0], a[mi][1], a[mi][2], a[mi][3], abase + SW128(row * 128 + kb));
            }
            uint32_t bfr[4][4];
#pragma unroll
            for (int ng = 0; ng < 4; ng++) {
                int row = n0 + ng * 16 + b_row_off;
                int kb = kk * 32 + b_kb_off;
                ldsm_x4(bfr[ng][0], bfr[ng][1], bfr[ng][2], bfr[ng][3], bbase + SW128(row * 128 + kb));
            }
#pragma unroll
            for (int mi = 0; mi < 2; mi++)
#pragma unroll
                for (int nj = 0; nj < 8; nj++) {
                    uint32_t b0 = bfr[nj >> 1][(nj & 1) * 2];
                    uint32_t b1 = bfr[nj >> 1][(nj & 1) * 2 + 1];
                    mma16816(acc[mi][nj][0], acc[mi][nj][1], acc[mi][nj][2], acc[mi][nj][3],
                             a[mi][0], a[mi][1], a[mi][2], a[mi][3], b0, b1);
                }
        }
        __syncthreads();
        if (s + 2 < 24) HLOAD(s + 2, buf);
    }

    int gr = mt * 128 + m0 + (lane >> 2);
    int gc = nt * 128 + n0 + (lane & 3) * 2;
#pragma unroll
    for (int mi = 0; mi < 2; mi++) {
#pragma unroll
        for (int nj = 0; nj < 8; nj++) {
            float* p0 = C + (size_t)(gr + mi * 16) * V_ + gc + nj * 8;
            float* p1 = C + (size_t)(gr + mi * 16 + 8) * V_ + gc + nj * 8;
            *reinterpret_cast<float2*>(p0) = make_float2(acc[mi][nj][0], acc[mi][nj][1]);
            *reinterpret_cast<float2*>(p1) = make_float2(acc[mi][nj][2], acc[mi][nj][3]);
        }
    }
}

// ---------------- host orchestration ----------------
extern "C" void kernel_launch(void* const* d_in, const int* in_sizes, int n_in,
                              void* d_out, int out_size) {
    const int*   tokens  = (const int*)d_in[0];
    const unsigned char* enc_mask = (const unsigned char*)d_in[1];
    const float* enc_out = (const float*)d_in[2];
    const float* embed_w = (const float*)d_in[3];
    const float* g1Wx = (const float*)d_in[4];
    const float* g1Wh = (const float*)d_in[5];
    const float* g1bx = (const float*)d_in[6];
    const float* g1bh = (const float*)d_in[7];
    const float* g2Wx = (const float*)d_in[8];
    const float* g2Wh = (const float*)d_in[9];
    const float* g2bx = (const float*)d_in[10];
    const float* g2bh = (const float*)d_in[11];
    const float* brW  = (const float*)d_in[12];
    const float* brB  = (const float*)d_in[13];
    const float* Wk   = (const float*)d_in[14];
    const float* bk   = (const float*)d_in[15];
    const float* Wq   = (const float*)d_in[16];
    const float* bq   = (const float*)d_in[17];
    const float* Ww   = (const float*)d_in[18];
    const float* bw   = (const float*)d_in[19];
    const float* Wf   = (const float*)d_in[20];
    const float* bf   = (const float*)d_in[21];
    const float* Wo   = (const float*)d_in[22];
    const float* bo   = (const float*)d_in[23];
    float* out = (float*)d_out;

    float* S = nullptr;
    cudaGetSymbolAddress((void**)&S, g_scratch);
    float* feat    = S + OFF_FEAT;
    float* keyup   = S + OFF_KEYUP;
    float* logits  = S + OFF_LOGITS;
    float* hT4     = S + OFF_HT;
    float* t4      = S + OFF_TMP;
    float* c4      = S + OFF_CTXRT;
    float* X1all   = S + OFF_X1ALL;
    float* Wfx2    = S + OFF_WFX2;
    float* bfx2    = S + OFF_BFX2;
    float* WqT     = S + OFF_WQT;
    float* WfT     = S + OFF_WFT;
    float* Wo2f    = S + OFF_WO2F;
    float* Wopk    = S + OFF_WOPK;
    float* bo2     = S + OFF_BO2;
    __nv_bfloat16* Ahl = (__nv_bfloat16*)(S + OFF_AHL);
    __nv_bfloat16* Bhl = (__nv_bfloat16*)(S + OFF_BHL);

    // ---- prep ----
    k_embed<<<B_ * T_, 128>>>(tokens, embed_w, feat);
    k_bridge<<<B_, 512>>>(enc_mask, enc_out, brW, brB, hT4);
    k_transpose<<<(512 * 512 + 255) / 256, 256>>>(Wq, WqT, 512, 512);
    k_transpose<<<(1024 * 1024 + 255) / 256, 256>>>(Wf, WfT, 1024, 1024);
    k_bfx2<<<6, 256>>>(g2Wx, bf, g2bx, bfx2);
    k_bo2<<<2, 256>>>(Wo, bf, bo, bo2);
    k_convB<<<(32000 * 128 + 255) / 256, 256>>>(embed_w, Bhl);
    {   // keyup = enc @ Wk^T + bk
        dim3 g(512 / BN, 2048 / BM);
        sgemm_nt<<<g, 256>>>(enc_out, Wk, bk, keyup, 2048, 512, 1024, 1024, 2);
    }
    {   // X1all = emb @ g1Wx^T + g1bx
        dim3 g(1536 / BN, 2048 / BM);
        sgemm_nt<<<g, 256>>>(feat, g1Wx, g1bx, X1all, 2048, 1536, 512, 2048, 0);
    }
    {   // Wfx2 = g2Wx (x) Wf
        dim3 g(1024 / BN, 1536 / BM);
        sgemm_nt<<<g, 256>>>(g2Wx, WfT, nullptr, Wfx2, 1536, 1024, 1024, 1024, 0);
    }
    {   // Wo2f[e][n] = sum_m Wo[e][1024+m] Wf[m][n]
        dim3 g(1024 / BN, 512 / BM);
        sgemm_nt<<<g, 256>>>(Wo + 1024, WfT, nullptr, Wo2f, 512, 1024, 1024, 2048, 0);
    }
    k_wopack<<<(512 * 2048 + 255) / 256, 256>>>(Wo, Wo2f, Wopk);

    // ---- persistent recurrence ----
    k_zero<<<1, 1>>>();
    cudaFuncSetAttribute(k_persistent, cudaFuncAttributeMaxDynamicSharedMemorySize, PERS_SMEM);
    k_persistent<<<NB, 512, PERS_SMEM>>>(X1all, g1Wh, g1bh, Wfx2, bfx2, g2Wh, g2bh,
                                         WqT, bq, Ww, bw,
                                         enc_out, enc_mask, keyup,
                                         feat, hT4, t4, c4);

    {   // logits = tanh(feat_pack @ Wopk^T + bo2)
        dim3 g(512 / BN, 2048 / BM);
        sgemm_nt<<<g, 256>>>(feat, Wopk, bo2, logits, 2048, 512, 2048, 2048, 1);
    }
    // out = logits @ embed_w^T via HMMA bf16 hi/lo K-extended GEMM
    k_convA<<<(2048 * 128 + 255) / 256, 256>>>(logits, Ahl);
    cudaFuncSetAttribute(mma_gemm_hmma, cudaFuncAttributeMaxDynamicSharedMemorySize, HG_SMEM_TOTAL);
    {
        dim3 g(V_ / 128, 2048 / 128);
        mma_gemm_hmma<<<g, 256, HG_SMEM_TOTAL>>>(Ahl, Bhl, out);
    }
}

// round 8
// speedup vs baseline: 2.5762x; 1.0015x over previous
#include <cuda_runtime.h>
#include <cuda_bf16.h>
#include <math.h>
#include <stdint.h>

// Problem dims
#define B_ 32
#define T_ 64
#define S_ 64
#define V_ 32000
#define E_ 512
#define H_ 512
#define U_ 1024
#define NH_ 8
#define D_ 64
#define DV_ 128
#define FEATW 2048
#define NB 148

// ---------------- scratch offsets (floats) ----------------
#define OFF_FEAT   0ull
#define OFF_KEYUP  4194304ull
#define OFF_LOGITS 5242880ull
#define OFF_HT     6291456ull     // hT4 [128 kg][32 b][4] = 16384
#define OFF_TMP    6307840ull     // t4 same layout = 16384
#define OFF_CTXRT  6340608ull     // c4 [256 kg][32 b][4] = 32768
#define OFF_X1ALL  6373376ull     // [2048][1536]
#define OFF_WFX2   9519104ull     // [1536][1024]
#define OFF_BFX2   11091968ull    // [1536] (pad 2048)
#define OFF_WQT    11094016ull    // [512][512]
#define OFF_WFT    11356160ull    // [1024][1024]
#define OFF_WO2F   12404736ull    // [512][1024]
#define OFF_WOPK   12929024ull    // [512][2048]
#define OFF_BO2    13977600ull    // [512] (pad 1024)
#define OFF_AHL    13978624ull    // [2048,1536] bf16
#define OFF_BHL    15551488ull    // [32000,1536] bf16
#define SCRATCH_FLOATS 40127488ull

__device__ float g_scratch[SCRATCH_FLOATS];
__device__ unsigned g_bar_ctr;

// ======================= helpers =======================
__device__ __forceinline__ uint32_t smem_to_u32(const void* p) {
    uint32_t a;
    asm("{ .reg .u64 t; cvta.to.shared.u64 t, %1; cvt.u32.u64 %0, t; }" : "=r"(a) : "l"(p));
    return a;
}
__device__ __forceinline__ void cp_async16(uint32_t dst, const void* src) {
    asm volatile("cp.async.cg.shared.global [%0], [%1], 16;" :: "r"(dst), "l"(src));
}
#define CP_COMMIT() asm volatile("cp.async.commit_group;" ::: "memory")
#define CP_WAIT(n)  asm volatile("cp.async.wait_group %0;" :: "n"(n) : "memory")
#define SW128(x) ((x) ^ (((x) >> 3) & 0x70))

__device__ __forceinline__ void ldsm_x4(uint32_t& r0, uint32_t& r1, uint32_t& r2, uint32_t& r3,
                                        uint32_t addr) {
    asm volatile("ldmatrix.sync.aligned.m8n8.x4.shared.b16 {%0,%1,%2,%3}, [%4];"
                 : "=r"(r0), "=r"(r1), "=r"(r2), "=r"(r3) : "r"(addr));
}
__device__ __forceinline__ void mma16816(float& c0, float& c1, float& c2, float& c3,
                                         uint32_t a0, uint32_t a1, uint32_t a2, uint32_t a3,
                                         uint32_t b0, uint32_t b1) {
    asm volatile("mma.sync.aligned.m16n8k16.row.col.f32.bf16.bf16.f32 "
                 "{%0,%1,%2,%3}, {%4,%5,%6,%7}, {%8,%9}, {%0,%1,%2,%3};"
                 : "+f"(c0), "+f"(c1), "+f"(c2), "+f"(c3)
                 : "r"(a0), "r"(a1), "r"(a2), "r"(a3), "r"(b0), "r"(b1));
}

__device__ __forceinline__ void gsync(unsigned& gen) {
    __syncthreads();
    if (threadIdx.x == 0) {
        __threadfence();
        atomicAdd(&g_bar_ctr, 1u);
        unsigned target = (gen + 1u) * (unsigned)NB;
        unsigned v;
        do {
            asm volatile("ld.acquire.gpu.u32 %0, [%1];" : "=r"(v) : "l"(&g_bar_ctr) : "memory");
        } while (v < target);
    }
    gen++;
    __syncthreads();
}
__global__ void k_zero() { g_bar_ctr = 0u; }

// ---------------- prep kernels ----------------
__global__ void k_embed(const int* __restrict__ tokens, const float* __restrict__ embed_w,
                        float* __restrict__ feat) {
    int bt = blockIdx.x;
    int tok = tokens[bt];
    const float4* src = reinterpret_cast<const float4*>(embed_w + (size_t)tok * E_);
    float4* dst = reinterpret_cast<float4*>(feat + (size_t)bt * FEATW);
    dst[threadIdx.x] = src[threadIdx.x];
}

// bridge -> h0 in [kg][b][4] layout
__global__ __launch_bounds__(512) void k_bridge(const unsigned char* __restrict__ mask,
                                                const float* __restrict__ enc_out,
                                                const float* __restrict__ Wb,
                                                const float* __restrict__ bb,
                                                float* __restrict__ hT4) {
    int b = blockIdx.x;
    int j = threadIdx.x;
    __shared__ float fn[512];
    __shared__ int sL;
    if (j == 0) {
        int L = S_;
        for (int s = 0; s < S_; s++) if (mask[b * S_ + s]) L--;
        sL = L;
    }
    __syncthreads();
    int L = sL;
    fn[j] = enc_out[((size_t)(L - 1) * B_ + b) * U_ + j];
    __syncthreads();
    float acc = bb[j];
    const float* wr = Wb + (size_t)j * 512;
    for (int k = 0; k < 512; k++) acc += fn[k] * wr[k];
    hT4[(j >> 2) * 128 + b * 4 + (j & 3)] = tanhf(acc);
}

__global__ void k_transpose(const float* __restrict__ W, float* __restrict__ WT, int R, int C) {
    int idx = blockIdx.x * 256 + threadIdx.x;
    if (idx >= R * C) return;
    int n = idx / C, k = idx % C;
    WT[(size_t)k * R + n] = W[idx];
}

__global__ void k_bfx2(const float* __restrict__ g2Wx, const float* __restrict__ bf,
                       const float* __restrict__ g2bx, float* __restrict__ bfx2) {
    int g = blockIdx.x * 256 + threadIdx.x;
    if (g >= 1536) return;
    float a = g2bx[g];
    const float4* w4 = reinterpret_cast<const float4*>(g2Wx + (size_t)g * 1024);
    const float4* b4 = reinterpret_cast<const float4*>(bf);
    for (int k = 0; k < 256; k++) {
        float4 w = w4[k], b = b4[k];
        a += w.x * b.x + w.y * b.y + w.z * b.z + w.w * b.w;
    }
    bfx2[g] = a;
}

__global__ void k_wopack(const float* __restrict__ Wo, const float* __restrict__ Wo2f,
                         float* __restrict__ Wp) {
    int idx = blockIdx.x * 256 + threadIdx.x;
    if (idx >= 512 * 2048) return;
    int e = idx >> 11, c = idx & 2047;
    Wp[idx] = (c < 1024) ? Wo[(size_t)e * 2048 + c] : Wo2f[(size_t)e * 1024 + (c - 1024)];
}
__global__ void k_bo2(const float* __restrict__ Wo, const float* __restrict__ bf,
                      const float* __restrict__ bo, float* __restrict__ bo2) {
    int e = blockIdx.x * 256 + threadIdx.x;
    if (e >= 512) return;
    float a = bo[e];
    const float* w = Wo + (size_t)e * 2048 + 1024;
    for (int m = 0; m < 1024; m++) a += w[m] * bf[m];
    bo2[e] = a;
}

// ---------------- tiled SGEMM-NT with lda ----------------
#define BM 128
#define BN 128
#define BKk 16
__global__ __launch_bounds__(256) void sgemm_nt(const float* __restrict__ A,
                                                const float* __restrict__ Bm,
                                                const float* __restrict__ bias,
                                                float* __restrict__ C,
                                                int M, int N, int K, int lda, int mode) {
    __shared__ float As[BKk][BM];
    __shared__ float Bs[BKk][BN];
    const int bm = blockIdx.y * BM, bn = blockIdx.x * BN;
    const int tid = threadIdx.x;
    const int tm = (tid >> 4) << 3;
    const int tn = (tid & 15) << 3;
    float acc[8][8];
#pragma unroll
    for (int i = 0; i < 8; i++)
#pragma unroll
        for (int j = 0; j < 8; j++) acc[i][j] = 0.f;

    for (int k0 = 0; k0 < K; k0 += BKk) {
#pragma unroll
        for (int i = 0; i < 2; i++) {
            int idx = tid + i * 256;
            int r = idx >> 2, c = (idx & 3) << 2;
            float4 v = *reinterpret_cast<const float4*>(A + (size_t)(bm + r) * lda + k0 + c);
            As[c][r] = v.x; As[c + 1][r] = v.y; As[c + 2][r] = v.z; As[c + 3][r] = v.w;
            float4 w = *reinterpret_cast<const float4*>(Bm + (size_t)(bn + r) * K + k0 + c);
            Bs[c][r] = w.x; Bs[c + 1][r] = w.y; Bs[c + 2][r] = w.z; Bs[c + 3][r] = w.w;
        }
        __syncthreads();
#pragma unroll
        for (int k = 0; k < BKk; k++) {
            float a[8], bb[8];
            *reinterpret_cast<float4*>(&a[0]) = *reinterpret_cast<const float4*>(&As[k][tm]);
            *reinterpret_cast<float4*>(&a[4]) = *reinterpret_cast<const float4*>(&As[k][tm + 4]);
            *reinterpret_cast<float4*>(&bb[0]) = *reinterpret_cast<const float4*>(&Bs[k][tn]);
            *reinterpret_cast<float4*>(&bb[4]) = *reinterpret_cast<const float4*>(&Bs[k][tn + 4]);
#pragma unroll
            for (int i = 0; i < 8; i++)
#pragma unroll
                for (int j = 0; j < 8; j++) acc[i][j] += a[i] * bb[j];
        }
        __syncthreads();
    }
#pragma unroll
    for (int i = 0; i < 8; i++) {
        int m = bm + tm + i;
#pragma unroll
        for (int j = 0; j < 8; j++) {
            int n = bn + tn + j;
            float v = acc[i][j];
            if (bias) v += bias[n];
            if (mode == 1) v = tanhf(v);
            if (mode == 2) {
                int s_ = m >> 5, b_ = m & 31, nh_ = n >> 6, d_ = n & 63;
                C[(((size_t)(b_ * 8 + nh_) * 64) + s_) * 64 + d_] = v;
            } else {
                C[(size_t)m * N + n] = v;
            }
        }
    }
}

// ---------------- persistent recurrence: weights smem-resident ----------------
// smem: W1s 12288 | W2xs 24576 | W2hs 12288 | scr 2048  = 51200 floats (200 KB)
#define PERS_SMEM (51200 * 4)

__global__ __launch_bounds__(512, 1)
void k_persistent(const float* __restrict__ X1all, const float* __restrict__ g1Wh,
                  const float* __restrict__ g1bh,
                  const float* __restrict__ Wfx2, const float* __restrict__ bfx2,
                  const float* __restrict__ g2Wh, const float* __restrict__ g2bh,
                  const float* __restrict__ WqT, const float* __restrict__ bq,
                  const float* __restrict__ Ww, const float* __restrict__ bw,
                  const float* __restrict__ enc_out, const unsigned char* __restrict__ mask,
                  const float* __restrict__ keyup,
                  float* __restrict__ feat, float* __restrict__ hT4,
                  float* __restrict__ t4, float* __restrict__ c4) {
    extern __shared__ float sm[];
    float* W1s  = sm;
    float* W2xs = sm + 12288;
    float* W2hs = sm + 36864;
    float* scr  = sm + 49152;
    const int bid = blockIdx.x, tid = threadIdx.x;
    unsigned gen = 0;
    const int bl = tid & 15, jl = (tid >> 4) & 7, q = tid >> 7;
    const int jb = bid >> 1, bh = bid & 1;
    const int j0 = jb * 8, b0 = bh * 16;

    // ---- stage loop-invariant weights ONCE ----
    if (bid < 128) {
        float4* d1 = reinterpret_cast<float4*>(W1s);
        for (int i = tid; i < 3072; i += 512) {
            int jj = i / 384, rem = i % 384, g = rem >> 7, k4 = rem & 127;
            d1[i] = *reinterpret_cast<const float4*>(
                g1Wh + ((size_t)(g * 512 + j0 + jj)) * 512 + k4 * 4);
        }
        float4* d2 = reinterpret_cast<float4*>(W2xs);
        for (int i = tid; i < 6144; i += 512) {
            int jj = i / 768, rem = i % 768, g = rem >> 8, k4 = rem & 255;
            d2[i] = *reinterpret_cast<const float4*>(
                Wfx2 + ((size_t)(g * 512 + j0 + jj)) * 1024 + k4 * 4);
        }
        float4* d3 = reinterpret_cast<float4*>(W2hs);
        for (int i = tid; i < 3072; i += 512) {
            int jj = i / 384, rem = i % 384, g = rem >> 7, k4 = rem & 127;
            d3[i] = *reinterpret_cast<const float4*>(
                g2Wh + ((size_t)(g * 512 + j0 + jj)) * 512 + k4 * 4);
        }
    }
    __syncthreads();

    for (int t = 0; t < T_; t++) {
        // ============ P1: GRU1 h-gates + combine ============
        float ar = 0.f, az = 0.f, an = 0.f;
        if (bid < 128) {
            const float4* xp = reinterpret_cast<const float4*>(hT4) + q * 1024 + b0 + bl;
            const float4* wr4 = reinterpret_cast<const float4*>(W1s + (jl * 3 + 0) * 512) + q * 32;
            const float4* wz4 = reinterpret_cast<const float4*>(W1s + (jl * 3 + 1) * 512) + q * 32;
            const float4* wn4 = reinterpret_cast<const float4*>(W1s + (jl * 3 + 2) * 512) + q * 32;
#pragma unroll 8
            for (int kk = 0; kk < 32; kk++) {
                float4 x = __ldcg(xp + kk * 32);
                float4 wr = wr4[kk], wz = wz4[kk], wn = wn4[kk];
                ar += x.x * wr.x + x.y * wr.y + x.z * wr.z + x.w * wr.w;
                az += x.x * wz.x + x.y * wz.y + x.z * wz.z + x.w * wz.w;
                an += x.x * wn.x + x.y * wn.y + x.z * wn.z + x.w * wn.w;
            }
            if (q) {
                int o = (q - 1) * 384 + (jl * 16 + bl) * 3;
                scr[o] = ar; scr[o + 1] = az; scr[o + 2] = an;
            }
        }
        __syncthreads();
        if (bid < 128 && q == 0) {
            int o = (jl * 16 + bl) * 3;
            ar += scr[o] + scr[384 + o] + scr[768 + o];
            az += scr[o + 1] + scr[384 + o + 1] + scr[768 + o + 1];
            an += scr[o + 2] + scr[384 + o + 2] + scr[768 + o + 2];
            int j = j0 + jl, b = b0 + bl, m = b * T_ + t;
            const float* X1 = X1all + (size_t)m * 1536;
            float r = 1.f / (1.f + expf(-(X1[j] + g1bh[j] + ar)));
            float z = 1.f / (1.f + expf(-(X1[512 + j] + g1bh[512 + j] + az)));
            float n = tanhf(X1[1024 + j] + r * (an + g1bh[1024 + j]));
            float hp = __ldcg(hT4 + (j >> 2) * 128 + b * 4 + (j & 3));
            float o2 = (1.f - z) * n + z * hp;
            t4[(j >> 2) * 128 + b * 4 + (j & 3)] = o2;
        }
        gsync(gen);

        // ============ P2: attention (2 (b,nh) pairs per block) ============
        if (bid < 128) {
            int pr = tid >> 8, tid2 = tid & 255;
            int p = bid * 2 + pr, b = p >> 3, nh = p & 7;
            float* st  = scr + pr * 512;
            float* sq  = scr + 1024 + pr * 64;
            float* sa  = scr + 1152 + pr * 64;
            float* qp  = scr + 1280 + pr * 256;
            float* scp = scr + 1792 + pr * 128;
            for (int i = tid2; i < 512; i += 256)
                st[i] = __ldcg(t4 + (i >> 2) * 128 + b * 4 + (i & 3));
            __syncthreads();
            {
                int d = tid2 & 63, kq = tid2 >> 6;
                float a = 0.f;
                const float* wp = WqT + nh * 64 + d;
                int k0 = kq * 128;
                for (int k = k0; k < k0 + 128; k++) a += st[k] * wp[(size_t)k * 512];
                qp[kq * 64 + d] = a;
            }
            __syncthreads();
            if (tid2 < 64)
                sq[tid2] = bq[nh * 64 + tid2] + qp[tid2] + qp[64 + tid2] + qp[128 + tid2] + qp[192 + tid2];
            __syncthreads();
            if (tid2 < 128) {
                int s = tid2 & 63, dh = tid2 >> 6;
                float a = 0.f;
                const float* kp = keyup + (((size_t)(b * 8 + nh)) * 64 + s) * 64 + dh * 32;
                const float* sqh = sq + dh * 32;
                const float* wwh = Ww + dh * 32;
#pragma unroll 8
                for (int d = 0; d < 32; d++) a += tanhf(sqh[d] + kp[d]) * wwh[d];
                scp[dh * 64 + s] = a;
            }
            __syncthreads();
            if (tid2 < 64) {
                float sc = scp[tid2] + scp[64 + tid2] + bw[0];
                if (mask[b * S_ + tid2]) sc -= 1e9f;
                sa[tid2] = sc;
            }
            __syncthreads();
            if (tid2 == 0) {
                float mx = -1e30f;
                for (int s = 0; s < 64; s++) mx = fmaxf(mx, sa[s]);
                float sum = 0.f;
                for (int s = 0; s < 64; s++) { float e = expf(sa[s] - mx); sa[s] = e; sum += e; }
                float inv = 1.f / sum;
                for (int s = 0; s < 64; s++) sa[s] *= inv;
            }
            __syncthreads();
            if (tid2 < 128) {
                float a = 0.f;
                const float* vp = enc_out + (size_t)b * U_ + nh * 128 + tid2;
#pragma unroll
                for (int s = 0; s < 64; s++) a += sa[s] * vp[(size_t)s * B_ * U_];
                int n = nh * 128 + tid2;
                c4[(n >> 2) * 128 + b * 4 + (n & 3)] = a;
                feat[((size_t)b * T_ + t) * FEATW + 1024 + n] = a;
            }
        }
        gsync(gen);

        // ============ P3: GRU2 gates + combine ============
        float a_r = 0.f, a_z = 0.f, a_xn = 0.f, a_hn = 0.f;
        if (bid < 128) {
            // x-part: K=1024 over c4 with W2xs
            {
                const float4* xp = reinterpret_cast<const float4*>(c4) + q * 2048 + b0 + bl;
                const float4* wr4 = reinterpret_cast<const float4*>(W2xs + (jl * 3 + 0) * 1024) + q * 64;
                const float4* wz4 = reinterpret_cast<const float4*>(W2xs + (jl * 3 + 1) * 1024) + q * 64;
                const float4* wn4 = reinterpret_cast<const float4*>(W2xs + (jl * 3 + 2) * 1024) + q * 64;
#pragma unroll 8
                for (int kk = 0; kk < 64; kk++) {
                    float4 x = __ldcg(xp + kk * 32);
                    float4 wr = wr4[kk], wz = wz4[kk], wn = wn4[kk];
                    a_r  += x.x * wr.x + x.y * wr.y + x.z * wr.z + x.w * wr.w;
                    a_z  += x.x * wz.x + x.y * wz.y + x.z * wz.z + x.w * wz.w;
                    a_xn += x.x * wn.x + x.y * wn.y + x.z * wn.z + x.w * wn.w;
                }
            }
            // h-part: K=512 over t4 with W2hs
            {
                const float4* xp = reinterpret_cast<const float4*>(t4) + q * 1024 + b0 + bl;
                const float4* wr4 = reinterpret_cast<const float4*>(W2hs + (jl * 3 + 0) * 512) + q * 32;
                const float4* wz4 = reinterpret_cast<const float4*>(W2hs + (jl * 3 + 1) * 512) + q * 32;
                const float4* wn4 = reinterpret_cast<const float4*>(W2hs + (jl * 3 + 2) * 512) + q * 32;
#pragma unroll 8
                for (int kk = 0; kk < 32; kk++) {
                    float4 x = __ldcg(xp + kk * 32);
                    float4 wr = wr4[kk], wz = wz4[kk], wn = wn4[kk];
                    a_r  += x.x * wr.x + x.y * wr.y + x.z * wr.z + x.w * wr.w;
                    a_z  += x.x * wz.x + x.y * wz.y + x.z * wz.z + x.w * wz.w;
                    a_hn += x.x * wn.x + x.y * wn.y + x.z * wn.z + x.w * wn.w;
                }
            }
            if (q) {
                int o = (q - 1) * 512 + (jl * 16 + bl) * 4;
                scr[o] = a_r; scr[o + 1] = a_z; scr[o + 2] = a_xn; scr[o + 3] = a_hn;
            }
        }
        __syncthreads();
        if (bid < 128 && q == 0) {
            int o = (jl * 16 + bl) * 4;
            a_r  += scr[o] + scr[512 + o] + scr[1024 + o];
            a_z  += scr[o + 1] + scr[512 + o + 1] + scr[1024 + o + 1];
            a_xn += scr[o + 2] + scr[512 + o + 2] + scr[1024 + o + 2];
            a_hn += scr[o + 3] + scr[512 + o + 3] + scr[1024 + o + 3];
            int j = j0 + jl, b = b0 + bl, m = b * T_ + t;
            float r = 1.f / (1.f + expf(-(a_r + bfx2[j] + g2bh[j])));
            float z = 1.f / (1.f + expf(-(a_z + bfx2[512 + j] + g2bh[512 + j])));
            float n = tanhf(a_xn + bfx2[1024 + j] + r * (a_hn + g2bh[1024 + j]));
            float hp = __ldcg(t4 + (j >> 2) * 128 + b * 4 + (j & 3));
            float o2 = (1.f - z) * n + z * hp;
            hT4[(j >> 2) * 128 + b * 4 + (j & 3)] = o2;
            feat[(size_t)m * FEATW + 512 + j] = o2;
        }
        gsync(gen);
    }
}

// ============ bf16 hi/lo split conversion ============
__global__ void k_convA(const float* __restrict__ L, __nv_bfloat16* __restrict__ A) {
    int idx = blockIdx.x * 256 + threadIdx.x;
    if (idx >= 2048 * 128) return;
    int m = idx >> 7, kg = (idx & 127) << 2;
    float4 v = *reinterpret_cast<const float4*>(L + (size_t)m * 512 + kg);
    __nv_bfloat16 h[4], l[4];
    float x[4] = {v.x, v.y, v.z, v.w};
#pragma unroll
    for (int i = 0; i < 4; i++) {
        h[i] = __float2bfloat16(x[i]);
        l[i] = __float2bfloat16(x[i] - __bfloat162float(h[i]));
    }
    __nv_bfloat162* p0 = reinterpret_cast<__nv_bfloat162*>(A + (size_t)m * 1536 + kg);
    __nv_bfloat162* p1 = reinterpret_cast<__nv_bfloat162*>(A + (size_t)m * 1536 + 512 + kg);
    __nv_bfloat162* p2 = reinterpret_cast<__nv_bfloat162*>(A + (size_t)m * 1536 + 1024 + kg);
    p0[0] = __nv_bfloat162(h[0], h[1]); p0[1] = __nv_bfloat162(h[2], h[3]);
    p1[0] = __nv_bfloat162(h[0], h[1]); p1[1] = __nv_bfloat162(h[2], h[3]);
    p2[0] = __nv_bfloat162(l[0], l[1]); p2[1] = __nv_bfloat162(l[2], l[3]);
}
__global__ void k_convB(const float* __restrict__ W, __nv_bfloat16* __restrict__ Bp) {
    int idx = blockIdx.x * 256 + threadIdx.x;
    if (idx >= 32000 * 128) return;
    int n = idx >> 7, kg = (idx & 127) << 2;
    float4 v = *reinterpret_cast<const float4*>(W + (size_t)n * 512 + kg);
    __nv_bfloat16 h[4], l[4];
    float x[4] = {v.x, v.y, v.z, v.w};
#pragma unroll
    for (int i = 0; i < 4; i++) {
        h[i] = __float2bfloat16(x[i]);
        l[i] = __float2bfloat16(x[i] - __bfloat162float(h[i]));
    }
    __nv_bfloat162* p0 = reinterpret_cast<__nv_bfloat162*>(Bp + (size_t)n * 1536 + kg);
    __nv_bfloat162* p1 = reinterpret_cast<__nv_bfloat162*>(Bp + (size_t)n * 1536 + 512 + kg);
    __nv_bfloat162* p2 = reinterpret_cast<__nv_bfloat162*>(Bp + (size_t)n * 1536 + 1024 + kg);
    p0[0] = __nv_bfloat162(h[0], h[1]); p0[1] = __nv_bfloat162(h[2], h[3]);
    p1[0] = __nv_bfloat162(l[0], l[1]); p1[1] = __nv_bfloat162(l[2], l[3]);
    p2[0] = __nv_bfloat162(h[0], h[1]); p2[1] = __nv_bfloat162(h[2], h[3]);
}

// ============ HMMA bf16 GEMM ============
#define HG_A_BYTES 16384
#define HG_B_BYTES 16384
#define HG_SMEM_TOTAL (2 * (HG_A_BYTES + HG_B_BYTES))

__global__ __launch_bounds__(256, 2)
void mma_gemm_hmma(const __nv_bfloat16* __restrict__ Ap, const __nv_bfloat16* __restrict__ Bp,
                   float* __restrict__ C) {
    extern __shared__ char smemc[];
    uint32_t sb_a = smem_to_u32(smemc);
    uint32_t sb_b = sb_a + 2 * HG_A_BYTES;
    const int tid = threadIdx.x, lane = tid & 31, wid = tid >> 5;
    const int mt = blockIdx.y, nt = blockIdx.x;
    const int m0 = (wid & 3) * 32;
    const int n0 = (wid >> 2) * 64;

    const __nv_bfloat16* Ag = Ap + (size_t)mt * 128 * 1536;
    const __nv_bfloat16* Bg = Bp + (size_t)nt * 128 * 1536;

#define HLOAD(s, buf) { \
    uint32_t ab_ = sb_a + (buf) * HG_A_BYTES; \
    uint32_t bb_ = sb_b + (buf) * HG_B_BYTES; \
    const __nv_bfloat16* As_ = Ag + (s) * 64; \
    const __nv_bfloat16* Bs_ = Bg + (s) * 64; \
    _Pragma("unroll") \
    for (int i_ = 0; i_ < 4; i_++) { int ix_ = tid + i_ * 256; int r_ = ix_ >> 3, c_ = ix_ & 7; \
        cp_async16(ab_ + SW128(r_ * 128 + c_ * 16), As_ + (size_t)r_ * 1536 + c_ * 8); } \
    _Pragma("unroll") \
    for (int i_ = 0; i_ < 4; i_++) { int ix_ = tid + i_ * 256; int r_ = ix_ >> 3, c_ = ix_ & 7; \
        cp_async16(bb_ + SW128(r_ * 128 + c_ * 16), Bs_ + (size_t)r_ * 1536 + c_ * 8); } \
    CP_COMMIT(); }

    float acc[2][8][4];
#pragma unroll
    for (int i = 0; i < 2; i++)
#pragma unroll
        for (int j = 0; j < 8; j++)
#pragma unroll
            for (int v = 0; v < 4; v++) acc[i][j][v] = 0.f;

    HLOAD(0, 0);
    HLOAD(1, 1);

    const int a_row_off = ((lane >> 3) & 1) * 8 + (lane & 7);
    const int a_kb_off  = ((lane >> 4) & 1) * 16;
    const int b_row_off = ((lane >> 4) & 1) * 8 + (lane & 7);
    const int b_kb_off  = ((lane >> 3) & 1) * 16;

    for (int s = 0; s < 24; s++) {
        int buf = s & 1;
        CP_WAIT(1);
        __syncthreads();
        uint32_t abase = sb_a + buf * HG_A_BYTES;
        uint32_t bbase = sb_b + buf * HG_B_BYTES;
#pragma unroll
        for (int kk = 0; kk < 4; kk++) {
            uint32_t a[2][4];
#pragma unroll
            for (int mi = 0; mi < 2; mi++) {
                int row = m0 + mi * 16 + a_row_off;
                int kb = kk * 32 + a_kb_off;
                ldsm_x4(a[mi][0], a[mi][1], a[mi][2], a[mi][3], abase + SW128(row * 128 + kb));
            }
            uint32_t bfr[4][4];
#pragma unroll
            for (int ng = 0; ng < 4; ng++) {
                int row = n0 + ng * 16 + b_row_off;
                int kb = kk * 32 + b_kb_off;
                ldsm_x4(bfr[ng][0], bfr[ng][1], bfr[ng][2], bfr[ng][3], bbase + SW128(row * 128 + kb));
            }
#pragma unroll
            for (int mi = 0; mi < 2; mi++)
#pragma unroll
                for (int nj = 0; nj < 8; nj++) {
                    uint32_t b0 = bfr[nj >> 1][(nj & 1) * 2];
                    uint32_t b1 = bfr[nj >> 1][(nj & 1) * 2 + 1];
                    mma16816(acc[mi][nj][0], acc[mi][nj][1], acc[mi][nj][2], acc[mi][nj][3],
                             a[mi][0], a[mi][1], a[mi][2], a[mi][3], b0, b1);
                }
        }
        __syncthreads();
        if (s + 2 < 24) HLOAD(s + 2, buf);
    }

    int gr = mt * 128 + m0 + (lane >> 2);
    int gc = nt * 128 + n0 + (lane & 3) * 2;
#pragma unroll
    for (int mi = 0; mi < 2; mi++) {
#pragma unroll
        for (int nj = 0; nj < 8; nj++) {
            float* p0 = C + (size_t)(gr + mi * 16) * V_ + gc + nj * 8;
            float* p1 = C + (size_t)(gr + mi * 16 + 8) * V_ + gc + nj * 8;
            *reinterpret_cast<float2*>(p0) = make_float2(acc[mi][nj][0], acc[mi][nj][1]);
            *reinterpret_cast<float2*>(p1) = make_float2(acc[mi][nj][2], acc[mi][nj][3]);
        }
    }
}

// ---------------- host orchestration ----------------
extern "C" void kernel_launch(void* const* d_in, const int* in_sizes, int n_in,
                              void* d_out, int out_size) {
    const int*   tokens  = (const int*)d_in[0];
    const unsigned char* enc_mask = (const unsigned char*)d_in[1];
    const float* enc_out = (const float*)d_in[2];
    const float* embed_w = (const float*)d_in[3];
    const float* g1Wx = (const float*)d_in[4];
    const float* g1Wh = (const float*)d_in[5];
    const float* g1bx = (const float*)d_in[6];
    const float* g1bh = (const float*)d_in[7];
    const float* g2Wx = (const float*)d_in[8];
    const float* g2Wh = (const float*)d_in[9];
    const float* g2bx = (const float*)d_in[10];
    const float* g2bh = (const float*)d_in[11];
    const float* brW  = (const float*)d_in[12];
    const float* brB  = (const float*)d_in[13];
    const float* Wk   = (const float*)d_in[14];
    const float* bk   = (const float*)d_in[15];
    const float* Wq   = (const float*)d_in[16];
    const float* bq   = (const float*)d_in[17];
    const float* Ww   = (const float*)d_in[18];
    const float* bw   = (const float*)d_in[19];
    const float* Wf   = (const float*)d_in[20];
    const float* bf   = (const float*)d_in[21];
    const float* Wo   = (const float*)d_in[22];
    const float* bo   = (const float*)d_in[23];
    float* out = (float*)d_out;

    float* S = nullptr;
    cudaGetSymbolAddress((void**)&S, g_scratch);
    float* feat    = S + OFF_FEAT;
    float* keyup   = S + OFF_KEYUP;
    float* logits  = S + OFF_LOGITS;
    float* hT4     = S + OFF_HT;
    float* t4      = S + OFF_TMP;
    float* c4      = S + OFF_CTXRT;
    float* X1all   = S + OFF_X1ALL;
    float* Wfx2    = S + OFF_WFX2;
    float* bfx2    = S + OFF_BFX2;
    float* WqT     = S + OFF_WQT;
    float* WfT     = S + OFF_WFT;
    float* Wo2f    = S + OFF_WO2F;
    float* Wopk    = S + OFF_WOPK;
    float* bo2     = S + OFF_BO2;
    __nv_bfloat16* Ahl = (__nv_bfloat16*)(S + OFF_AHL);
    __nv_bfloat16* Bhl = (__nv_bfloat16*)(S + OFF_BHL);

    // ---- prep ----
    k_embed<<<B_ * T_, 128>>>(tokens, embed_w, feat);
    k_bridge<<<B_, 512>>>(enc_mask, enc_out, brW, brB, hT4);
    k_transpose<<<(512 * 512 + 255) / 256, 256>>>(Wq, WqT, 512, 512);
    k_transpose<<<(1024 * 1024 + 255) / 256, 256>>>(Wf, WfT, 1024, 1024);
    k_bfx2<<<6, 256>>>(g2Wx, bf, g2bx, bfx2);
    k_bo2<<<2, 256>>>(Wo, bf, bo, bo2);
    k_convB<<<(32000 * 128 + 255) / 256, 256>>>(embed_w, Bhl);
    {   // keyup = enc @ Wk^T + bk
        dim3 g(512 / BN, 2048 / BM);
        sgemm_nt<<<g, 256>>>(enc_out, Wk, bk, keyup, 2048, 512, 1024, 1024, 2);
    }
    {   // X1all = emb @ g1Wx^T + g1bx
        dim3 g(1536 / BN, 2048 / BM);
        sgemm_nt<<<g, 256>>>(feat, g1Wx, g1bx, X1all, 2048, 1536, 512, 2048, 0);
    }
    {   // Wfx2 = g2Wx (x) Wf
        dim3 g(1024 / BN, 1536 / BM);
        sgemm_nt<<<g, 256>>>(g2Wx, WfT, nullptr, Wfx2, 1536, 1024, 1024, 1024, 0);
    }
    {   // Wo2f[e][n] = sum_m Wo[e][1024+m] Wf[m][n]
        dim3 g(1024 / BN, 512 / BM);
        sgemm_nt<<<g, 256>>>(Wo + 1024, WfT, nullptr, Wo2f, 512, 1024, 1024, 2048, 0);
    }
    k_wopack<<<(512 * 2048 + 255) / 256, 256>>>(Wo, Wo2f, Wopk);

    // ---- persistent recurrence ----
    k_zero<<<1, 1>>>();
    cudaFuncSetAttribute(k_persistent, cudaFuncAttributeMaxDynamicSharedMemorySize, PERS_SMEM);
    k_persistent<<<NB, 512, PERS_SMEM>>>(X1all, g1Wh, g1bh, Wfx2, bfx2, g2Wh, g2bh,
                                         WqT, bq, Ww, bw,
                                         enc_out, enc_mask, keyup,
                                         feat, hT4, t4, c4);

    {   // logits = tanh(feat_pack @ Wopk^T + bo2)
        dim3 g(512 / BN, 2048 / BM);
        sgemm_nt<<<g, 256>>>(feat, Wopk, bo2, logits, 2048, 512, 2048, 2048, 1);
    }
    // out = logits @ embed_w^T via HMMA bf16 hi/lo K-extended GEMM
    k_convA<<<(2048 * 128 + 255) / 256, 256>>>(logits, Ahl);
    cudaFuncSetAttribute(mma_gemm_hmma, cudaFuncAttributeMaxDynamicSharedMemorySize, HG_SMEM_TOTAL);
    {
        dim3 g(V_ / 128, 2048 / 128);
        mma_gemm_hmma<<<g, 256, HG_SMEM_TOTAL>>>(Ahl, Bhl, out);
    }
}

// round 9
// speedup vs baseline: 2.6070x; 1.0120x over previous
#include <cuda_runtime.h>
#include <cuda_bf16.h>
#include <math.h>
#include <stdint.h>

#define B_ 32
#define T_ 64
#define S_ 64
#define V_ 32000
#define E_ 512
#define H_ 512
#define U_ 1024
#define NH_ 8
#define FEATW 2048
#define NB 128

// ---------------- scratch offsets (floats) ----------------
#define OFF_FEAT   0ull
#define OFF_KEYUP  4194304ull
#define OFF_LOGITS 5242880ull
#define OFF_HT     6291456ull     // hT4 [128 kg][32 b][4]
#define OFF_TMP    6307840ull     // t4 same layout
#define OFF_CTXRT  6340608ull     // c4 [256 kg][32 b][4]
#define OFF_X1ALL  6373376ull     // X1T [64 t][1536 j][32 b] = 3,145,728
#define OFF_WFX2   9519104ull
#define OFF_BFX2   11091968ull
#define OFF_WQT    11094016ull
#define OFF_WFT    11356160ull
#define OFF_WO2F   12404736ull
#define OFF_WOPK   12929024ull
#define OFF_BO2    13977600ull
#define OFF_AHL    13978624ull    // [2048,1536] bf16
#define OFF_BHL    15551488ull    // [32000,1536] bf16
#define SCRATCH_FLOATS 40127488ull

__device__ float g_scratch[SCRATCH_FLOATS];
__device__ unsigned g_bar_ctr;

__device__ __forceinline__ uint32_t smem_to_u32(const void* p) {
    uint32_t a;
    asm("{ .reg .u64 t; cvta.to.shared.u64 t, %1; cvt.u32.u64 %0, t; }" : "=r"(a) : "l"(p));
    return a;
}
__device__ __forceinline__ void cp_async16(uint32_t dst, const void* src) {
    asm volatile("cp.async.cg.shared.global [%0], [%1], 16;" :: "r"(dst), "l"(src));
}
#define CP_COMMIT() asm volatile("cp.async.commit_group;" ::: "memory")
#define CP_WAIT(n)  asm volatile("cp.async.wait_group %0;" :: "n"(n) : "memory")
#define SW128(x) ((x) ^ (((x) >> 3) & 0x70))

__device__ __forceinline__ void ldsm_x4(uint32_t& r0, uint32_t& r1, uint32_t& r2, uint32_t& r3,
                                        uint32_t addr) {
    asm volatile("ldmatrix.sync.aligned.m8n8.x4.shared.b16 {%0,%1,%2,%3}, [%4];"
                 : "=r"(r0), "=r"(r1), "=r"(r2), "=r"(r3) : "r"(addr));
}
__device__ __forceinline__ void mma16816(float& c0, float& c1, float& c2, float& c3,
                                         uint32_t a0, uint32_t a1, uint32_t a2, uint32_t a3,
                                         uint32_t b0, uint32_t b1) {
    asm volatile("mma.sync.aligned.m16n8k16.row.col.f32.bf16.bf16.f32 "
                 "{%0,%1,%2,%3}, {%4,%5,%6,%7}, {%8,%9}, {%0,%1,%2,%3};"
                 : "+f"(c0), "+f"(c1), "+f"(c2), "+f"(c3)
                 : "r"(a0), "r"(a1), "r"(a2), "r"(a3), "r"(b0), "r"(b1));
}

__device__ __forceinline__ void gsync(unsigned& gen) {
    __syncthreads();
    if (threadIdx.x == 0) {
        __threadfence();
        atomicAdd(&g_bar_ctr, 1u);
        unsigned target = (gen + 1u) * (unsigned)NB;
        unsigned v;
        do {
            asm volatile("ld.acquire.gpu.u32 %0, [%1];" : "=r"(v) : "l"(&g_bar_ctr) : "memory");
            if (v < target) __nanosleep(32);
        } while (v < target);
    }
    gen++;
    __syncthreads();
}
__global__ void k_zero() { g_bar_ctr = 0u; }

// ---------------- prep kernels ----------------
__global__ void k_embed(const int* __restrict__ tokens, const float* __restrict__ embed_w,
                        float* __restrict__ feat) {
    int bt = blockIdx.x;
    int tok = tokens[bt];
    const float4* src = reinterpret_cast<const float4*>(embed_w + (size_t)tok * E_);
    float4* dst = reinterpret_cast<float4*>(feat + (size_t)bt * FEATW);
    dst[threadIdx.x] = src[threadIdx.x];
}

__global__ __launch_bounds__(512) void k_bridge(const unsigned char* __restrict__ mask,
                                                const float* __restrict__ enc_out,
                                                const float* __restrict__ Wb,
                                                const float* __restrict__ bb,
                                                float* __restrict__ hT4) {
    int b = blockIdx.x;
    int j = threadIdx.x;
    __shared__ float fn[512];
    __shared__ int sL;
    if (j == 0) {
        int L = S_;
        for (int s = 0; s < S_; s++) if (mask[b * S_ + s]) L--;
        sL = L;
    }
    __syncthreads();
    int L = sL;
    fn[j] = enc_out[((size_t)(L - 1) * B_ + b) * U_ + j];
    __syncthreads();
    float acc = bb[j];
    const float* wr = Wb + (size_t)j * 512;
    for (int k = 0; k < 512; k++) acc += fn[k] * wr[k];
    hT4[(j >> 2) * 128 + b * 4 + (j & 3)] = tanhf(acc);
}

__global__ void k_transpose(const float* __restrict__ W, float* __restrict__ WT, int R, int C) {
    int idx = blockIdx.x * 256 + threadIdx.x;
    if (idx >= R * C) return;
    int n = idx / C, k = idx % C;
    WT[(size_t)k * R + n] = W[idx];
}

__global__ void k_bfx2(const float* __restrict__ g2Wx, const float* __restrict__ bf,
                       const float* __restrict__ g2bx, float* __restrict__ bfx2) {
    int g = blockIdx.x * 256 + threadIdx.x;
    if (g >= 1536) return;
    float a = g2bx[g];
    const float4* w4 = reinterpret_cast<const float4*>(g2Wx + (size_t)g * 1024);
    const float4* b4 = reinterpret_cast<const float4*>(bf);
    for (int k = 0; k < 256; k++) {
        float4 w = w4[k], b = b4[k];
        a += w.x * b.x + w.y * b.y + w.z * b.z + w.w * b.w;
    }
    bfx2[g] = a;
}

__global__ void k_wopack(const float* __restrict__ Wo, const float* __restrict__ Wo2f,
                         float* __restrict__ Wp) {
    int idx = blockIdx.x * 256 + threadIdx.x;
    if (idx >= 512 * 2048) return;
    int e = idx >> 11, c = idx & 2047;
    Wp[idx] = (c < 1024) ? Wo[(size_t)e * 2048 + c] : Wo2f[(size_t)e * 1024 + (c - 1024)];
}
__global__ void k_bo2(const float* __restrict__ Wo, const float* __restrict__ bf,
                      const float* __restrict__ bo, float* __restrict__ bo2) {
    int e = blockIdx.x * 256 + threadIdx.x;
    if (e >= 512) return;
    float a = bo[e];
    const float* w = Wo + (size_t)e * 2048 + 1024;
    for (int m = 0; m < 1024; m++) a += w[m] * bf[m];
    bo2[e] = a;
}

// ---------------- tiled SGEMM-NT with lda ----------------
// mode 0 plain, 1 tanh, 2 keyup remap, 3 X1T remap, 4 tanh + bf16 hi/lo split into Ahl
#define BM 128
#define BN 128
#define BKk 16
__global__ __launch_bounds__(256) void sgemm_nt(const float* __restrict__ A,
                                                const float* __restrict__ Bm,
                                                const float* __restrict__ bias,
                                                float* __restrict__ C,
                                                int M, int N, int K, int lda, int mode) {
    __shared__ float As[BKk][BM];
    __shared__ float Bs[BKk][BN];
    const int bm = blockIdx.y * BM, bn = blockIdx.x * BN;
    const int tid = threadIdx.x;
    const int tm = (tid >> 4) << 3;
    const int tn = (tid & 15) << 3;
    float acc[8][8];
#pragma unroll
    for (int i = 0; i < 8; i++)
#pragma unroll
        for (int j = 0; j < 8; j++) acc[i][j] = 0.f;

    for (int k0 = 0; k0 < K; k0 += BKk) {
#pragma unroll
        for (int i = 0; i < 2; i++) {
            int idx = tid + i * 256;
            int r = idx >> 2, c = (idx & 3) << 2;
            float4 v = *reinterpret_cast<const float4*>(A + (size_t)(bm + r) * lda + k0 + c);
            As[c][r] = v.x; As[c + 1][r] = v.y; As[c + 2][r] = v.z; As[c + 3][r] = v.w;
            float4 w = *reinterpret_cast<const float4*>(Bm + (size_t)(bn + r) * K + k0 + c);
            Bs[c][r] = w.x; Bs[c + 1][r] = w.y; Bs[c + 2][r] = w.z; Bs[c + 3][r] = w.w;
        }
        __syncthreads();
#pragma unroll
        for (int k = 0; k < BKk; k++) {
            float a[8], bb[8];
            *reinterpret_cast<float4*>(&a[0]) = *reinterpret_cast<const float4*>(&As[k][tm]);
            *reinterpret_cast<float4*>(&a[4]) = *reinterpret_cast<const float4*>(&As[k][tm + 4]);
            *reinterpret_cast<float4*>(&bb[0]) = *reinterpret_cast<const float4*>(&Bs[k][tn]);
            *reinterpret_cast<float4*>(&bb[4]) = *reinterpret_cast<const float4*>(&Bs[k][tn + 4]);
#pragma unroll
            for (int i = 0; i < 8; i++)
#pragma unroll
                for (int j = 0; j < 8; j++) acc[i][j] += a[i] * bb[j];
        }
        __syncthreads();
    }
#pragma unroll
    for (int i = 0; i < 8; i++) {
        int m = bm + tm + i;
#pragma unroll
        for (int j = 0; j < 8; j++) {
            int n = bn + tn + j;
            float v = acc[i][j];
            if (bias) v += bias[n];
            if (mode == 1) v = tanhf(v);
            if (mode == 2) {
                int s_ = m >> 5, b_ = m & 31, nh_ = n >> 6, d_ = n & 63;
                C[(((size_t)(b_ * 8 + nh_) * 64) + s_) * 64 + d_] = v;
            } else if (mode == 3) {
                int b_ = m >> 6, t_ = m & 63;
                C[((size_t)t_ * 1536 + n) * 32 + b_] = v;
            } else if (mode == 4) {
                v = tanhf(v);
                __nv_bfloat16* Ahl = reinterpret_cast<__nv_bfloat16*>(C);
                __nv_bfloat16 hi = __float2bfloat16(v);
                __nv_bfloat16 lo = __float2bfloat16(v - __bfloat162float(hi));
                Ahl[(size_t)m * 1536 + n] = hi;
                Ahl[(size_t)m * 1536 + 512 + n] = hi;
                Ahl[(size_t)m * 1536 + 1024 + n] = lo;
            } else {
                C[(size_t)m * N + n] = v;
            }
        }
    }
}

// ---------------- persistent recurrence ----------------
#define PERS_SMEM (51200 * 4)

__global__ __launch_bounds__(512, 1)
void k_persistent(const float* __restrict__ X1T, const float* __restrict__ g1Wh,
                  const float* __restrict__ g1bh,
                  const float* __restrict__ Wfx2, const float* __restrict__ bfx2,
                  const float* __restrict__ g2Wh, const float* __restrict__ g2bh,
                  const float* __restrict__ WqT, const float* __restrict__ bq,
                  const float* __restrict__ Ww, const float* __restrict__ bw,
                  const float* __restrict__ enc_out, const unsigned char* __restrict__ mask,
                  const float* __restrict__ keyup,
                  float* __restrict__ feat, float* __restrict__ hT4,
                  float* __restrict__ t4, float* __restrict__ c4) {
    extern __shared__ float sm[];
    float* W1s  = sm;
    float* W2xs = sm + 12288;
    float* W2hs = sm + 36864;
    float* scr  = sm + 49152;
    const int bid = blockIdx.x, tid = threadIdx.x;
    unsigned gen = 0;
    const int bl = tid & 15, jl = (tid >> 4) & 7, q = tid >> 7;
    const int jb = bid >> 1, bh = bid & 1;
    const int j0 = jb * 8, b0 = bh * 16;

    // stage loop-invariant weights ONCE
    {
        float4* d1 = reinterpret_cast<float4*>(W1s);
        for (int i = tid; i < 3072; i += 512) {
            int jj = i / 384, rem = i % 384, g = rem >> 7, k4 = rem & 127;
            d1[i] = *reinterpret_cast<const float4*>(
                g1Wh + ((size_t)(g * 512 + j0 + jj)) * 512 + k4 * 4);
        }
        float4* d2 = reinterpret_cast<float4*>(W2xs);
        for (int i = tid; i < 6144; i += 512) {
            int jj = i / 768, rem = i % 768, g = rem >> 8, k4 = rem & 255;
            d2[i] = *reinterpret_cast<const float4*>(
                Wfx2 + ((size_t)(g * 512 + j0 + jj)) * 1024 + k4 * 4);
        }
        float4* d3 = reinterpret_cast<float4*>(W2hs);
        for (int i = tid; i < 3072; i += 512) {
            int jj = i / 384, rem = i % 384, g = rem >> 7, k4 = rem & 127;
            d3[i] = *reinterpret_cast<const float4*>(
                g2Wh + ((size_t)(g * 512 + j0 + jj)) * 512 + k4 * 4);
        }
    }
    __syncthreads();

    float h_r, h_z, h_hn;   // GRU2 h-part partials carried P2 -> P3

    for (int t = 0; t < T_; t++) {
        // ============ P1: GRU1 h-gates + combine ============
        float ar = 0.f, az = 0.f, an = 0.f;
        {
            const float4* xp = reinterpret_cast<const float4*>(hT4) + q * 1024 + b0 + bl;
            const float4* wr4 = reinterpret_cast<const float4*>(W1s + (jl * 3 + 0) * 512) + q * 32;
            const float4* wz4 = reinterpret_cast<const float4*>(W1s + (jl * 3 + 1) * 512) + q * 32;
            const float4* wn4 = reinterpret_cast<const float4*>(W1s + (jl * 3 + 2) * 512) + q * 32;
#pragma unroll 8
            for (int kk = 0; kk < 32; kk++) {
                float4 x = __ldcg(xp + kk * 32);
                float4 wr = wr4[kk], wz = wz4[kk], wn = wn4[kk];
                ar += x.x * wr.x + x.y * wr.y + x.z * wr.z + x.w * wr.w;
                az += x.x * wz.x + x.y * wz.y + x.z * wz.z + x.w * wz.w;
                an += x.x * wn.x + x.y * wn.y + x.z * wn.z + x.w * wn.w;
            }
            if (q) {
                int o = (q - 1) * 384 + (jl * 16 + bl) * 3;
                scr[o] = ar; scr[o + 1] = az; scr[o + 2] = an;
            }
        }
        __syncthreads();
        if (q == 0) {
            int o = (jl * 16 + bl) * 3;
            ar += scr[o] + scr[384 + o] + scr[768 + o];
            az += scr[o + 1] + scr[384 + o + 1] + scr[768 + o + 1];
            an += scr[o + 2] + scr[384 + o + 2] + scr[768 + o + 2];
            int j = j0 + jl, b = b0 + bl;
            const float* X1 = X1T + ((size_t)t * 1536) * 32;
            float xr = X1[(size_t)j * 32 + b];
            float xz = X1[(size_t)(512 + j) * 32 + b];
            float xn = X1[(size_t)(1024 + j) * 32 + b];
            float r = 1.f / (1.f + expf(-(xr + g1bh[j] + ar)));
            float z = 1.f / (1.f + expf(-(xz + g1bh[512 + j] + az)));
            float n = tanhf(xn + r * (an + g1bh[1024 + j]));
            float hp = __ldcg(hT4 + (j >> 2) * 128 + b * 4 + (j & 3));
            float o2 = (1.f - z) * n + z * hp;
            t4[(j >> 2) * 128 + b * 4 + (j & 3)] = o2;
        }
        gsync(gen);

        // ============ P2: attention + GRU2 h-part (register carry) ============
        {
            int pr = tid >> 8, tid2 = tid & 255;
            int p = bid * 2 + pr, b = p >> 3, nh = p & 7;
            float* st  = scr + pr * 512;
            float* sq  = scr + 1024 + pr * 64;
            float* sa  = scr + 1152 + pr * 64;
            float* qp  = scr + 1280 + pr * 256;
            float* scp = scr + 1792 + pr * 128;
            for (int i = tid2; i < 512; i += 256)
                st[i] = __ldcg(t4 + (i >> 2) * 128 + b * 4 + (i & 3));
            __syncthreads();
            {
                int d = tid2 & 63, kq = tid2 >> 6;
                float a = 0.f;
                const float* wp = WqT + nh * 64 + d;
                int k0 = kq * 128;
                for (int k = k0; k < k0 + 128; k++) a += st[k] * wp[(size_t)k * 512];
                qp[kq * 64 + d] = a;
            }
            __syncthreads();
            if (tid2 < 64)
                sq[tid2] = bq[nh * 64 + tid2] + qp[tid2] + qp[64 + tid2] + qp[128 + tid2] + qp[192 + tid2];
            __syncthreads();
            if (tid2 < 128) {
                int s = tid2 & 63, dh = tid2 >> 6;
                float a = 0.f;
                const float* kp = keyup + (((size_t)(b * 8 + nh)) * 64 + s) * 64 + dh * 32;
                const float* sqh = sq + dh * 32;
                const float* wwh = Ww + dh * 32;
#pragma unroll 8
                for (int d = 0; d < 32; d++) a += tanhf(sqh[d] + kp[d]) * wwh[d];
                scp[dh * 64 + s] = a;
            }
            __syncthreads();
            if (tid2 < 64) {
                float sc = scp[tid2] + scp[64 + tid2] + bw[0];
                if (mask[b * S_ + tid2]) sc -= 1e9f;
                sa[tid2] = sc;
            }
            __syncthreads();
            if (tid2 == 0) {
                float mx = -1e30f;
                for (int s = 0; s < 64; s++) mx = fmaxf(mx, sa[s]);
                float sum = 0.f;
                for (int s = 0; s < 64; s++) { float e = expf(sa[s] - mx); sa[s] = e; sum += e; }
                float inv = 1.f / sum;
                for (int s = 0; s < 64; s++) sa[s] *= inv;
            }
            __syncthreads();
            if (tid2 < 128) {
                float a = 0.f;
                const float* vp = enc_out + (size_t)b * U_ + nh * 128 + tid2;
#pragma unroll
                for (int s = 0; s < 64; s++) a += sa[s] * vp[(size_t)s * B_ * U_];
                int n = nh * 128 + tid2;
                c4[(n >> 2) * 128 + b * 4 + (n & 3)] = a;
                feat[((size_t)b * T_ + t) * FEATW + 1024 + n] = a;
            }
        }
        // GRU2 h-part: K=512 over t4 (ready since P1 barrier), partials in registers
        {
            h_r = 0.f; h_z = 0.f; h_hn = 0.f;
            const float4* xp = reinterpret_cast<const float4*>(t4) + q * 1024 + b0 + bl;
            const float4* wr4 = reinterpret_cast<const float4*>(W2hs + (jl * 3 + 0) * 512) + q * 32;
            const float4* wz4 = reinterpret_cast<const float4*>(W2hs + (jl * 3 + 1) * 512) + q * 32;
            const float4* wn4 = reinterpret_cast<const float4*>(W2hs + (jl * 3 + 2) * 512) + q * 32;
#pragma unroll 8
            for (int kk = 0; kk < 32; kk++) {
                float4 x = __ldcg(xp + kk * 32);
                float4 wr = wr4[kk], wz = wz4[kk], wn = wn4[kk];
                h_r  += x.x * wr.x + x.y * wr.y + x.z * wr.z + x.w * wr.w;
                h_z  += x.x * wz.x + x.y * wz.y + x.z * wz.z + x.w * wz.w;
                h_hn += x.x * wn.x + x.y * wn.y + x.z * wn.z + x.w * wn.w;
            }
        }
        gsync(gen);

        // ============ P3: GRU2 x-part + combine ============
        float a_r = h_r, a_z = h_z, a_xn = 0.f, a_hn = h_hn;
        {
            const float4* xp = reinterpret_cast<const float4*>(c4) + q * 2048 + b0 + bl;
            const float4* wr4 = reinterpret_cast<const float4*>(W2xs + (jl * 3 + 0) * 1024) + q * 64;
            const float4* wz4 = reinterpret_cast<const float4*>(W2xs + (jl * 3 + 1) * 1024) + q * 64;
            const float4* wn4 = reinterpret_cast<const float4*>(W2xs + (jl * 3 + 2) * 1024) + q * 64;
#pragma unroll 8
            for (int kk = 0; kk < 64; kk++) {
                float4 x = __ldcg(xp + kk * 32);
                float4 wr = wr4[kk], wz = wz4[kk], wn = wn4[kk];
                a_r  += x.x * wr.x + x.y * wr.y + x.z * wr.z + x.w * wr.w;
                a_z  += x.x * wz.x + x.y * wz.y + x.z * wz.z + x.w * wz.w;
                a_xn += x.x * wn.x + x.y * wn.y + x.z * wn.z + x.w * wn.w;
            }
            if (q) {
                int o = (q - 1) * 512 + (jl * 16 + bl) * 4;
                scr[o] = a_r; scr[o + 1] = a_z; scr[o + 2] = a_xn; scr[o + 3] = a_hn;
            }
        }
        __syncthreads();
        if (q == 0) {
            int o = (jl * 16 + bl) * 4;
            a_r  += scr[o] + scr[512 + o] + scr[1024 + o];
            a_z  += scr[o + 1] + scr[512 + o + 1] + scr[1024 + o + 1];
            a_xn += scr[o + 2] + scr[512 + o + 2] + scr[1024 + o + 2];
            a_hn += scr[o + 3] + scr[512 + o + 3] + scr[1024 + o + 3];
            int j = j0 + jl, b = b0 + bl, m = b * T_ + t;
            float r = 1.f / (1.f + expf(-(a_r + bfx2[j] + g2bh[j])));
            float z = 1.f / (1.f + expf(-(a_z + bfx2[512 + j] + g2bh[512 + j])));
            float n = tanhf(a_xn + bfx2[1024 + j] + r * (a_hn + g2bh[1024 + j]));
            float hp = __ldcg(t4 + (j >> 2) * 128 + b * 4 + (j & 3));
            float o2 = (1.f - z) * n + z * hp;
            hT4[(j >> 2) * 128 + b * 4 + (j & 3)] = o2;
            feat[(size_t)m * FEATW + 512 + j] = o2;
        }
        gsync(gen);
    }
}

// ============ bf16 hi/lo split for embed_w ============
__global__ void k_convB(const float* __restrict__ W, __nv_bfloat16* __restrict__ Bp) {
    int idx = blockIdx.x * 256 + threadIdx.x;
    if (idx >= 32000 * 128) return;
    int n = idx >> 7, kg = (idx & 127) << 2;
    float4 v = *reinterpret_cast<const float4*>(W + (size_t)n * 512 + kg);
    __nv_bfloat16 h[4], l[4];
    float x[4] = {v.x, v.y, v.z, v.w};
#pragma unroll
    for (int i = 0; i < 4; i++) {
        h[i] = __float2bfloat16(x[i]);
        l[i] = __float2bfloat16(x[i] - __bfloat162float(h[i]));
    }
    __nv_bfloat162* p0 = reinterpret_cast<__nv_bfloat162*>(Bp + (size_t)n * 1536 + kg);
    __nv_bfloat162* p1 = reinterpret_cast<__nv_bfloat162*>(Bp + (size_t)n * 1536 + 512 + kg);
    __nv_bfloat162* p2 = reinterpret_cast<__nv_bfloat162*>(Bp + (size_t)n * 1536 + 1024 + kg);
    p0[0] = __nv_bfloat162(h[0], h[1]); p0[1] = __nv_bfloat162(h[2], h[3]);
    p1[0] = __nv_bfloat162(l[0], l[1]); p1[1] = __nv_bfloat162(l[2], l[3]);
    p2[0] = __nv_bfloat162(h[0], h[1]); p2[1] = __nv_bfloat162(h[2], h[3]);
}

// ============ HMMA bf16 GEMM ============
#define HG_A_BYTES 16384
#define HG_B_BYTES 16384
#define HG_SMEM_TOTAL (2 * (HG_A_BYTES + HG_B_BYTES))

__global__ __launch_bounds__(256, 2)
void mma_gemm_hmma(const __nv_bfloat16* __restrict__ Ap, const __nv_bfloat16* __restrict__ Bp,
                   float* __restrict__ C) {
    extern __shared__ char smemc[];
    uint32_t sb_a = smem_to_u32(smemc);
    uint32_t sb_b = sb_a + 2 * HG_A_BYTES;
    const int tid = threadIdx.x, lane = tid & 31, wid = tid >> 5;
    const int mt = blockIdx.y, nt = blockIdx.x;
    const int m0 = (wid & 3) * 32;
    const int n0 = (wid >> 2) * 64;

    const __nv_bfloat16* Ag = Ap + (size_t)mt * 128 * 1536;
    const __nv_bfloat16* Bg = Bp + (size_t)nt * 128 * 1536;

#define HLOAD(s, buf) { \
    uint32_t ab_ = sb_a + (buf) * HG_A_BYTES; \
    uint32_t bb_ = sb_b + (buf) * HG_B_BYTES; \
    const __nv_bfloat16* As_ = Ag + (s) * 64; \
    const __nv_bfloat16* Bs_ = Bg + (s) * 64; \
    _Pragma("unroll") \
    for (int i_ = 0; i_ < 4; i_++) { int ix_ = tid + i_ * 256; int r_ = ix_ >> 3, c_ = ix_ & 7; \
        cp_async16(ab_ + SW128(r_ * 128 + c_ * 16), As_ + (size_t)r_ * 1536 + c_ * 8); } \
    _Pragma("unroll") \
    for (int i_ = 0; i_ < 4; i_++) { int ix_ = tid + i_ * 256; int r_ = ix_ >> 3, c_ = ix_ & 7; \
        cp_async16(bb_ + SW128(r_ * 128 + c_ * 16), Bs_ + (size_t)r_ * 1536 + c_ * 8); } \
    CP_COMMIT(); }

    float acc[2][8][4];
#pragma unroll
    for (int i = 0; i < 2; i++)
#pragma unroll
        for (int j = 0; j < 8; j++)
#pragma unroll
            for (int v = 0; v < 4; v++) acc[i][j][v] = 0.f;

    HLOAD(0, 0);
    HLOAD(1, 1);

    const int a_row_off = ((lane >> 3) & 1) * 8 + (lane & 7);
    const int a_kb_off  = ((lane >> 4) & 1) * 16;
    const int b_row_off = ((lane >> 4) & 1) * 8 + (lane & 7);
    const int b_kb_off  = ((lane >> 3) & 1) * 16;

    for (int s = 0; s < 24; s++) {
        int buf = s & 1;
        CP_WAIT(1);
        __syncthreads();
        uint32_t abase = sb_a + buf * HG_A_BYTES;
        uint32_t bbase = sb_b + buf * HG_B_BYTES;
#pragma unroll
        for (int kk = 0; kk < 4; kk++) {
            uint32_t a[2][4];
#pragma unroll
            for (int mi = 0; mi < 2; mi++) {
                int row = m0 + mi * 16 + a_row_off;
                int kb = kk * 32 + a_kb_off;
                ldsm_x4(a[mi][0], a[mi][1], a[mi][2], a[mi][3], abase + SW128(row * 128 + kb));
            }
            uint32_t bfr[4][4];
#pragma unroll
            for (int ng = 0; ng < 4; ng++) {
                int row = n0 + ng * 16 + b_row_off;
                int kb = kk * 32 + b_kb_off;
                ldsm_x4(bfr[ng][0], bfr[ng][1], bfr[ng][2], bfr[ng][3], bbase + SW128(row * 128 + kb));
            }
#pragma unroll
            for (int mi = 0; mi < 2; mi++)
#pragma unroll
                for (int nj = 0; nj < 8; nj++) {
                    uint32_t b0 = bfr[nj >> 1][(nj & 1) * 2];
                    uint32_t b1 = bfr[nj >> 1][(nj & 1) * 2 + 1];
                    mma16816(acc[mi][nj][0], acc[mi][nj][1], acc[mi][nj][2], acc[mi][nj][3],
                             a[mi][0], a[mi][1], a[mi][2], a[mi][3], b0, b1);
                }
        }
        __syncthreads();
        if (s + 2 < 24) HLOAD(s + 2, buf);
    }

    int gr = mt * 128 + m0 + (lane >> 2);
    int gc = nt * 128 + n0 + (lane & 3) * 2;
#pragma unroll
    for (int mi = 0; mi < 2; mi++) {
#pragma unroll
        for (int nj = 0; nj < 8; nj++) {
            float* p0 = C + (size_t)(gr + mi * 16) * V_ + gc + nj * 8;
            float* p1 = C + (size_t)(gr + mi * 16 + 8) * V_ + gc + nj * 8;
            *reinterpret_cast<float2*>(p0) = make_float2(acc[mi][nj][0], acc[mi][nj][1]);
            *reinterpret_cast<float2*>(p1) = make_float2(acc[mi][nj][2], acc[mi][nj][3]);
        }
    }
}

// ---------------- host orchestration ----------------
extern "C" void kernel_launch(void* const* d_in, const int* in_sizes, int n_in,
                              void* d_out, int out_size) {
    const int*   tokens  = (const int*)d_in[0];
    const unsigned char* enc_mask = (const unsigned char*)d_in[1];
    const float* enc_out = (const float*)d_in[2];
    const float* embed_w = (const float*)d_in[3];
    const float* g1Wx = (const float*)d_in[4];
    const float* g1Wh = (const float*)d_in[5];
    const float* g1bx = (const float*)d_in[6];
    const float* g1bh = (const float*)d_in[7];
    const float* g2Wx = (const float*)d_in[8];
    const float* g2Wh = (const float*)d_in[9];
    const float* g2bx = (const float*)d_in[10];
    const float* g2bh = (const float*)d_in[11];
    const float* brW  = (const float*)d_in[12];
    const float* brB  = (const float*)d_in[13];
    const float* Wk   = (const float*)d_in[14];
    const float* bk   = (const float*)d_in[15];
    const float* Wq   = (const float*)d_in[16];
    const float* bq   = (const float*)d_in[17];
    const float* Ww   = (const float*)d_in[18];
    const float* bw   = (const float*)d_in[19];
    const float* Wf   = (const float*)d_in[20];
    const float* bf   = (const float*)d_in[21];
    const float* Wo   = (const float*)d_in[22];
    const float* bo   = (const float*)d_in[23];
    float* out = (float*)d_out;

    float* S = nullptr;
    cudaGetSymbolAddress((void**)&S, g_scratch);
    float* feat    = S + OFF_FEAT;
    float* keyup   = S + OFF_KEYUP;
    float* hT4     = S + OFF_HT;
    float* t4      = S + OFF_TMP;
    float* c4      = S + OFF_CTXRT;
    float* X1T     = S + OFF_X1ALL;
    float* Wfx2    = S + OFF_WFX2;
    float* bfx2    = S + OFF_BFX2;
    float* WqT     = S + OFF_WQT;
    float* WfT     = S + OFF_WFT;
    float* Wo2f    = S + OFF_WO2F;
    float* Wopk    = S + OFF_WOPK;
    float* bo2     = S + OFF_BO2;
    __nv_bfloat16* Ahl = (__nv_bfloat16*)(S + OFF_AHL);
    __nv_bfloat16* Bhl = (__nv_bfloat16*)(S + OFF_BHL);

    // ---- prep ----
    k_embed<<<B_ * T_, 128>>>(tokens, embed_w, feat);
    k_bridge<<<B_, 512>>>(enc_mask, enc_out, brW, brB, hT4);
    k_transpose<<<(512 * 512 + 255) / 256, 256>>>(Wq, WqT, 512, 512);
    k_transpose<<<(1024 * 1024 + 255) / 256, 256>>>(Wf, WfT, 1024, 1024);
    k_bfx2<<<6, 256>>>(g2Wx, bf, g2bx, bfx2);
    k_bo2<<<2, 256>>>(Wo, bf, bo, bo2);
    k_convB<<<(32000 * 128 + 255) / 256, 256>>>(embed_w, Bhl);
    {   // keyup = enc @ Wk^T + bk
        dim3 g(512 / BN, 2048 / BM);
        sgemm_nt<<<g, 256>>>(enc_out, Wk, bk, keyup, 2048, 512, 1024, 1024, 2);
    }
    {   // X1T = emb @ g1Wx^T + g1bx, stored [t][j][b]
        dim3 g(1536 / BN, 2048 / BM);
        sgemm_nt<<<g, 256>>>(feat, g1Wx, g1bx, X1T, 2048, 1536, 512, 2048, 3);
    }
    {   // Wfx2 = g2Wx (x) Wf
        dim3 g(1024 / BN, 1536 / BM);
        sgemm_nt<<<g, 256>>>(g2Wx, WfT, nullptr, Wfx2, 1536, 1024, 1024, 1024, 0);
    }
    {   // Wo2f[e][n] = sum_m Wo[e][1024+m] Wf[m][n]
        dim3 g(1024 / BN, 512 / BM);
        sgemm_nt<<<g, 256>>>(Wo + 1024, WfT, nullptr, Wo2f, 512, 1024, 1024, 2048, 0);
    }
    k_wopack<<<(512 * 2048 + 255) / 256, 256>>>(Wo, Wo2f, Wopk);

    // ---- persistent recurrence ----
    k_zero<<<1, 1>>>();
    cudaFuncSetAttribute(k_persistent, cudaFuncAttributeMaxDynamicSharedMemorySize, PERS_SMEM);
    k_persistent<<<NB, 512, PERS_SMEM>>>(X1T, g1Wh, g1bh, Wfx2, bfx2, g2Wh, g2bh,
                                         WqT, bq, Ww, bw,
                                         enc_out, enc_mask, keyup,
                                         feat, hT4, t4, c4);

    {   // logits = tanh(feat_pack @ Wopk^T + bo2) -> Ahl hi/lo directly (mode 4)
        dim3 g(512 / BN, 2048 / BM);
        sgemm_nt<<<g, 256>>>(feat, Wopk, bo2, (float*)Ahl, 2048, 512, 2048, 2048, 4);
    }
    cudaFuncSetAttribute(mma_gemm_hmma, cudaFuncAttributeMaxDynamicSharedMemorySize, HG_SMEM_TOTAL);
    {
        dim3 g(V_ / 128, 2048 / 128);
        mma_gemm_hmma<<<g, 256, HG_SMEM_TOTAL>>>(Ahl, Bhl, out);
    }
}